// round 4
// baseline (speedup 1.0000x reference)
#include <cuda_runtime.h>
#include <math.h>

// Problem dims (fixed by the dataset)
#define BB 4
#define NN 96
#define TT 512
#define KK 12
#define GG 8

// ---------------- device scratch (no cudaMalloc allowed) ----------------
__device__ float g_lead[KK * 18];                         // per lead: L(3), e1(3), e2(3), Y(9)
__device__ float g_splat[(size_t)BB * KK * TT * 128];     // (B,K,T,2,8,8)
__device__ float g_w2T[9216];                             // conv2 weights transposed [ic][j][oc]
__device__ float g_w1T[576];                              // conv1 weights transposed [c*9+j][oc]

typedef unsigned long long u64;

__device__ __forceinline__ u64 pack2(float x) {
    u64 r; asm("mov.b64 %0, {%1, %1};" : "=l"(r) : "f"(x)); return r;
}
__device__ __forceinline__ void ffma2(u64& d, u64 a, u64 b) {
    asm("fma.rn.f32x2 %0, %1, %2, %0;" : "+l"(d) : "l"(a), "l"(b));
}
__device__ __forceinline__ void unpack2(float& lo, float& hi, u64 v) {
    asm("mov.b64 {%0, %1}, %2;" : "=f"(lo), "=f"(hi) : "l"(v));
}

__device__ __forceinline__ float softplusf(float x) {
    return (x > 20.0f) ? x : log1pf(expf(x));
}

// ---------------- kernel 0: leads + weight transposes ----------------
__global__ void prep_kernel(const float* __restrict__ ra, const float* __restrict__ la,
                            const float* __restrict__ ll, const float* __restrict__ chest,
                            const float* __restrict__ w1, const float* __restrict__ w2) {
    int tid = threadIdx.x;
    for (int idx = tid; idx < 9216; idx += 256) {
        int oc = idx / 288;
        int rem = idx - oc * 288;   // ic*9 + j
        g_w2T[rem * 32 + oc] = w2[idx];
    }
    for (int idx = tid; idx < 576; idx += 256) {
        int oc = idx / 18;
        int r = idx - oc * 18;
        g_w1T[r * 32 + oc] = w1[idx];
    }
    if (tid >= KK) return;
    int k = tid;
    float vx, vy, vz;
    float rax = ra[0], ray = ra[1], raz = ra[2];
    float lax = la[0], lay = la[1], laz = la[2];
    float llx = ll[0], lly = ll[1], llz = ll[2];
    switch (k) {
        case 0: vx = lax - rax; vy = lay - ray; vz = laz - raz; break;
        case 1: vx = llx - rax; vy = lly - ray; vz = llz - raz; break;
        case 2: vx = llx - lax; vy = lly - lay; vz = llz - laz; break;
        case 3: vx = rax - 0.5f * (lax + llx); vy = ray - 0.5f * (lay + lly); vz = raz - 0.5f * (laz + llz); break;
        case 4: vx = lax - 0.5f * (rax + llx); vy = lay - 0.5f * (ray + lly); vz = laz - 0.5f * (raz + llz); break;
        case 5: vx = llx - 0.5f * (rax + lax); vy = lly - 0.5f * (ray + lay); vz = llz - 0.5f * (raz + laz); break;
        default:
            vx = chest[(k - 6) * 3 + 0]; vy = chest[(k - 6) * 3 + 1]; vz = chest[(k - 6) * 3 + 2];
            break;
    }
    float n = sqrtf(vx * vx + vy * vy + vz * vz);
    float d = fmaxf(n, 1e-6f);
    float Lx = vx / d, Ly = vy / d, Lz = vz / d;
    float e1x = 0.0f, e1y = Lz, e1z = -Ly;
    float n1 = sqrtf(e1y * e1y + e1z * e1z);
    if (n1 < 1e-4f) { e1x = -Lz; e1y = 0.0f; e1z = Lx; n1 = sqrtf(e1x * e1x + e1z * e1z); }
    float d1 = fmaxf(n1, 1e-6f);
    e1x /= d1; e1y /= d1; e1z /= d1;
    float e2x = e1y * Lz - e1z * Ly;
    float e2y = e1z * Lx - e1x * Lz;
    float e2z = e1x * Ly - e1y * Lx;
    float n2 = sqrtf(e2x * e2x + e2y * e2y + e2z * e2z);
    float d2 = fmaxf(n2, 1e-6f);
    e2x /= d2; e2y /= d2; e2z /= d2;
    float* o = g_lead + k * 18;
    o[0] = Lx; o[1] = Ly; o[2] = Lz;
    o[3] = e1x; o[4] = e1y; o[5] = e1z;
    o[6] = e2x; o[7] = e2y; o[8] = e2z;
    o[9]  = 0.282095f;
    o[10] = -0.488603f * Ly;
    o[11] = 0.488603f * Lz;
    o[12] = -0.488603f * Lx;
    o[13] = 1.092548f * Lx * Ly;
    o[14] = -1.092548f * Ly * Lz;
    o[15] = 0.315392f * (3.0f * Lz * Lz - 1.0f);
    o[16] = -1.092548f * Lx * Lz;
    o[17] = 0.546274f * (Lx * Lx - Ly * Ly);
}

// ---------------- kernel 1: splat rasterization ----------------
#define NC 32

__global__ __launch_bounds__(384) void splat_kernel(
    const float* __restrict__ mu, const float* __restrict__ sigma0,
    const float* __restrict__ sigma_vel, const float* __restrict__ amplitude,
    const float* __restrict__ sh_base, const float* __restrict__ sh_vel,
    const float* __restrict__ p0, const float* __restrict__ p_vel,
    const float* __restrict__ tau_raw, const float* __restrict__ gam_raw) {
    __shared__ float  sLead[KK][18];
    __shared__ float2 sAA[NC][KK];
    __shared__ float  sKu[NC][KK][9];
    __shared__ float  sKv[NC][KK][9];

    int t = blockIdx.x, b = blockIdx.y;
    int tid = threadIdx.x;
    if (tid < KK * 18) ((float*)sLead)[tid] = g_lead[tid];

    float tau = softplusf(tau_raw[0]) + 0.06f;
    float inv2tau2 = 0.5f / (tau * tau);
    float gamma = softplusf(gam_raw[0]) + 1e-6f;
    float tval = (float)t * (1.0f / (float)(TT - 1));

    int warp = tid >> 5, lane = tid & 31;
    int px0 = lane * 2;
    int hh = px0 >> 3, w0 = px0 & 7;
    float acc00 = 0.f, acc01 = 0.f, acc10 = 0.f, acc11 = 0.f;

    int nl = tid / KK, kk = tid - nl * KK;
    __syncthreads();

    for (int c = 0; c < NN / NC; ++c) {
        {
            int n = c * NC + nl;
            int bn = b * NN + n;
            float dt = tval - mu[bn];
            float sig = softplusf(sigma0[bn] + sigma_vel[bn] * dt) + 1e-3f;
            float z = dt / sig;
            float gauss = amplitude[bn] * __expf(-0.5f * z * z);
            float prx = p0[bn * 3 + 0] + p_vel[bn * 3 + 0] * dt;
            float pry = p0[bn * 3 + 1] + p_vel[bn * 3 + 1] * dt;
            float prz = p0[bn * 3 + 2] + p_vel[bn * 3 + 2] * dt;
            float nrm = fmaxf(sqrtf(prx * prx + pry * pry + prz * prz), 1e-8f);
            float th = tanhf(nrm);
            float sc = th / nrm;
            float ppx = prx * sc, ppy = pry * sc, ppz = prz * sc;
            const float* Ld = sLead[kk];
            float u = tanhf(ppx * Ld[3] + ppy * Ld[4] + ppz * Ld[5]);
            float v = tanhf(ppx * Ld[6] + ppy * Ld[7] + ppz * Ld[8]);
            float pn = fmaxf(th, 1e-8f);
            float cosl = (ppx * Ld[0] + ppy * Ld[1] + ppz * Ld[2]) / pn;
            float hem = fmaxf(cosl, 0.0f);
            float ccv = fminf(fmaxf(cosl, -1.0f + 1e-6f), 1.0f - 1e-6f);
            float theta = acosf(ccv);
            float weight = hem * __expf(-gamma * theta * theta);
            float A = gauss * weight;
            float shp = 0.0f;
            #pragma unroll
            for (int m = 0; m < 9; ++m)
                shp += (sh_base[bn * 9 + m] + sh_vel[bn * 9 + m] * dt) * Ld[9 + m];
            sAA[nl][kk] = make_float2(A, A * shp);
            #pragma unroll
            for (int g = 0; g < GG; ++g) {
                float gx = -1.0f + (float)g * (2.0f / 7.0f);
                float du = u - gx, dv = v - gx;
                sKu[nl][kk][g] = __expf(-inv2tau2 * du * du);
                sKv[nl][kk][g] = __expf(-inv2tau2 * dv * dv);
            }
        }
        __syncthreads();
        #pragma unroll 8
        for (int n2 = 0; n2 < NC; ++n2) {
            float2 aa = sAA[n2][warp];
            float kvh = sKv[n2][warp][hh];
            float ku0 = sKu[n2][warp][w0];
            float ku1 = sKu[n2][warp][w0 + 1];
            float tA = aa.x * kvh, tS = aa.y * kvh;
            acc00 = fmaf(tA, ku0, acc00);
            acc01 = fmaf(tA, ku1, acc01);
            acc10 = fmaf(tS, ku0, acc10);
            acc11 = fmaf(tS, ku1, acc11);
        }
        __syncthreads();
    }
    size_t base = ((size_t)((b * KK + warp) * TT + t)) * 128;
    g_splat[base + px0]          = acc00;
    g_splat[base + px0 + 1]      = acc01;
    g_splat[base + 64 + px0]     = acc10;
    g_splat[base + 64 + px0 + 1] = acc11;
}

// ---------------- kernel 2: CNN readout (chunked H1 for occupancy) ----------
// 128 threads, 4 tiles per block; thread = pixel, handles 2 tiles.
// conv1 -> conv2 processed in four 8-input-channel chunks through a small
// shared H1 buffer so the block fits 55.6KB smem and <=128 regs -> 4 blocks/SM.
#define W2T_OFF  0        // 9216  [ic][j][oc]
#define W1T_OFF  9216     // 576   [c*9+j][oc]
#define B1_OFF   9792     // 32
#define B2_OFF   9824     // 32
#define FC_OFF   9856     // 32
#define FCB_OFF  9888     // 1 (+3 pad)
#define IN_OFF   9892     // 4 tiles * 2 ch * 100  (padded 10x10)
#define H1C_OFF  10692    // 4 tiles * 8 ch * 100 (one chunk)
#define RED_OFF  13892    // 8
#define SMEM_FLOATS 13900

__global__ __launch_bounds__(128, 4) void cnn_kernel(
    const float* __restrict__ b1g, const float* __restrict__ b2g,
    const float* __restrict__ fcw, const float* __restrict__ fcb,
    float* __restrict__ out) {
    extern __shared__ float sm[];
    int tid = threadIdx.x;
    int tile0 = blockIdx.x * 4;
    int group = tid >> 6;           // 0/1 -> tiles {2g, 2g+1}
    int p = tid & 63;
    int x = p & 7, y = p >> 3;

    // ---- stage weights + zero padded buffers ----
    for (int i = tid; i < 800; i += 128) sm[IN_OFF + i] = 0.0f;
    for (int i = tid; i < 3200; i += 128) sm[H1C_OFF + i] = 0.0f;
    {
        float4* dst = (float4*)(sm + W2T_OFF);
        const float4* src = (const float4*)g_w2T;
        for (int i = tid; i < 2304; i += 128) dst[i] = src[i];
        float4* dst1 = (float4*)(sm + W1T_OFF);
        const float4* src1 = (const float4*)g_w1T;
        for (int i = tid; i < 144; i += 128) dst1[i] = src1[i];
    }
    if (tid < 32) {
        sm[B1_OFF + tid] = b1g[tid];
        sm[B2_OFF + tid] = b2g[tid];
        sm[FC_OFF + tid] = fcw[tid];
    }
    if (tid == 0) sm[FCB_OFF] = fcb[0];

    // ---- stage splat inputs into padded IN ----
    __syncthreads();
    for (int i = tid; i < 512; i += 128) {
        int tj = i >> 7;
        int e = i & 127;
        int ch = e >> 6;
        int pp = e & 63;
        int py = pp >> 3, px = pp & 7;
        sm[IN_OFF + (tj * 2 + ch) * 100 + (py + 1) * 10 + (px + 1)] =
            g_splat[(size_t)(tile0 + tj) * 128 + e];
    }
    __syncthreads();

    // conv2 accumulators (persist across chunks): 32 oc as 16 pairs, 2 tiles
    u64 acc0[16], acc1[16];
    #pragma unroll
    for (int q = 0; q < 16; ++q) {
        u64 bb = ((const u64*)(sm + B2_OFF))[q];
        acc0[q] = bb; acc1[q] = bb;
    }

    int ibase0 = IN_OFF + (group * 2 + 0) * 200 + y * 10 + x;
    int ibase1 = IN_OFF + (group * 2 + 1) * 200 + y * 10 + x;
    int hw0 = H1C_OFF + (group * 2 + 0) * 800 + (y + 1) * 10 + (x + 1);
    int hw1 = H1C_OFF + (group * 2 + 1) * 800 + (y + 1) * 10 + (x + 1);
    int pbase = y * 10 + x;

    #pragma unroll 1
    for (int cc = 0; cc < 4; ++cc) {
        // ---- conv1 for 8 output channels (this chunk) ----
        {
            u64 c1a[4], c1b[4];
            #pragma unroll
            for (int q = 0; q < 4; ++q) {
                u64 bb = ((const u64*)(sm + B1_OFF))[cc * 4 + q];
                c1a[q] = bb; c1b[q] = bb;
            }
            #pragma unroll
            for (int c = 0; c < 2; ++c)
                #pragma unroll
                for (int r = 0; r < 3; ++r)
                    #pragma unroll
                    for (int q3 = 0; q3 < 3; ++q3) {
                        int j = c * 9 + r * 3 + q3;
                        u64 pa0 = pack2(sm[ibase0 + c * 100 + r * 10 + q3]);
                        u64 pa1 = pack2(sm[ibase1 + c * 100 + r * 10 + q3]);
                        const ulonglong2* wv =
                            (const ulonglong2*)(sm + W1T_OFF + j * 32 + cc * 8);
                        ulonglong2 w0v = wv[0], w1v = wv[1];
                        ffma2(c1a[0], pa0, w0v.x); ffma2(c1a[1], pa0, w0v.y);
                        ffma2(c1a[2], pa0, w1v.x); ffma2(c1a[3], pa0, w1v.y);
                        ffma2(c1b[0], pa1, w0v.x); ffma2(c1b[1], pa1, w0v.y);
                        ffma2(c1b[2], pa1, w1v.x); ffma2(c1b[3], pa1, w1v.y);
                    }
            #pragma unroll
            for (int q = 0; q < 4; ++q) {
                float lo, hi;
                unpack2(lo, hi, c1a[q]);
                sm[hw0 + (2 * q) * 100]     = lo * normcdff(lo);
                sm[hw0 + (2 * q + 1) * 100] = hi * normcdff(hi);
                unpack2(lo, hi, c1b[q]);
                sm[hw1 + (2 * q) * 100]     = lo * normcdff(lo);
                sm[hw1 + (2 * q + 1) * 100] = hi * normcdff(hi);
            }
        }
        __syncthreads();

        // ---- conv2 partial over these 8 input channels ----
        const float* h1a = sm + H1C_OFF + (group * 2 + 0) * 800;
        const float* h1b = sm + H1C_OFF + (group * 2 + 1) * 800;
        #pragma unroll 1
        for (int icl = 0; icl < 8; ++icl) {
            float a0[9], a1[9];
            int base = icl * 100 + pbase;
            #pragma unroll
            for (int r = 0; r < 3; ++r)
                #pragma unroll
                for (int q3 = 0; q3 < 3; ++q3) {
                    a0[r * 3 + q3] = h1a[base + r * 10 + q3];
                    a1[r * 3 + q3] = h1b[base + r * 10 + q3];
                }
            const float* wrow = sm + W2T_OFF + (cc * 8 + icl) * 288;
            #pragma unroll
            for (int j = 0; j < 9; ++j) {
                u64 pa0 = pack2(a0[j]);
                u64 pa1 = pack2(a1[j]);
                const ulonglong2* wv = (const ulonglong2*)(wrow + j * 32);
                #pragma unroll
                for (int q = 0; q < 8; ++q) {
                    ulonglong2 w = wv[q];
                    ffma2(acc0[2 * q], pa0, w.x); ffma2(acc0[2 * q + 1], pa0, w.y);
                    ffma2(acc1[2 * q], pa1, w.x); ffma2(acc1[2 * q + 1], pa1, w.y);
                }
            }
        }
        __syncthreads();
    }

    // ---- GELU + fc dot per pixel, then mean over 64 pixels ----
    float sa = 0.0f, sb = 0.0f;
    #pragma unroll
    for (int q = 0; q < 16; ++q) {
        float f0 = sm[FC_OFF + 2 * q], f1 = sm[FC_OFF + 2 * q + 1];
        float lo, hi;
        unpack2(lo, hi, acc0[q]);
        sa = fmaf(lo * normcdff(lo), f0, sa);
        sa = fmaf(hi * normcdff(hi), f1, sa);
        unpack2(lo, hi, acc1[q]);
        sb = fmaf(lo * normcdff(lo), f0, sb);
        sb = fmaf(hi * normcdff(hi), f1, sb);
    }
    #pragma unroll
    for (int off = 16; off > 0; off >>= 1) {
        sa += __shfl_down_sync(0xffffffffu, sa, off);
        sb += __shfl_down_sync(0xffffffffu, sb, off);
    }
    int w = tid >> 5;  // warp 0..3
    if ((tid & 31) == 0) {
        sm[RED_OFF + (w >> 1) * 4 + (w & 1) * 2 + 0] = sa;
        sm[RED_OFF + (w >> 1) * 4 + (w & 1) * 2 + 1] = sb;
    }
    __syncthreads();
    if (tid < 4) {
        int grp = tid >> 1, sel = tid & 1;
        float v = sm[RED_OFF + grp * 4 + sel] + sm[RED_OFF + grp * 4 + 2 + sel];
        v = v * (1.0f / 64.0f) + sm[FCB_OFF];
        int tile = tile0 + tid;
        int b = tile / (KK * TT);
        int rem = tile - b * (KK * TT);
        int k = rem / TT;
        int t = rem - k * TT;
        out[(b * TT + t) * KK + k] = v;
    }
}

// ---------------- launch ----------------
extern "C" void kernel_launch(void* const* d_in, const int* in_sizes, int n_in,
                              void* d_out, int out_size) {
    const float* mu        = (const float*)d_in[0];
    const float* sigma0    = (const float*)d_in[1];
    const float* sigma_vel = (const float*)d_in[2];
    const float* amplitude = (const float*)d_in[3];
    const float* sh_base   = (const float*)d_in[4];
    const float* sh_vel    = (const float*)d_in[5];
    const float* p0        = (const float*)d_in[6];
    const float* p_vel     = (const float*)d_in[7];
    const float* tau_raw   = (const float*)d_in[8];
    const float* gam_raw   = (const float*)d_in[9];
    const float* limb_ra   = (const float*)d_in[10];
    const float* limb_la   = (const float*)d_in[11];
    const float* limb_ll   = (const float*)d_in[12];
    const float* chest     = (const float*)d_in[13];
    const float* conv1_w   = (const float*)d_in[14];
    const float* conv1_b   = (const float*)d_in[15];
    const float* conv2_w   = (const float*)d_in[16];
    const float* conv2_b   = (const float*)d_in[17];
    const float* fc_w      = (const float*)d_in[18];
    const float* fc_b      = (const float*)d_in[19];
    float* out = (float*)d_out;

    prep_kernel<<<1, 256>>>(limb_ra, limb_la, limb_ll, chest, conv1_w, conv2_w);
    splat_kernel<<<dim3(TT, BB), 384>>>(mu, sigma0, sigma_vel, amplitude,
                                        sh_base, sh_vel, p0, p_vel, tau_raw, gam_raw);
    size_t shbytes = SMEM_FLOATS * sizeof(float);
    cudaFuncSetAttribute(cnn_kernel, cudaFuncAttributeMaxDynamicSharedMemorySize, (int)shbytes);
    cnn_kernel<<<(BB * KK * TT) / 4, 128, shbytes>>>(conv1_b, conv2_b, fc_w, fc_b, out);
}

// round 5
// speedup vs baseline: 1.1121x; 1.1121x over previous
#include <cuda_runtime.h>
#include <math.h>

// Problem dims (fixed by the dataset)
#define BB 4
#define NN 96
#define TT 512
#define KK 12
#define GG 8

// ---------------- device scratch (no cudaMalloc allowed) ----------------
__device__ float g_lead[KK * 18];                         // per lead: L(3), e1(3), e2(3), Y(9)
__device__ float g_splat[(size_t)BB * KK * TT * 128];     // (B,K,T,2,8,8)
__device__ float g_w2T[9216];                             // conv2 weights transposed [ic][j][oc]
__device__ float g_w1T[576];                              // conv1 weights transposed [c*9+j][oc]

typedef unsigned long long u64;

__device__ __forceinline__ u64 pack2(float x) {
    u64 r; asm("mov.b64 %0, {%1, %1};" : "=l"(r) : "f"(x)); return r;
}
__device__ __forceinline__ void ffma2(u64& d, u64 a, u64 b) {
    asm("fma.rn.f32x2 %0, %1, %2, %0;" : "+l"(d) : "l"(a), "l"(b));
}
__device__ __forceinline__ void unpack2(float& lo, float& hi, u64 v) {
    asm("mov.b64 {%0, %1}, %2;" : "=f"(lo), "=f"(hi) : "l"(v));
}

__device__ __forceinline__ float softplusf(float x) {
    return (x > 20.0f) ? x : log1pf(expf(x));
}
// fast softplus: __expf/__logf (rel err ~5e-7) — called per (n,k,t) in splat
__device__ __forceinline__ float softplus_fast(float x) {
    return (x > 20.0f) ? x : __logf(1.0f + __expf(x));
}
// fast tanh via exp identity; rel err ~1e-6
__device__ __forceinline__ float tanh_fast(float x) {
    float xc = fminf(fmaxf(x, -15.0f), 15.0f);
    float t = __expf(2.0f * xc);
    return (t - 1.0f) * __fdividef(1.0f, t + 1.0f);
}
// acos minimax for c in [0,1] (abs err ~6.8e-5); only used where hem>0
__device__ __forceinline__ float acos_fast01(float c) {
    float p = sqrtf(fmaxf(1.0f - c, 0.0f));
    float poly = fmaf(c, fmaf(c, fmaf(c, -0.0187293f, 0.0742610f), -0.2121144f), 1.5707288f);
    return p * poly;
}
// GELU via A&S erf approx (abs err ~1.5e-7)
__device__ __forceinline__ float gelu_fast(float x) {
    float ax = fabsf(x);
    float z = ax * 0.70710678118f;
    float t = __fdividef(1.0f, fmaf(0.3275911f, z, 1.0f));
    float poly = t * fmaf(t, fmaf(t, fmaf(t, fmaf(t, 1.061405429f, -1.453152027f),
                                          1.421413741f), -0.284496736f), 0.254829592f);
    float e = __expf(-z * z);
    float erfv = fmaf(-poly, e, 1.0f);          // erf(|x|/sqrt2)
    erfv = copysignf(erfv, x);
    return 0.5f * x * (1.0f + erfv);
}

// ---------------- kernel 0: leads + weight transposes ----------------
__global__ void prep_kernel(const float* __restrict__ ra, const float* __restrict__ la,
                            const float* __restrict__ ll, const float* __restrict__ chest,
                            const float* __restrict__ w1, const float* __restrict__ w2) {
    int tid = threadIdx.x;
    for (int idx = tid; idx < 9216; idx += 256) {
        int oc = idx / 288;
        int rem = idx - oc * 288;   // ic*9 + j
        g_w2T[rem * 32 + oc] = w2[idx];
    }
    for (int idx = tid; idx < 576; idx += 256) {
        int oc = idx / 18;
        int r = idx - oc * 18;
        g_w1T[r * 32 + oc] = w1[idx];
    }
    if (tid >= KK) return;
    int k = tid;
    float vx, vy, vz;
    float rax = ra[0], ray = ra[1], raz = ra[2];
    float lax = la[0], lay = la[1], laz = la[2];
    float llx = ll[0], lly = ll[1], llz = ll[2];
    switch (k) {
        case 0: vx = lax - rax; vy = lay - ray; vz = laz - raz; break;
        case 1: vx = llx - rax; vy = lly - ray; vz = llz - raz; break;
        case 2: vx = llx - lax; vy = lly - lay; vz = llz - laz; break;
        case 3: vx = rax - 0.5f * (lax + llx); vy = ray - 0.5f * (lay + lly); vz = raz - 0.5f * (laz + llz); break;
        case 4: vx = lax - 0.5f * (rax + llx); vy = lay - 0.5f * (ray + lly); vz = laz - 0.5f * (raz + llz); break;
        case 5: vx = llx - 0.5f * (rax + lax); vy = lly - 0.5f * (ray + lay); vz = llz - 0.5f * (raz + laz); break;
        default:
            vx = chest[(k - 6) * 3 + 0]; vy = chest[(k - 6) * 3 + 1]; vz = chest[(k - 6) * 3 + 2];
            break;
    }
    float n = sqrtf(vx * vx + vy * vy + vz * vz);
    float d = fmaxf(n, 1e-6f);
    float Lx = vx / d, Ly = vy / d, Lz = vz / d;
    float e1x = 0.0f, e1y = Lz, e1z = -Ly;
    float n1 = sqrtf(e1y * e1y + e1z * e1z);
    if (n1 < 1e-4f) { e1x = -Lz; e1y = 0.0f; e1z = Lx; n1 = sqrtf(e1x * e1x + e1z * e1z); }
    float d1 = fmaxf(n1, 1e-6f);
    e1x /= d1; e1y /= d1; e1z /= d1;
    float e2x = e1y * Lz - e1z * Ly;
    float e2y = e1z * Lx - e1x * Lz;
    float e2z = e1x * Ly - e1y * Lx;
    float n2 = sqrtf(e2x * e2x + e2y * e2y + e2z * e2z);
    float d2 = fmaxf(n2, 1e-6f);
    e2x /= d2; e2y /= d2; e2z /= d2;
    float* o = g_lead + k * 18;
    o[0] = Lx; o[1] = Ly; o[2] = Lz;
    o[3] = e1x; o[4] = e1y; o[5] = e1z;
    o[6] = e2x; o[7] = e2y; o[8] = e2z;
    o[9]  = 0.282095f;
    o[10] = -0.488603f * Ly;
    o[11] = 0.488603f * Lz;
    o[12] = -0.488603f * Lx;
    o[13] = 1.092548f * Lx * Ly;
    o[14] = -1.092548f * Ly * Lz;
    o[15] = 0.315392f * (3.0f * Lz * Lz - 1.0f);
    o[16] = -1.092548f * Lx * Lz;
    o[17] = 0.546274f * (Lx * Lx - Ly * Ly);
}

// ---------------- kernel 1: splat rasterization ----------------
#define NC 32

__global__ __launch_bounds__(384) void splat_kernel(
    const float* __restrict__ mu, const float* __restrict__ sigma0,
    const float* __restrict__ sigma_vel, const float* __restrict__ amplitude,
    const float* __restrict__ sh_base, const float* __restrict__ sh_vel,
    const float* __restrict__ p0, const float* __restrict__ p_vel,
    const float* __restrict__ tau_raw, const float* __restrict__ gam_raw) {
    __shared__ float  sLead[KK][18];
    __shared__ float2 sAA[NC][KK];
    __shared__ float  sKu[NC][KK][9];
    __shared__ float  sKv[NC][KK][9];

    int t = blockIdx.x, b = blockIdx.y;
    int tid = threadIdx.x;
    if (tid < KK * 18) ((float*)sLead)[tid] = g_lead[tid];

    float tau = softplusf(tau_raw[0]) + 0.06f;   // once per thread: keep precise
    float inv2tau2 = 0.5f / (tau * tau);
    float gamma = softplusf(gam_raw[0]) + 1e-6f;
    float tval = (float)t * (1.0f / (float)(TT - 1));

    int warp = tid >> 5, lane = tid & 31;
    int px0 = lane * 2;
    int hh = px0 >> 3, w0 = px0 & 7;
    float acc00 = 0.f, acc01 = 0.f, acc10 = 0.f, acc11 = 0.f;

    int nl = tid / KK, kk = tid - nl * KK;
    __syncthreads();

    for (int c = 0; c < NN / NC; ++c) {
        {
            int n = c * NC + nl;
            int bn = b * NN + n;
            float dt = tval - mu[bn];
            float sig = softplus_fast(sigma0[bn] + sigma_vel[bn] * dt) + 1e-3f;
            float z = dt * __fdividef(1.0f, sig);
            float gauss = amplitude[bn] * __expf(-0.5f * z * z);
            float prx = p0[bn * 3 + 0] + p_vel[bn * 3 + 0] * dt;
            float pry = p0[bn * 3 + 1] + p_vel[bn * 3 + 1] * dt;
            float prz = p0[bn * 3 + 2] + p_vel[bn * 3 + 2] * dt;
            float nrm = fmaxf(sqrtf(prx * prx + pry * pry + prz * prz), 1e-8f);
            float th = tanh_fast(nrm);
            float sc = th * __fdividef(1.0f, nrm);
            float ppx = prx * sc, ppy = pry * sc, ppz = prz * sc;
            const float* Ld = sLead[kk];
            float u = tanh_fast(ppx * Ld[3] + ppy * Ld[4] + ppz * Ld[5]);
            float v = tanh_fast(ppx * Ld[6] + ppy * Ld[7] + ppz * Ld[8]);
            float pn = fmaxf(th, 1e-8f);
            float cosl = (ppx * Ld[0] + ppy * Ld[1] + ppz * Ld[2]) * __fdividef(1.0f, pn);
            float hem = fmaxf(cosl, 0.0f);
            float ccv = fminf(fmaxf(cosl, -1.0f + 1e-6f), 1.0f - 1e-6f);
            float theta = acos_fast01(ccv);
            float weight = hem * __expf(-gamma * theta * theta);
            float A = gauss * weight;
            float shp = 0.0f;
            #pragma unroll
            for (int m = 0; m < 9; ++m)
                shp += (sh_base[bn * 9 + m] + sh_vel[bn * 9 + m] * dt) * Ld[9 + m];
            sAA[nl][kk] = make_float2(A, A * shp);
            #pragma unroll
            for (int g = 0; g < GG; ++g) {
                float gx = -1.0f + (float)g * (2.0f / 7.0f);
                float du = u - gx, dv = v - gx;
                sKu[nl][kk][g] = __expf(-inv2tau2 * du * du);
                sKv[nl][kk][g] = __expf(-inv2tau2 * dv * dv);
            }
        }
        __syncthreads();
        #pragma unroll 8
        for (int n2 = 0; n2 < NC; ++n2) {
            float2 aa = sAA[n2][warp];
            float kvh = sKv[n2][warp][hh];
            float ku0 = sKu[n2][warp][w0];
            float ku1 = sKu[n2][warp][w0 + 1];
            float tA = aa.x * kvh, tS = aa.y * kvh;
            acc00 = fmaf(tA, ku0, acc00);
            acc01 = fmaf(tA, ku1, acc01);
            acc10 = fmaf(tS, ku0, acc10);
            acc11 = fmaf(tS, ku1, acc11);
        }
        __syncthreads();
    }
    size_t base = ((size_t)((b * KK + warp) * TT + t)) * 128;
    g_splat[base + px0]          = acc00;
    g_splat[base + px0 + 1]      = acc01;
    g_splat[base + 64 + px0]     = acc10;
    g_splat[base + 64 + px0 + 1] = acc11;
}

// ---------------- kernel 2: CNN readout (chunked H1 for occupancy) ----------
#define W2T_OFF  0        // 9216  [ic][j][oc]
#define W1T_OFF  9216     // 576   [c*9+j][oc]
#define B1_OFF   9792     // 32
#define B2_OFF   9824     // 32
#define FC_OFF   9856     // 32
#define FCB_OFF  9888     // 1 (+3 pad)
#define IN_OFF   9892     // 4 tiles * 2 ch * 100  (padded 10x10)
#define H1C_OFF  10692    // 4 tiles * 8 ch * 100 (one chunk)
#define RED_OFF  13892    // 8
#define SMEM_FLOATS 13900

__global__ __launch_bounds__(128, 4) void cnn_kernel(
    const float* __restrict__ b1g, const float* __restrict__ b2g,
    const float* __restrict__ fcw, const float* __restrict__ fcb,
    float* __restrict__ out) {
    extern __shared__ float sm[];
    int tid = threadIdx.x;
    int tile0 = blockIdx.x * 4;
    int group = tid >> 6;           // 0/1 -> tiles {2g, 2g+1}
    int p = tid & 63;
    int x = p & 7, y = p >> 3;

    // ---- stage weights + zero padded buffers ----
    for (int i = tid; i < 800; i += 128) sm[IN_OFF + i] = 0.0f;
    for (int i = tid; i < 3200; i += 128) sm[H1C_OFF + i] = 0.0f;
    {
        float4* dst = (float4*)(sm + W2T_OFF);
        const float4* src = (const float4*)g_w2T;
        for (int i = tid; i < 2304; i += 128) dst[i] = src[i];
        float4* dst1 = (float4*)(sm + W1T_OFF);
        const float4* src1 = (const float4*)g_w1T;
        for (int i = tid; i < 144; i += 128) dst1[i] = src1[i];
    }
    if (tid < 32) {
        sm[B1_OFF + tid] = b1g[tid];
        sm[B2_OFF + tid] = b2g[tid];
        sm[FC_OFF + tid] = fcw[tid];
    }
    if (tid == 0) sm[FCB_OFF] = fcb[0];

    // ---- stage splat inputs into padded IN ----
    __syncthreads();
    for (int i = tid; i < 512; i += 128) {
        int tj = i >> 7;
        int e = i & 127;
        int ch = e >> 6;
        int pp = e & 63;
        int py = pp >> 3, px = pp & 7;
        sm[IN_OFF + (tj * 2 + ch) * 100 + (py + 1) * 10 + (px + 1)] =
            g_splat[(size_t)(tile0 + tj) * 128 + e];
    }
    __syncthreads();

    // conv2 accumulators (persist across chunks): 32 oc as 16 pairs, 2 tiles
    u64 acc0[16], acc1[16];
    #pragma unroll
    for (int q = 0; q < 16; ++q) {
        u64 bb = ((const u64*)(sm + B2_OFF))[q];
        acc0[q] = bb; acc1[q] = bb;
    }

    int ibase0 = IN_OFF + (group * 2 + 0) * 200 + y * 10 + x;
    int ibase1 = IN_OFF + (group * 2 + 1) * 200 + y * 10 + x;
    int hw0 = H1C_OFF + (group * 2 + 0) * 800 + (y + 1) * 10 + (x + 1);
    int hw1 = H1C_OFF + (group * 2 + 1) * 800 + (y + 1) * 10 + (x + 1);
    int pbase = y * 10 + x;

    #pragma unroll 1
    for (int cc = 0; cc < 4; ++cc) {
        // ---- conv1 for 8 output channels (this chunk) ----
        {
            u64 c1a[4], c1b[4];
            #pragma unroll
            for (int q = 0; q < 4; ++q) {
                u64 bb = ((const u64*)(sm + B1_OFF))[cc * 4 + q];
                c1a[q] = bb; c1b[q] = bb;
            }
            #pragma unroll
            for (int c = 0; c < 2; ++c)
                #pragma unroll
                for (int r = 0; r < 3; ++r)
                    #pragma unroll
                    for (int q3 = 0; q3 < 3; ++q3) {
                        int j = c * 9 + r * 3 + q3;
                        u64 pa0 = pack2(sm[ibase0 + c * 100 + r * 10 + q3]);
                        u64 pa1 = pack2(sm[ibase1 + c * 100 + r * 10 + q3]);
                        const ulonglong2* wv =
                            (const ulonglong2*)(sm + W1T_OFF + j * 32 + cc * 8);
                        ulonglong2 w0v = wv[0], w1v = wv[1];
                        ffma2(c1a[0], pa0, w0v.x); ffma2(c1a[1], pa0, w0v.y);
                        ffma2(c1a[2], pa0, w1v.x); ffma2(c1a[3], pa0, w1v.y);
                        ffma2(c1b[0], pa1, w0v.x); ffma2(c1b[1], pa1, w0v.y);
                        ffma2(c1b[2], pa1, w1v.x); ffma2(c1b[3], pa1, w1v.y);
                    }
            #pragma unroll
            for (int q = 0; q < 4; ++q) {
                float lo, hi;
                unpack2(lo, hi, c1a[q]);
                sm[hw0 + (2 * q) * 100]     = gelu_fast(lo);
                sm[hw0 + (2 * q + 1) * 100] = gelu_fast(hi);
                unpack2(lo, hi, c1b[q]);
                sm[hw1 + (2 * q) * 100]     = gelu_fast(lo);
                sm[hw1 + (2 * q + 1) * 100] = gelu_fast(hi);
            }
        }
        __syncthreads();

        // ---- conv2 partial over these 8 input channels ----
        const float* h1a = sm + H1C_OFF + (group * 2 + 0) * 800;
        const float* h1b = sm + H1C_OFF + (group * 2 + 1) * 800;
        #pragma unroll 1
        for (int icl = 0; icl < 8; ++icl) {
            float a0[9], a1[9];
            int base = icl * 100 + pbase;
            #pragma unroll
            for (int r = 0; r < 3; ++r)
                #pragma unroll
                for (int q3 = 0; q3 < 3; ++q3) {
                    a0[r * 3 + q3] = h1a[base + r * 10 + q3];
                    a1[r * 3 + q3] = h1b[base + r * 10 + q3];
                }
            const float* wrow = sm + W2T_OFF + (cc * 8 + icl) * 288;
            #pragma unroll
            for (int j = 0; j < 9; ++j) {
                u64 pa0 = pack2(a0[j]);
                u64 pa1 = pack2(a1[j]);
                const ulonglong2* wv = (const ulonglong2*)(wrow + j * 32);
                #pragma unroll
                for (int q = 0; q < 8; ++q) {
                    ulonglong2 w = wv[q];
                    ffma2(acc0[2 * q], pa0, w.x); ffma2(acc0[2 * q + 1], pa0, w.y);
                    ffma2(acc1[2 * q], pa1, w.x); ffma2(acc1[2 * q + 1], pa1, w.y);
                }
            }
        }
        __syncthreads();
    }

    // ---- GELU + fc dot per pixel, then mean over 64 pixels ----
    float sa = 0.0f, sb = 0.0f;
    #pragma unroll
    for (int q = 0; q < 16; ++q) {
        float f0 = sm[FC_OFF + 2 * q], f1 = sm[FC_OFF + 2 * q + 1];
        float lo, hi;
        unpack2(lo, hi, acc0[q]);
        sa = fmaf(gelu_fast(lo), f0, sa);
        sa = fmaf(gelu_fast(hi), f1, sa);
        unpack2(lo, hi, acc1[q]);
        sb = fmaf(gelu_fast(lo), f0, sb);
        sb = fmaf(gelu_fast(hi), f1, sb);
    }
    #pragma unroll
    for (int off = 16; off > 0; off >>= 1) {
        sa += __shfl_down_sync(0xffffffffu, sa, off);
        sb += __shfl_down_sync(0xffffffffu, sb, off);
    }
    int w = tid >> 5;  // warp 0..3
    if ((tid & 31) == 0) {
        sm[RED_OFF + (w >> 1) * 4 + (w & 1) * 2 + 0] = sa;
        sm[RED_OFF + (w >> 1) * 4 + (w & 1) * 2 + 1] = sb;
    }
    __syncthreads();
    if (tid < 4) {
        int grp = tid >> 1, sel = tid & 1;
        float v = sm[RED_OFF + grp * 4 + sel] + sm[RED_OFF + grp * 4 + 2 + sel];
        v = v * (1.0f / 64.0f) + sm[FCB_OFF];
        int tile = tile0 + tid;
        int b = tile / (KK * TT);
        int rem = tile - b * (KK * TT);
        int k = rem / TT;
        int t = rem - k * TT;
        out[(b * TT + t) * KK + k] = v;
    }
}

// ---------------- launch ----------------
extern "C" void kernel_launch(void* const* d_in, const int* in_sizes, int n_in,
                              void* d_out, int out_size) {
    const float* mu        = (const float*)d_in[0];
    const float* sigma0    = (const float*)d_in[1];
    const float* sigma_vel = (const float*)d_in[2];
    const float* amplitude = (const float*)d_in[3];
    const float* sh_base   = (const float*)d_in[4];
    const float* sh_vel    = (const float*)d_in[5];
    const float* p0        = (const float*)d_in[6];
    const float* p_vel     = (const float*)d_in[7];
    const float* tau_raw   = (const float*)d_in[8];
    const float* gam_raw   = (const float*)d_in[9];
    const float* limb_ra   = (const float*)d_in[10];
    const float* limb_la   = (const float*)d_in[11];
    const float* limb_ll   = (const float*)d_in[12];
    const float* chest     = (const float*)d_in[13];
    const float* conv1_w   = (const float*)d_in[14];
    const float* conv1_b   = (const float*)d_in[15];
    const float* conv2_w   = (const float*)d_in[16];
    const float* conv2_b   = (const float*)d_in[17];
    const float* fc_w      = (const float*)d_in[18];
    const float* fc_b      = (const float*)d_in[19];
    float* out = (float*)d_out;

    prep_kernel<<<1, 256>>>(limb_ra, limb_la, limb_ll, chest, conv1_w, conv2_w);
    splat_kernel<<<dim3(TT, BB), 384>>>(mu, sigma0, sigma_vel, amplitude,
                                        sh_base, sh_vel, p0, p_vel, tau_raw, gam_raw);
    size_t shbytes = SMEM_FLOATS * sizeof(float);
    cudaFuncSetAttribute(cnn_kernel, cudaFuncAttributeMaxDynamicSharedMemorySize, (int)shbytes);
    cnn_kernel<<<(BB * KK * TT) / 4, 128, shbytes>>>(conv1_b, conv2_b, fc_w, fc_b, out);
}

// round 7
// speedup vs baseline: 1.8318x; 1.6472x over previous
#include <cuda_runtime.h>
#include <cuda_bf16.h>
#include <math.h>
#include <stdint.h>

// Problem dims (fixed by the dataset)
#define BB 4
#define NN 96
#define TT 512
#define KK 12
#define GG 8

typedef unsigned long long u64;

// ---------------- device scratch (no cudaMalloc allowed) ----------------
__device__ float g_lead[KK * 18];
__device__ float g_splat[(size_t)BB * KK * TT * 128];     // (B,K,T,2,8,8)
__device__ float g_w1T[576];                              // conv1 weights [c*9+j][oc]
// conv2 B-matrix fragments in mma.m16n8k16 register order, hi/lo split:
// index = (((s*18 + ks)*4 + n8)*32 + lane)*2 + r   (uint32, bf16x2 each)
__device__ __align__(16) uint32_t g_bfrag[9216];

// ---------------- small helpers ----------------
__device__ __forceinline__ u64 pack2(float x) {
    u64 r; asm("mov.b64 %0, {%1, %1};" : "=l"(r) : "f"(x)); return r;
}
__device__ __forceinline__ void ffma2(u64& d, u64 a, u64 b) {
    asm("fma.rn.f32x2 %0, %1, %2, %0;" : "+l"(d) : "l"(a), "l"(b));
}
__device__ __forceinline__ void unpack2(float& lo, float& hi, u64 v) {
    asm("mov.b64 {%0, %1}, %2;" : "=f"(lo), "=f"(hi) : "l"(v));
}
__device__ __forceinline__ float softplusf(float x) {
    return (x > 20.0f) ? x : log1pf(expf(x));
}
__device__ __forceinline__ float softplus_fast(float x) {
    return (x > 20.0f) ? x : __logf(1.0f + __expf(x));
}
__device__ __forceinline__ float tanh_fast(float x) {
    float xc = fminf(fmaxf(x, -15.0f), 15.0f);
    float t = __expf(2.0f * xc);
    return (t - 1.0f) * __fdividef(1.0f, t + 1.0f);
}
// Pade [5/4] tanh, valid |x|<=1 (args are dots of unit vectors with |p|<1)
__device__ __forceinline__ float tanh_pade(float x) {
    float x2 = x * x;
    float p = fmaf(fmaf(x2, 1.0f, 105.0f), x2, 945.0f);
    float q = fmaf(fmaf(15.0f, x2, 420.0f), x2, 945.0f);
    return __fdividef(x * p, q);
}
__device__ __forceinline__ float acos_fast01(float c) {
    float p = sqrtf(fmaxf(1.0f - c, 0.0f));
    float poly = fmaf(c, fmaf(c, fmaf(c, -0.0187293f, 0.0742610f), -0.2121144f), 1.5707288f);
    return p * poly;
}
__device__ __forceinline__ float gelu_fast(float x) {
    float ax = fabsf(x);
    float z = ax * 0.70710678118f;
    float t = __fdividef(1.0f, fmaf(0.3275911f, z, 1.0f));
    float poly = t * fmaf(t, fmaf(t, fmaf(t, fmaf(t, 1.061405429f, -1.453152027f),
                                          1.421413741f), -0.284496736f), 0.254829592f);
    float e = __expf(-z * z);
    float erfv = fmaf(-poly, e, 1.0f);
    erfv = copysignf(erfv, x);
    return 0.5f * x * (1.0f + erfv);
}
__device__ __forceinline__ uint32_t smem_u32(const void* p) {
    uint32_t a;
    asm("{ .reg .u64 t; cvta.to.shared.u64 t, %1; cvt.u32.u64 %0, t; }" : "=r"(a) : "l"(p));
    return a;
}
// pack two f32 -> bf16x2 (lo = a, hi = b)
#define CVTPACK(r, a, b) \
    asm("cvt.rn.bf16x2.f32 %0, %2, %1;" : "=r"(r) : "f"(a), "f"(b))
// ldmatrix x4 (A fragments)
#define LDMATRIX_X4(r0, r1, r2, r3, addr) \
    asm volatile("ldmatrix.sync.aligned.m8n8.x4.shared.b16 {%0,%1,%2,%3}, [%4];" \
                 : "=r"(r0), "=r"(r1), "=r"(r2), "=r"(r3) : "r"(addr))
// bf16 mma m16n8k16, C += A*B
#define MMA16816(c, a, b) \
    asm volatile("mma.sync.aligned.m16n8k16.row.col.f32.bf16.bf16.f32 " \
                 "{%0,%1,%2,%3},{%4,%5,%6,%7},{%8,%9},{%0,%1,%2,%3};" \
                 : "+f"((c)[0]), "+f"((c)[1]), "+f"((c)[2]), "+f"((c)[3]) \
                 : "r"((a)[0]), "r"((a)[1]), "r"((a)[2]), "r"((a)[3]), \
                   "r"((b).x), "r"((b).y))

// ---------------- kernel 0: leads + conv1 transpose + conv2 B-fragments ----
__global__ void prep_kernel(const float* __restrict__ ra, const float* __restrict__ la,
                            const float* __restrict__ ll, const float* __restrict__ chest,
                            const float* __restrict__ w1, const float* __restrict__ w2) {
    int tid = threadIdx.x;
    // conv2 B fragments: for each (s, ks, n8, lane, r) pack B[k][oc], B[k+1][oc]
    for (int i = tid; i < 9216; i += 256) {
        int r = i & 1;
        int lane = (i >> 1) & 31;
        int n8 = (i >> 6) & 3;
        int rest = i >> 8;               // 0..35
        int ks = rest % 18;
        int s = rest / 18;               // 0=hi, 1=lo
        int oc = n8 * 8 + (lane >> 2);
        int k0 = ks * 16 + (lane & 3) * 2 + r * 8;
        uint32_t pk = 0;
        #pragma unroll
        for (int e = 0; e < 2; ++e) {
            int k = k0 + e;
            int j = k / 32, ic = k % 32;
            float w = w2[oc * 288 + ic * 9 + j];
            __nv_bfloat16 h = __float2bfloat16(w);
            unsigned short bits;
            if (s == 0) bits = __bfloat16_as_ushort(h);
            else {
                float hf = __bfloat162float(h);
                bits = __bfloat16_as_ushort(__float2bfloat16(w - hf));
            }
            pk |= (uint32_t)bits << (16 * e);
        }
        g_bfrag[i] = pk;
    }
    for (int idx = tid; idx < 576; idx += 256) {
        int oc = idx / 18;
        int r = idx - oc * 18;
        g_w1T[r * 32 + oc] = w1[idx];
    }
    if (tid >= KK) return;
    int k = tid;
    float vx, vy, vz;
    float rax = ra[0], ray = ra[1], raz = ra[2];
    float lax = la[0], lay = la[1], laz = la[2];
    float llx = ll[0], lly = ll[1], llz = ll[2];
    switch (k) {
        case 0: vx = lax - rax; vy = lay - ray; vz = laz - raz; break;
        case 1: vx = llx - rax; vy = lly - ray; vz = llz - raz; break;
        case 2: vx = llx - lax; vy = lly - lay; vz = llz - laz; break;
        case 3: vx = rax - 0.5f * (lax + llx); vy = ray - 0.5f * (lay + lly); vz = raz - 0.5f * (laz + llz); break;
        case 4: vx = lax - 0.5f * (rax + llx); vy = lay - 0.5f * (ray + lly); vz = laz - 0.5f * (raz + llz); break;
        case 5: vx = llx - 0.5f * (rax + lax); vy = lly - 0.5f * (ray + lay); vz = llz - 0.5f * (raz + laz); break;
        default:
            vx = chest[(k - 6) * 3 + 0]; vy = chest[(k - 6) * 3 + 1]; vz = chest[(k - 6) * 3 + 2];
            break;
    }
    float n = sqrtf(vx * vx + vy * vy + vz * vz);
    float d = fmaxf(n, 1e-6f);
    float Lx = vx / d, Ly = vy / d, Lz = vz / d;
    float e1x = 0.0f, e1y = Lz, e1z = -Ly;
    float n1 = sqrtf(e1y * e1y + e1z * e1z);
    if (n1 < 1e-4f) { e1x = -Lz; e1y = 0.0f; e1z = Lx; n1 = sqrtf(e1x * e1x + e1z * e1z); }
    float d1 = fmaxf(n1, 1e-6f);
    e1x /= d1; e1y /= d1; e1z /= d1;
    float e2x = e1y * Lz - e1z * Ly;
    float e2y = e1z * Lx - e1x * Lz;
    float e2z = e1x * Ly - e1y * Lx;
    float n2 = sqrtf(e2x * e2x + e2y * e2y + e2z * e2z);
    float d2 = fmaxf(n2, 1e-6f);
    e2x /= d2; e2y /= d2; e2z /= d2;
    float* o = g_lead + k * 18;
    o[0] = Lx; o[1] = Ly; o[2] = Lz;
    o[3] = e1x; o[4] = e1y; o[5] = e1z;
    o[6] = e2x; o[7] = e2y; o[8] = e2z;
    o[9]  = 0.282095f;
    o[10] = -0.488603f * Ly;
    o[11] = 0.488603f * Lz;
    o[12] = -0.488603f * Lx;
    o[13] = 1.092548f * Lx * Ly;
    o[14] = -1.092548f * Ly * Lz;
    o[15] = 0.315392f * (3.0f * Lz * Lz - 1.0f);
    o[16] = -1.092548f * Lx * Lz;
    o[17] = 0.546274f * (Lx * Lx - Ly * Ly);
}

// ---------------- kernel 1: splat rasterization ----------------
#define NC 32

__global__ __launch_bounds__(384) void splat_kernel(
    const float* __restrict__ mu, const float* __restrict__ sigma0,
    const float* __restrict__ sigma_vel, const float* __restrict__ amplitude,
    const float* __restrict__ sh_base, const float* __restrict__ sh_vel,
    const float* __restrict__ p0, const float* __restrict__ p_vel,
    const float* __restrict__ tau_raw, const float* __restrict__ gam_raw) {
    __shared__ float  sLead[KK][18];
    __shared__ float2 sAA[NC][KK];
    __shared__ float  sKu[NC][KK][9];
    __shared__ float  sKv[NC][KK][9];

    int t = blockIdx.x, b = blockIdx.y;
    int tid = threadIdx.x;
    if (tid < KK * 18) ((float*)sLead)[tid] = g_lead[tid];

    float tau = softplusf(tau_raw[0]) + 0.06f;
    float inv2tau2 = 0.5f / (tau * tau);
    float gamma = softplusf(gam_raw[0]) + 1e-6f;
    float tval = (float)t * (1.0f / (float)(TT - 1));
    const float DLT = 2.0f / 7.0f;
    float aD = inv2tau2 * DLT;
    float Cc = __expf(-2.0f * aD * DLT);   // exp recurrence constant

    int warp = tid >> 5, lane = tid & 31;
    int px0 = lane * 2;
    int hh = px0 >> 3, w0 = px0 & 7;
    float acc00 = 0.f, acc01 = 0.f, acc10 = 0.f, acc11 = 0.f;

    int nl = tid / KK, kk = tid - nl * KK;
    __syncthreads();

    for (int c = 0; c < NN / NC; ++c) {
        {
            int n = c * NC + nl;
            int bn = b * NN + n;
            float dt = tval - mu[bn];
            float sig = softplus_fast(sigma0[bn] + sigma_vel[bn] * dt) + 1e-3f;
            float z = dt * __fdividef(1.0f, sig);
            float gauss = amplitude[bn] * __expf(-0.5f * z * z);
            float prx = p0[bn * 3 + 0] + p_vel[bn * 3 + 0] * dt;
            float pry = p0[bn * 3 + 1] + p_vel[bn * 3 + 1] * dt;
            float prz = p0[bn * 3 + 2] + p_vel[bn * 3 + 2] * dt;
            float nrm = fmaxf(sqrtf(prx * prx + pry * pry + prz * prz), 1e-8f);
            float th = tanh_fast(nrm);
            float sc = th * __fdividef(1.0f, nrm);
            float ppx = prx * sc, ppy = pry * sc, ppz = prz * sc;
            const float* Ld = sLead[kk];
            float u = tanh_pade(ppx * Ld[3] + ppy * Ld[4] + ppz * Ld[5]);
            float v = tanh_pade(ppx * Ld[6] + ppy * Ld[7] + ppz * Ld[8]);
            float pn = fmaxf(th, 1e-8f);
            float cosl = (ppx * Ld[0] + ppy * Ld[1] + ppz * Ld[2]) * __fdividef(1.0f, pn);
            float hem = fmaxf(cosl, 0.0f);
            float ccv = fminf(fmaxf(cosl, -1.0f + 1e-6f), 1.0f - 1e-6f);
            float theta = acos_fast01(ccv);
            float weight = hem * __expf(-gamma * theta * theta);
            float A = gauss * weight;
            float shp = 0.0f;
            #pragma unroll
            for (int m = 0; m < 9; ++m)
                shp += (sh_base[bn * 9 + m] + sh_vel[bn * 9 + m] * dt) * Ld[9 + m];
            sAA[nl][kk] = make_float2(A, A * shp);
            // Gaussian grid via exp recurrence: 2 exp per axis instead of 8
            {
                float d0 = u + 1.0f;
                float Kx = __expf(-inv2tau2 * d0 * d0);
                float Rx = __expf(aD * (2.0f * d0 - DLT));
                #pragma unroll
                for (int g = 0; g < GG; ++g) { sKu[nl][kk][g] = Kx; Kx *= Rx; Rx *= Cc; }
                float d0v = v + 1.0f;
                float Kv2 = __expf(-inv2tau2 * d0v * d0v);
                float Rv = __expf(aD * (2.0f * d0v - DLT));
                #pragma unroll
                for (int g = 0; g < GG; ++g) { sKv[nl][kk][g] = Kv2; Kv2 *= Rv; Rv *= Cc; }
            }
        }
        __syncthreads();
        #pragma unroll 8
        for (int n2 = 0; n2 < NC; ++n2) {
            float2 aa = sAA[n2][warp];
            float kvh = sKv[n2][warp][hh];
            float ku0 = sKu[n2][warp][w0];
            float ku1 = sKu[n2][warp][w0 + 1];
            float tA = aa.x * kvh, tS = aa.y * kvh;
            acc00 = fmaf(tA, ku0, acc00);
            acc01 = fmaf(tA, ku1, acc01);
            acc10 = fmaf(tS, ku0, acc10);
            acc11 = fmaf(tS, ku1, acc11);
        }
        __syncthreads();
    }
    size_t base = ((size_t)((b * KK + warp) * TT + t)) * 128;
    g_splat[base + px0]          = acc00;
    g_splat[base + px0 + 1]      = acc01;
    g_splat[base + 64 + px0]     = acc10;
    g_splat[base + 64 + px0 + 1] = acc11;
}

// ---------------- kernel 2: CNN — conv1 FFMA2, conv2 via mma.sync bf16 hi/lo ----
// 128 threads = 4 warps, 2 tiles per block. GEMM M=128 (pixels), N=32 (oc),
// K=288 (9 shifts x 32 ic). A fragments come straight off padded H1 planes
// via ldmatrix; B fragments precomputed in register order.
// smem float-index layout:
#define SM_RED   0       // 8
#define SM_B1    8       // 32
#define SM_B2    40      // 32
#define SM_FC    72      // 32
#define SM_FCB   104     // 1
#define SM_W1T   112     // 576
#define SM_IN    688     // [2 tiles][2 ch][100] fp32
#define SM_H1H   1088    // [2 tiles][4 icg][100 px][8 ch] bf16 = 3200 f32
#define SM_H1L   4288    // 3200 f32
#define SM_BF    7488    // 9216 u32 (B fragments hi+lo)
#define SMEM_FLOATS 16704
#define CNN_SMEM_BYTES (SMEM_FLOATS * 4)

__global__ __launch_bounds__(128) void cnn_kernel(
    const float* __restrict__ b1g, const float* __restrict__ b2g,
    const float* __restrict__ fcw, const float* __restrict__ fcb,
    float* __restrict__ out) {
    extern __shared__ float sm[];
    int tid = threadIdx.x;
    int tile0 = blockIdx.x * 2;
    int warp = tid >> 5, lane = tid & 31;
    int tj = tid >> 6;               // tile for conv1 pixel role
    int p = tid & 63;
    int x = p & 7, y = p >> 3;

    // ---- stage weights / inputs / zero padded planes ----
    for (int i = tid; i < 400; i += 128) sm[SM_IN + i] = 0.0f;
    for (int i = tid; i < 6400; i += 128) sm[SM_H1H + i] = 0.0f;   // H1H + H1L contiguous
    {
        float4* dst1 = (float4*)(sm + SM_W1T);
        const float4* src1 = (const float4*)g_w1T;
        for (int i = tid; i < 144; i += 128) dst1[i] = src1[i];
        float4* dbf = (float4*)(sm + SM_BF);
        const float4* sbf = (const float4*)g_bfrag;
        for (int i = tid; i < 2304; i += 128) dbf[i] = sbf[i];
    }
    if (tid < 32) {
        sm[SM_B1 + tid] = b1g[tid];
        sm[SM_B2 + tid] = b2g[tid];
        sm[SM_FC + tid] = fcw[tid];
    }
    if (tid == 0) sm[SM_FCB] = fcb[0];
    __syncthreads();

    for (int i = tid; i < 256; i += 128) {
        int tt = i >> 7;
        int e = i & 127;
        int ch = e >> 6;
        int pp = e & 63;
        int py = pp >> 3, px = pp & 7;
        sm[SM_IN + (tt * 2 + ch) * 100 + (py + 1) * 10 + (px + 1)] =
            g_splat[(size_t)(tile0 + tt) * 128 + e];
    }
    __syncthreads();

    // ---- conv1 (2->32) via FFMA2; GELU; hi/lo bf16 split into H1 planes ----
    {
        u64 acc[16];
        #pragma unroll
        for (int q = 0; q < 16; ++q) acc[q] = ((const u64*)(sm + SM_B1))[q];
        #pragma unroll
        for (int c = 0; c < 2; ++c)
            #pragma unroll
            for (int r = 0; r < 3; ++r)
                #pragma unroll
                for (int q3 = 0; q3 < 3; ++q3) {
                    int j = c * 9 + r * 3 + q3;
                    u64 pa = pack2(sm[SM_IN + (tj * 2 + c) * 100 + (y + r) * 10 + (x + q3)]);
                    const ulonglong2* wv = (const ulonglong2*)(sm + SM_W1T + j * 32);
                    #pragma unroll
                    for (int q = 0; q < 8; ++q) {
                        ulonglong2 w = wv[q];
                        ffma2(acc[2 * q], pa, w.x);
                        ffma2(acc[2 * q + 1], pa, w.y);
                    }
                }
        int ppx = (y + 1) * 10 + (x + 1);
        uint4* h1hw = (uint4*)(sm + SM_H1H);
        uint4* h1lw = (uint4*)(sm + SM_H1L);
        #pragma unroll
        for (int icg = 0; icg < 4; ++icg) {
            uint32_t ph[4], pl[4];
            #pragma unroll
            for (int qq = 0; qq < 4; ++qq) {
                float lo, hi;
                unpack2(lo, hi, acc[icg * 4 + qq]);
                float g0 = gelu_fast(lo);
                float g1 = gelu_fast(hi);
                uint32_t pr; CVTPACK(pr, g0, g1);
                float b0 = __uint_as_float(pr << 16);
                float b1v = __uint_as_float(pr & 0xFFFF0000u);
                uint32_t pr2; CVTPACK(pr2, g0 - b0, g1 - b1v);
                ph[qq] = pr; pl[qq] = pr2;
            }
            int hidx = (tj * 4 + icg) * 100 + ppx;
            h1hw[hidx] = make_uint4(ph[0], ph[1], ph[2], ph[3]);
            h1lw[hidx] = make_uint4(pl[0], pl[1], pl[2], pl[3]);
        }
    }
    __syncthreads();

    // ---- conv2 GEMM via mma.sync m16n8k16, 3 passes (hh, hl, lh) fused ----
    // warp -> rows: tile wtj = warp>>1, half = warp&1; rows = half*32 + mt*16 + rl
    int wtj = warp >> 1, whalf = warp & 1;
    int mat = lane >> 3;
    int rl = ((mat & 1) << 3) | (lane & 7);  // row within m16
    int kseg = mat >> 1;                     // 0/1 -> icg offset within ksg
    uint32_t h1h_addr = smem_u32(sm + SM_H1H);
    uint32_t h1l_addr = smem_u32(sm + SM_H1L);
    // per-mt pixel coords for this thread's ldmatrix row
    int py0 = (whalf * 32 + rl) >> 3,  px0_ = (whalf * 32 + rl) & 7;        // mt=0
    int py1 = (whalf * 32 + 16 + rl) >> 3, px1_ = (whalf * 32 + 16 + rl) & 7; // mt=1

    float cacc[2][4][4];
    #pragma unroll
    for (int mt = 0; mt < 2; ++mt)
        #pragma unroll
        for (int n8 = 0; n8 < 4; ++n8)
            #pragma unroll
            for (int e = 0; e < 4; ++e) cacc[mt][n8][e] = 0.0f;

    const uint2* bfr = (const uint2*)(sm + SM_BF);

    #pragma unroll 1
    for (int j = 0; j < 9; ++j) {
        int dy2 = j / 3, dx2 = j - dy2 * 3;
        int pix0 = (py0 + dy2) * 10 + (px0_ + dx2);
        int pix1 = (py1 + dy2) * 10 + (px1_ + dx2);
        uint32_t ah[2][2][4], al[2][2][4];
        #pragma unroll
        for (int ksg = 0; ksg < 2; ++ksg) {
            int plane = (wtj * 4 + ksg * 2 + kseg) * 100;
            uint32_t a0h = h1h_addr + (plane + pix0) * 16;
            uint32_t a1h = h1h_addr + (plane + pix1) * 16;
            uint32_t a0l = h1l_addr + (plane + pix0) * 16;
            uint32_t a1l = h1l_addr + (plane + pix1) * 16;
            LDMATRIX_X4(ah[0][ksg][0], ah[0][ksg][1], ah[0][ksg][2], ah[0][ksg][3], a0h);
            LDMATRIX_X4(ah[1][ksg][0], ah[1][ksg][1], ah[1][ksg][2], ah[1][ksg][3], a1h);
            LDMATRIX_X4(al[0][ksg][0], al[0][ksg][1], al[0][ksg][2], al[0][ksg][3], a0l);
            LDMATRIX_X4(al[1][ksg][0], al[1][ksg][1], al[1][ksg][2], al[1][ksg][3], a1l);
        }
        #pragma unroll
        for (int ksg = 0; ksg < 2; ++ksg) {
            int ks = 2 * j + ksg;
            #pragma unroll
            for (int n8 = 0; n8 < 4; ++n8) {
                uint2 bh = bfr[((0 * 18 + ks) * 4 + n8) * 32 + lane];
                uint2 bl = bfr[((1 * 18 + ks) * 4 + n8) * 32 + lane];
                #pragma unroll
                for (int mt = 0; mt < 2; ++mt) {
                    MMA16816(cacc[mt][n8], ah[mt][ksg], bh);
                    MMA16816(cacc[mt][n8], ah[mt][ksg], bl);
                    MMA16816(cacc[mt][n8], al[mt][ksg], bh);
                }
            }
        }
    }

    // ---- epilogue: bias + GELU + fc dot (per element), tile mean ----
    // thread's C elements: rows (lane/4)+{0,8} per mt; cols oc = n8*8+(lane%4)*2+{0,1}
    float s = 0.0f;
    #pragma unroll
    for (int n8 = 0; n8 < 4; ++n8) {
        int oc0 = n8 * 8 + (lane & 3) * 2;
        float bb0 = sm[SM_B2 + oc0], bb1 = sm[SM_B2 + oc0 + 1];
        float ff0 = sm[SM_FC + oc0], ff1 = sm[SM_FC + oc0 + 1];
        #pragma unroll
        for (int mt = 0; mt < 2; ++mt) {
            s = fmaf(gelu_fast(cacc[mt][n8][0] + bb0), ff0, s);
            s = fmaf(gelu_fast(cacc[mt][n8][1] + bb1), ff1, s);
            s = fmaf(gelu_fast(cacc[mt][n8][2] + bb0), ff0, s);
            s = fmaf(gelu_fast(cacc[mt][n8][3] + bb1), ff1, s);
        }
    }
    #pragma unroll
    for (int off = 16; off > 0; off >>= 1)
        s += __shfl_xor_sync(0xffffffffu, s, off);
    if (lane == 0) sm[SM_RED + warp] = s;
    __syncthreads();
    if (tid < 2) {
        float v = sm[SM_RED + tid * 2] + sm[SM_RED + tid * 2 + 1];
        v = v * (1.0f / 64.0f) + sm[SM_FCB];
        int tile = tile0 + tid;
        int b = tile / (KK * TT);
        int rem = tile - b * (KK * TT);
        int k = rem / TT;
        int t = rem - k * TT;
        out[(b * TT + t) * KK + k] = v;
    }
}

// ---------------- launch ----------------
extern "C" void kernel_launch(void* const* d_in, const int* in_sizes, int n_in,
                              void* d_out, int out_size) {
    const float* mu        = (const float*)d_in[0];
    const float* sigma0    = (const float*)d_in[1];
    const float* sigma_vel = (const float*)d_in[2];
    const float* amplitude = (const float*)d_in[3];
    const float* sh_base   = (const float*)d_in[4];
    const float* sh_vel    = (const float*)d_in[5];
    const float* p0        = (const float*)d_in[6];
    const float* p_vel     = (const float*)d_in[7];
    const float* tau_raw   = (const float*)d_in[8];
    const float* gam_raw   = (const float*)d_in[9];
    const float* limb_ra   = (const float*)d_in[10];
    const float* limb_la   = (const float*)d_in[11];
    const float* limb_ll   = (const float*)d_in[12];
    const float* chest     = (const float*)d_in[13];
    const float* conv1_w   = (const float*)d_in[14];
    const float* conv1_b   = (const float*)d_in[15];
    const float* conv2_w   = (const float*)d_in[16];
    const float* conv2_b   = (const float*)d_in[17];
    const float* fc_w      = (const float*)d_in[18];
    const float* fc_b      = (const float*)d_in[19];
    float* out = (float*)d_out;

    prep_kernel<<<1, 256>>>(limb_ra, limb_la, limb_ll, chest, conv1_w, conv2_w);
    splat_kernel<<<dim3(TT, BB), 384>>>(mu, sigma0, sigma_vel, amplitude,
                                        sh_base, sh_vel, p0, p_vel, tau_raw, gam_raw);
    cudaFuncSetAttribute(cnn_kernel, cudaFuncAttributeMaxDynamicSharedMemorySize,
                         CNN_SMEM_BYTES);
    cnn_kernel<<<(BB * KK * TT) / 2, 128, CNN_SMEM_BYTES>>>(conv1_b, conv2_b, fc_w, fc_b, out);
}

// round 8
// speedup vs baseline: 2.0503x; 1.1193x over previous
#include <cuda_runtime.h>
#include <cuda_bf16.h>
#include <math.h>
#include <stdint.h>

// Problem dims (fixed by the dataset)
#define BB 4
#define NN 96
#define TT 512
#define KK 12
#define GG 8

typedef unsigned long long u64;

// ---------------- device scratch (no cudaMalloc allowed) ----------------
__device__ float g_lead[KK * 18];
__device__ float g_splat[(size_t)BB * KK * TT * 128];     // (B,K,T,2,8,8)
__device__ float g_w1T[576];                              // conv1 weights [c*9+j][oc]
// conv2 B-matrix fragments in mma.m16n8k16 register order, hi/lo split:
// index = (((s*18 + ks)*4 + n8)*32 + lane)*2 + r   (uint32, bf16x2 each)
__device__ __align__(16) uint32_t g_bfrag[9216];

// ---------------- small helpers ----------------
__device__ __forceinline__ u64 pack2(float x) {
    u64 r; asm("mov.b64 %0, {%1, %1};" : "=l"(r) : "f"(x)); return r;
}
__device__ __forceinline__ void ffma2(u64& d, u64 a, u64 b) {
    asm("fma.rn.f32x2 %0, %1, %2, %0;" : "+l"(d) : "l"(a), "l"(b));
}
__device__ __forceinline__ void unpack2(float& lo, float& hi, u64 v) {
    asm("mov.b64 {%0, %1}, %2;" : "=f"(lo), "=f"(hi) : "l"(v));
}
__device__ __forceinline__ float softplusf(float x) {
    return (x > 20.0f) ? x : log1pf(expf(x));
}
__device__ __forceinline__ float softplus_fast(float x) {
    return (x > 20.0f) ? x : __logf(1.0f + __expf(x));
}
__device__ __forceinline__ float tanh_fast(float x) {
    float xc = fminf(fmaxf(x, -15.0f), 15.0f);
    float t = __expf(2.0f * xc);
    return (t - 1.0f) * __fdividef(1.0f, t + 1.0f);
}
// Pade [5/4] tanh, valid |x|<=1 (args are dots of unit vectors with |p|<1)
__device__ __forceinline__ float tanh_pade(float x) {
    float x2 = x * x;
    float p = fmaf(fmaf(x2, 1.0f, 105.0f), x2, 945.0f);
    float q = fmaf(fmaf(15.0f, x2, 420.0f), x2, 945.0f);
    return __fdividef(x * p, q);
}
__device__ __forceinline__ float acos_fast01(float c) {
    float p = sqrtf(fmaxf(1.0f - c, 0.0f));
    float poly = fmaf(c, fmaf(c, fmaf(c, -0.0187293f, 0.0742610f), -0.2121144f), 1.5707288f);
    return p * poly;
}
__device__ __forceinline__ float gelu_fast(float x) {
    float ax = fabsf(x);
    float z = ax * 0.70710678118f;
    float t = __fdividef(1.0f, fmaf(0.3275911f, z, 1.0f));
    float poly = t * fmaf(t, fmaf(t, fmaf(t, fmaf(t, 1.061405429f, -1.453152027f),
                                          1.421413741f), -0.284496736f), 0.254829592f);
    float e = __expf(-z * z);
    float erfv = fmaf(-poly, e, 1.0f);
    erfv = copysignf(erfv, x);
    return 0.5f * x * (1.0f + erfv);
}
__device__ __forceinline__ uint32_t smem_u32(const void* p) {
    uint32_t a;
    asm("{ .reg .u64 t; cvta.to.shared.u64 t, %1; cvt.u32.u64 %0, t; }" : "=r"(a) : "l"(p));
    return a;
}
// pack two f32 -> bf16x2 (lo = a, hi = b)
#define CVTPACK(r, a, b) \
    asm("cvt.rn.bf16x2.f32 %0, %2, %1;" : "=r"(r) : "f"(a), "f"(b))
// ldmatrix x4 (A fragments)
#define LDMATRIX_X4(r0, r1, r2, r3, addr) \
    asm volatile("ldmatrix.sync.aligned.m8n8.x4.shared.b16 {%0,%1,%2,%3}, [%4];" \
                 : "=r"(r0), "=r"(r1), "=r"(r2), "=r"(r3) : "r"(addr))
// bf16 mma m16n8k16, C += A*B
#define MMA16816(c, a, b) \
    asm volatile("mma.sync.aligned.m16n8k16.row.col.f32.bf16.bf16.f32 " \
                 "{%0,%1,%2,%3},{%4,%5,%6,%7},{%8,%9},{%0,%1,%2,%3};" \
                 : "+f"((c)[0]), "+f"((c)[1]), "+f"((c)[2]), "+f"((c)[3]) \
                 : "r"((a)[0]), "r"((a)[1]), "r"((a)[2]), "r"((a)[3]), \
                   "r"((b).x), "r"((b).y))

// ---------------- kernel 0: leads + conv1 transpose + conv2 B-fragments ----
__global__ void prep_kernel(const float* __restrict__ ra, const float* __restrict__ la,
                            const float* __restrict__ ll, const float* __restrict__ chest,
                            const float* __restrict__ w1, const float* __restrict__ w2) {
    int tid = threadIdx.x;
    // conv2 B fragments: for each (s, ks, n8, lane, r) pack B[k][oc], B[k+1][oc]
    for (int i = tid; i < 9216; i += 256) {
        int r = i & 1;
        int lane = (i >> 1) & 31;
        int n8 = (i >> 6) & 3;
        int rest = i >> 8;               // 0..35
        int ks = rest % 18;
        int s = rest / 18;               // 0=hi, 1=lo
        int oc = n8 * 8 + (lane >> 2);
        int k0 = ks * 16 + (lane & 3) * 2 + r * 8;
        uint32_t pk = 0;
        #pragma unroll
        for (int e = 0; e < 2; ++e) {
            int k = k0 + e;
            int j = k / 32, ic = k % 32;
            float w = w2[oc * 288 + ic * 9 + j];
            __nv_bfloat16 h = __float2bfloat16(w);
            unsigned short bits;
            if (s == 0) bits = __bfloat16_as_ushort(h);
            else {
                float hf = __bfloat162float(h);
                bits = __bfloat16_as_ushort(__float2bfloat16(w - hf));
            }
            pk |= (uint32_t)bits << (16 * e);
        }
        g_bfrag[i] = pk;
    }
    for (int idx = tid; idx < 576; idx += 256) {
        int oc = idx / 18;
        int r = idx - oc * 18;
        g_w1T[r * 32 + oc] = w1[idx];
    }
    if (tid >= KK) return;
    int k = tid;
    float vx, vy, vz;
    float rax = ra[0], ray = ra[1], raz = ra[2];
    float lax = la[0], lay = la[1], laz = la[2];
    float llx = ll[0], lly = ll[1], llz = ll[2];
    switch (k) {
        case 0: vx = lax - rax; vy = lay - ray; vz = laz - raz; break;
        case 1: vx = llx - rax; vy = lly - ray; vz = llz - raz; break;
        case 2: vx = llx - lax; vy = lly - lay; vz = llz - laz; break;
        case 3: vx = rax - 0.5f * (lax + llx); vy = ray - 0.5f * (lay + lly); vz = raz - 0.5f * (laz + llz); break;
        case 4: vx = lax - 0.5f * (rax + llx); vy = lay - 0.5f * (ray + lly); vz = laz - 0.5f * (raz + llz); break;
        case 5: vx = llx - 0.5f * (rax + lax); vy = lly - 0.5f * (ray + lay); vz = llz - 0.5f * (raz + laz); break;
        default:
            vx = chest[(k - 6) * 3 + 0]; vy = chest[(k - 6) * 3 + 1]; vz = chest[(k - 6) * 3 + 2];
            break;
    }
    float n = sqrtf(vx * vx + vy * vy + vz * vz);
    float d = fmaxf(n, 1e-6f);
    float Lx = vx / d, Ly = vy / d, Lz = vz / d;
    float e1x = 0.0f, e1y = Lz, e1z = -Ly;
    float n1 = sqrtf(e1y * e1y + e1z * e1z);
    if (n1 < 1e-4f) { e1x = -Lz; e1y = 0.0f; e1z = Lx; n1 = sqrtf(e1x * e1x + e1z * e1z); }
    float d1 = fmaxf(n1, 1e-6f);
    e1x /= d1; e1y /= d1; e1z /= d1;
    float e2x = e1y * Lz - e1z * Ly;
    float e2y = e1z * Lx - e1x * Lz;
    float e2z = e1x * Ly - e1y * Lx;
    float n2 = sqrtf(e2x * e2x + e2y * e2y + e2z * e2z);
    float d2 = fmaxf(n2, 1e-6f);
    e2x /= d2; e2y /= d2; e2z /= d2;
    float* o = g_lead + k * 18;
    o[0] = Lx; o[1] = Ly; o[2] = Lz;
    o[3] = e1x; o[4] = e1y; o[5] = e1z;
    o[6] = e2x; o[7] = e2y; o[8] = e2z;
    o[9]  = 0.282095f;
    o[10] = -0.488603f * Ly;
    o[11] = 0.488603f * Lz;
    o[12] = -0.488603f * Lx;
    o[13] = 1.092548f * Lx * Ly;
    o[14] = -1.092548f * Ly * Lz;
    o[15] = 0.315392f * (3.0f * Lz * Lz - 1.0f);
    o[16] = -1.092548f * Lx * Lz;
    o[17] = 0.546274f * (Lx * Lx - Ly * Ly);
}

// ---------------- kernel 1: splat rasterization ----------------
#define NC 32

__global__ __launch_bounds__(384) void splat_kernel(
    const float* __restrict__ mu, const float* __restrict__ sigma0,
    const float* __restrict__ sigma_vel, const float* __restrict__ amplitude,
    const float* __restrict__ sh_base, const float* __restrict__ sh_vel,
    const float* __restrict__ p0, const float* __restrict__ p_vel,
    const float* __restrict__ tau_raw, const float* __restrict__ gam_raw) {
    __shared__ float  sLead[KK][18];
    __shared__ float2 sAA[NC][KK];
    __shared__ float  sKu[NC][KK][9];
    __shared__ float  sKv[NC][KK][9];

    int t = blockIdx.x, b = blockIdx.y;
    int tid = threadIdx.x;
    if (tid < KK * 18) ((float*)sLead)[tid] = g_lead[tid];

    float tau = softplusf(tau_raw[0]) + 0.06f;
    float inv2tau2 = 0.5f / (tau * tau);
    float gamma = softplusf(gam_raw[0]) + 1e-6f;
    float tval = (float)t * (1.0f / (float)(TT - 1));
    const float DLT = 2.0f / 7.0f;
    float aD = inv2tau2 * DLT;
    float Cc = __expf(-2.0f * aD * DLT);   // exp recurrence constant

    int warp = tid >> 5, lane = tid & 31;
    int px0 = lane * 2;
    int hh = px0 >> 3, w0 = px0 & 7;
    float acc00 = 0.f, acc01 = 0.f, acc10 = 0.f, acc11 = 0.f;

    int nl = tid / KK, kk = tid - nl * KK;
    __syncthreads();

    for (int c = 0; c < NN / NC; ++c) {
        {
            int n = c * NC + nl;
            int bn = b * NN + n;
            float dt = tval - mu[bn];
            float sig = softplus_fast(sigma0[bn] + sigma_vel[bn] * dt) + 1e-3f;
            float z = dt * __fdividef(1.0f, sig);
            float gauss = amplitude[bn] * __expf(-0.5f * z * z);
            float prx = p0[bn * 3 + 0] + p_vel[bn * 3 + 0] * dt;
            float pry = p0[bn * 3 + 1] + p_vel[bn * 3 + 1] * dt;
            float prz = p0[bn * 3 + 2] + p_vel[bn * 3 + 2] * dt;
            float nrm = fmaxf(sqrtf(prx * prx + pry * pry + prz * prz), 1e-8f);
            float th = tanh_fast(nrm);
            float sc = th * __fdividef(1.0f, nrm);
            float ppx = prx * sc, ppy = pry * sc, ppz = prz * sc;
            const float* Ld = sLead[kk];
            float u = tanh_pade(ppx * Ld[3] + ppy * Ld[4] + ppz * Ld[5]);
            float v = tanh_pade(ppx * Ld[6] + ppy * Ld[7] + ppz * Ld[8]);
            float pn = fmaxf(th, 1e-8f);
            float cosl = (ppx * Ld[0] + ppy * Ld[1] + ppz * Ld[2]) * __fdividef(1.0f, pn);
            float hem = fmaxf(cosl, 0.0f);
            float ccv = fminf(fmaxf(cosl, -1.0f + 1e-6f), 1.0f - 1e-6f);
            float theta = acos_fast01(ccv);
            float weight = hem * __expf(-gamma * theta * theta);
            float A = gauss * weight;
            float shp = 0.0f;
            #pragma unroll
            for (int m = 0; m < 9; ++m)
                shp += (sh_base[bn * 9 + m] + sh_vel[bn * 9 + m] * dt) * Ld[9 + m];
            sAA[nl][kk] = make_float2(A, A * shp);
            // Gaussian grid via exp recurrence: 2 exp per axis instead of 8
            {
                float d0 = u + 1.0f;
                float Kx = __expf(-inv2tau2 * d0 * d0);
                float Rx = __expf(aD * (2.0f * d0 - DLT));
                #pragma unroll
                for (int g = 0; g < GG; ++g) { sKu[nl][kk][g] = Kx; Kx *= Rx; Rx *= Cc; }
                float d0v = v + 1.0f;
                float Kv2 = __expf(-inv2tau2 * d0v * d0v);
                float Rv = __expf(aD * (2.0f * d0v - DLT));
                #pragma unroll
                for (int g = 0; g < GG; ++g) { sKv[nl][kk][g] = Kv2; Kv2 *= Rv; Rv *= Cc; }
            }
        }
        __syncthreads();
        #pragma unroll 8
        for (int n2 = 0; n2 < NC; ++n2) {
            float2 aa = sAA[n2][warp];
            float kvh = sKv[n2][warp][hh];
            float ku0 = sKu[n2][warp][w0];
            float ku1 = sKu[n2][warp][w0 + 1];
            float tA = aa.x * kvh, tS = aa.y * kvh;
            acc00 = fmaf(tA, ku0, acc00);
            acc01 = fmaf(tA, ku1, acc01);
            acc10 = fmaf(tS, ku0, acc10);
            acc11 = fmaf(tS, ku1, acc11);
        }
        __syncthreads();
    }
    size_t base = ((size_t)((b * KK + warp) * TT + t)) * 128;
    g_splat[base + px0]          = acc00;
    g_splat[base + px0 + 1]      = acc01;
    g_splat[base + 64 + px0]     = acc10;
    g_splat[base + 64 + px0 + 1] = acc11;
}

// ---------------- kernel 2: PERSISTENT CNN — stage weights once, loop tiles ----
// 256 threads = 8 warps, 4 tiles per iteration, grid 296 (2 blocks/SM).
// smem float-index layout:
#define SM_RED   0       // 16
#define SM_B1    16      // 32
#define SM_B2    48      // 32
#define SM_FC    80      // 32
#define SM_FCB   112     // 1 (+3 pad)
#define SM_W1T   116     // 576
#define SM_IN    692     // [4 tiles][2 ch][100] fp32
#define SM_H1H   1492    // [4 tiles][4 icg][100 px][8 ch] bf16 = 6400 f32
#define SM_H1L   7892    // 6400 f32
#define SM_BF    14292   // 9216 u32 (B fragments hi+lo)
#define SMEM_FLOATS 23508
#define CNN_SMEM_BYTES (SMEM_FLOATS * 4)
#define QUADS (BB * KK * TT / 4)   // 6144
#define CNN_GRID 296

__global__ __launch_bounds__(256, 2) void cnn_kernel(
    const float* __restrict__ b1g, const float* __restrict__ b2g,
    const float* __restrict__ fcw, const float* __restrict__ fcb,
    float* __restrict__ out) {
    extern __shared__ float sm[];
    int tid = threadIdx.x;
    int warp = tid >> 5, lane = tid & 31;
    int tj = tid >> 6;               // tile 0..3 for conv1 pixel role
    int p = tid & 63;
    int x = p & 7, y = p >> 3;

    // ---- one-time staging: weights + zeroed padded planes ----
    for (int i = tid; i < 13600; i += 256) sm[SM_IN + i] = 0.0f;  // IN + H1H + H1L
    {
        float4* dst1 = (float4*)(sm + SM_W1T);
        const float4* src1 = (const float4*)g_w1T;
        for (int i = tid; i < 144; i += 256) dst1[i] = src1[i];
        float4* dbf = (float4*)(sm + SM_BF);
        const float4* sbf = (const float4*)g_bfrag;
        for (int i = tid; i < 2304; i += 256) dbf[i] = sbf[i];
    }
    if (tid < 32) {
        sm[SM_B1 + tid] = b1g[tid];
        sm[SM_B2 + tid] = b2g[tid];
        sm[SM_FC + tid] = fcw[tid];
    }
    if (tid == 0) sm[SM_FCB] = fcb[0];

    // conv2 warp geometry (fixed per thread)
    int wtj = warp >> 1, whalf = warp & 1;     // tile 0..3, half 0/1
    int mat = lane >> 3;
    int rl = ((mat & 1) << 3) | (lane & 7);
    int kseg = mat >> 1;
    uint32_t h1h_addr = smem_u32(sm + SM_H1H);
    uint32_t h1l_addr = smem_u32(sm + SM_H1L);
    int py0 = (whalf * 32 + rl) >> 3,       px0_ = (whalf * 32 + rl) & 7;
    int py1 = (whalf * 32 + 16 + rl) >> 3,  px1_ = (whalf * 32 + 16 + rl) & 7;
    const uint2* bfr = (const uint2*)(sm + SM_BF);
    __syncthreads();

    for (int quad = blockIdx.x; quad < QUADS; quad += CNN_GRID) {
        int tile0 = quad * 4;

        // ---- stage splat inputs into padded IN planes ----
        for (int i = tid; i < 512; i += 256) {
            int tt = i >> 7;
            int e = i & 127;
            int ch = e >> 6;
            int pp = e & 63;
            int py = pp >> 3, px = pp & 7;
            sm[SM_IN + (tt * 2 + ch) * 100 + (py + 1) * 10 + (px + 1)] =
                g_splat[(size_t)(tile0 + tt) * 128 + e];
        }
        __syncthreads();

        // ---- conv1 (2->32) via FFMA2; GELU; hi/lo bf16 split into H1 planes ----
        {
            u64 acc[16];
            #pragma unroll
            for (int q = 0; q < 16; ++q) acc[q] = ((const u64*)(sm + SM_B1))[q];
            #pragma unroll
            for (int c = 0; c < 2; ++c)
                #pragma unroll
                for (int r = 0; r < 3; ++r)
                    #pragma unroll
                    for (int q3 = 0; q3 < 3; ++q3) {
                        int j = c * 9 + r * 3 + q3;
                        u64 pa = pack2(sm[SM_IN + (tj * 2 + c) * 100 + (y + r) * 10 + (x + q3)]);
                        const ulonglong2* wv = (const ulonglong2*)(sm + SM_W1T + j * 32);
                        #pragma unroll
                        for (int q = 0; q < 8; ++q) {
                            ulonglong2 w = wv[q];
                            ffma2(acc[2 * q], pa, w.x);
                            ffma2(acc[2 * q + 1], pa, w.y);
                        }
                    }
            int ppx = (y + 1) * 10 + (x + 1);
            uint4* h1hw = (uint4*)(sm + SM_H1H);
            uint4* h1lw = (uint4*)(sm + SM_H1L);
            #pragma unroll
            for (int icg = 0; icg < 4; ++icg) {
                uint32_t ph[4], pl[4];
                #pragma unroll
                for (int qq = 0; qq < 4; ++qq) {
                    float lo, hi;
                    unpack2(lo, hi, acc[icg * 4 + qq]);
                    float g0 = gelu_fast(lo);
                    float g1 = gelu_fast(hi);
                    uint32_t pr; CVTPACK(pr, g0, g1);
                    float b0 = __uint_as_float(pr << 16);
                    float b1v = __uint_as_float(pr & 0xFFFF0000u);
                    uint32_t pr2; CVTPACK(pr2, g0 - b0, g1 - b1v);
                    ph[qq] = pr; pl[qq] = pr2;
                }
                int hidx = (tj * 4 + icg) * 100 + ppx;
                h1hw[hidx] = make_uint4(ph[0], ph[1], ph[2], ph[3]);
                h1lw[hidx] = make_uint4(pl[0], pl[1], pl[2], pl[3]);
            }
        }
        __syncthreads();

        // ---- conv2 GEMM via mma.sync m16n8k16, 3 passes (hh, hl, lh) fused ----
        float cacc[2][4][4];
        #pragma unroll
        for (int mt = 0; mt < 2; ++mt)
            #pragma unroll
            for (int n8 = 0; n8 < 4; ++n8)
                #pragma unroll
                for (int e = 0; e < 4; ++e) cacc[mt][n8][e] = 0.0f;

        #pragma unroll 1
        for (int j = 0; j < 9; ++j) {
            int dy2 = j / 3, dx2 = j - dy2 * 3;
            int pix0 = (py0 + dy2) * 10 + (px0_ + dx2);
            int pix1 = (py1 + dy2) * 10 + (px1_ + dx2);
            uint32_t ah[2][2][4], al[2][2][4];
            #pragma unroll
            for (int ksg = 0; ksg < 2; ++ksg) {
                int plane = (wtj * 4 + ksg * 2 + kseg) * 100;
                uint32_t a0h = h1h_addr + (plane + pix0) * 16;
                uint32_t a1h = h1h_addr + (plane + pix1) * 16;
                uint32_t a0l = h1l_addr + (plane + pix0) * 16;
                uint32_t a1l = h1l_addr + (plane + pix1) * 16;
                LDMATRIX_X4(ah[0][ksg][0], ah[0][ksg][1], ah[0][ksg][2], ah[0][ksg][3], a0h);
                LDMATRIX_X4(ah[1][ksg][0], ah[1][ksg][1], ah[1][ksg][2], ah[1][ksg][3], a1h);
                LDMATRIX_X4(al[0][ksg][0], al[0][ksg][1], al[0][ksg][2], al[0][ksg][3], a0l);
                LDMATRIX_X4(al[1][ksg][0], al[1][ksg][1], al[1][ksg][2], al[1][ksg][3], a1l);
            }
            #pragma unroll
            for (int ksg = 0; ksg < 2; ++ksg) {
                int ks = 2 * j + ksg;
                #pragma unroll
                for (int n8 = 0; n8 < 4; ++n8) {
                    uint2 bh = bfr[((0 * 18 + ks) * 4 + n8) * 32 + lane];
                    uint2 bl = bfr[((1 * 18 + ks) * 4 + n8) * 32 + lane];
                    #pragma unroll
                    for (int mt = 0; mt < 2; ++mt) {
                        MMA16816(cacc[mt][n8], ah[mt][ksg], bh);
                        MMA16816(cacc[mt][n8], ah[mt][ksg], bl);
                        MMA16816(cacc[mt][n8], al[mt][ksg], bh);
                    }
                }
            }
        }

        // ---- epilogue: bias + GELU + fc dot, warp reduce ----
        float s = 0.0f;
        #pragma unroll
        for (int n8 = 0; n8 < 4; ++n8) {
            int oc0 = n8 * 8 + (lane & 3) * 2;
            float bb0 = sm[SM_B2 + oc0], bb1 = sm[SM_B2 + oc0 + 1];
            float ff0 = sm[SM_FC + oc0], ff1 = sm[SM_FC + oc0 + 1];
            #pragma unroll
            for (int mt = 0; mt < 2; ++mt) {
                s = fmaf(gelu_fast(cacc[mt][n8][0] + bb0), ff0, s);
                s = fmaf(gelu_fast(cacc[mt][n8][1] + bb1), ff1, s);
                s = fmaf(gelu_fast(cacc[mt][n8][2] + bb0), ff0, s);
                s = fmaf(gelu_fast(cacc[mt][n8][3] + bb1), ff1, s);
            }
        }
        #pragma unroll
        for (int off = 16; off > 0; off >>= 1)
            s += __shfl_xor_sync(0xffffffffu, s, off);
        if (lane == 0) sm[SM_RED + warp] = s;
        __syncthreads();
        if (tid < 4) {
            float v = sm[SM_RED + tid * 2] + sm[SM_RED + tid * 2 + 1];
            v = v * (1.0f / 64.0f) + sm[SM_FCB];
            int tile = tile0 + tid;
            int b = tile / (KK * TT);
            int rem = tile - b * (KK * TT);
            int k = rem / TT;
            int t = rem - k * TT;
            out[(b * TT + t) * KK + k] = v;
        }
        // next-iter staging is fenced by the loop's first __syncthreads()
    }
}

// ---------------- launch ----------------
extern "C" void kernel_launch(void* const* d_in, const int* in_sizes, int n_in,
                              void* d_out, int out_size) {
    const float* mu        = (const float*)d_in[0];
    const float* sigma0    = (const float*)d_in[1];
    const float* sigma_vel = (const float*)d_in[2];
    const float* amplitude = (const float*)d_in[3];
    const float* sh_base   = (const float*)d_in[4];
    const float* sh_vel    = (const float*)d_in[5];
    const float* p0        = (const float*)d_in[6];
    const float* p_vel     = (const float*)d_in[7];
    const float* tau_raw   = (const float*)d_in[8];
    const float* gam_raw   = (const float*)d_in[9];
    const float* limb_ra   = (const float*)d_in[10];
    const float* limb_la   = (const float*)d_in[11];
    const float* limb_ll   = (const float*)d_in[12];
    const float* chest     = (const float*)d_in[13];
    const float* conv1_w   = (const float*)d_in[14];
    const float* conv1_b   = (const float*)d_in[15];
    const float* conv2_w   = (const float*)d_in[16];
    const float* conv2_b   = (const float*)d_in[17];
    const float* fc_w      = (const float*)d_in[18];
    const float* fc_b      = (const float*)d_in[19];
    float* out = (float*)d_out;

    prep_kernel<<<1, 256>>>(limb_ra, limb_la, limb_ll, chest, conv1_w, conv2_w);
    splat_kernel<<<dim3(TT, BB), 384>>>(mu, sigma0, sigma_vel, amplitude,
                                        sh_base, sh_vel, p0, p_vel, tau_raw, gam_raw);
    cudaFuncSetAttribute(cnn_kernel, cudaFuncAttributeMaxDynamicSharedMemorySize,
                         CNN_SMEM_BYTES);
    cnn_kernel<<<CNN_GRID, 256, CNN_SMEM_BYTES>>>(conv1_b, conv2_b, fc_w, fc_b, out);
}

// round 9
// speedup vs baseline: 2.1201x; 1.0340x over previous
#include <cuda_runtime.h>
#include <cuda_bf16.h>
#include <math.h>
#include <stdint.h>

// Problem dims (fixed by the dataset)
#define BB 4
#define NN 96
#define TT 512
#define KK 12
#define GG 8

typedef unsigned long long u64;

// ---------------- device scratch (no cudaMalloc allowed) ----------------
__device__ float g_lead[KK * 18];
__device__ float g_splat[(size_t)BB * KK * TT * 128];     // (B,K,T,2,8,8)
__device__ float g_w1T[576];                              // conv1 weights [c*9+j][oc]
// conv2 B fragments, uint4-interleaved: frag f = (ks*4+n8)*32+lane holds
// uint32s [4f..4f+3] = {bh_r0, bh_r1, bl_r0, bl_r1}
__device__ __align__(16) uint32_t g_bfrag[9216];

// ---------------- small helpers ----------------
__device__ __forceinline__ u64 pack2(float x) {
    u64 r; asm("mov.b64 %0, {%1, %1};" : "=l"(r) : "f"(x)); return r;
}
__device__ __forceinline__ void ffma2(u64& d, u64 a, u64 b) {
    asm("fma.rn.f32x2 %0, %1, %2, %0;" : "+l"(d) : "l"(a), "l"(b));
}
__device__ __forceinline__ void unpack2(float& lo, float& hi, u64 v) {
    asm("mov.b64 {%0, %1}, %2;" : "=f"(lo), "=f"(hi) : "l"(v));
}
__device__ __forceinline__ float softplusf(float x) {
    return (x > 20.0f) ? x : log1pf(expf(x));
}
__device__ __forceinline__ float softplus_fast(float x) {
    return (x > 20.0f) ? x : __logf(1.0f + __expf(x));
}
__device__ __forceinline__ float tanh_fast(float x) {
    float xc = fminf(fmaxf(x, -15.0f), 15.0f);
    float t = __expf(2.0f * xc);
    return (t - 1.0f) * __fdividef(1.0f, t + 1.0f);
}
// Pade [5/4] tanh, valid |x|<=1 (args are dots of unit vectors with |p|<1)
__device__ __forceinline__ float tanh_pade(float x) {
    float x2 = x * x;
    float p = fmaf(fmaf(x2, 1.0f, 105.0f), x2, 945.0f);
    float q = fmaf(fmaf(15.0f, x2, 420.0f), x2, 945.0f);
    return __fdividef(x * p, q);
}
__device__ __forceinline__ float acos_fast01(float c) {
    float p = sqrtf(fmaxf(1.0f - c, 0.0f));
    float poly = fmaf(c, fmaf(c, fmaf(c, -0.0187293f, 0.0742610f), -0.2121144f), 1.5707288f);
    return p * poly;
}
__device__ __forceinline__ float gelu_fast(float x) {
    float ax = fabsf(x);
    float z = ax * 0.70710678118f;
    float t = __fdividef(1.0f, fmaf(0.3275911f, z, 1.0f));
    float poly = t * fmaf(t, fmaf(t, fmaf(t, fmaf(t, 1.061405429f, -1.453152027f),
                                          1.421413741f), -0.284496736f), 0.254829592f);
    float e = __expf(-z * z);
    float erfv = fmaf(-poly, e, 1.0f);
    erfv = copysignf(erfv, x);
    return 0.5f * x * (1.0f + erfv);
}
__device__ __forceinline__ uint32_t smem_u32(const void* p) {
    uint32_t a;
    asm("{ .reg .u64 t; cvta.to.shared.u64 t, %1; cvt.u32.u64 %0, t; }" : "=r"(a) : "l"(p));
    return a;
}
// pack two f32 -> bf16x2 (lo = a, hi = b)
#define CVTPACK(r, a, b) \
    asm("cvt.rn.bf16x2.f32 %0, %2, %1;" : "=r"(r) : "f"(a), "f"(b))
// ldmatrix x4 (A fragments)
#define LDMATRIX_X4(r0, r1, r2, r3, addr) \
    asm volatile("ldmatrix.sync.aligned.m8n8.x4.shared.b16 {%0,%1,%2,%3}, [%4];" \
                 : "=r"(r0), "=r"(r1), "=r"(r2), "=r"(r3) : "r"(addr))
// bf16 mma m16n8k16, C += A*B  (B passed as two b32 regs)
#define MMA16816(c, a, b0, b1) \
    asm volatile("mma.sync.aligned.m16n8k16.row.col.f32.bf16.bf16.f32 " \
                 "{%0,%1,%2,%3},{%4,%5,%6,%7},{%8,%9},{%0,%1,%2,%3};" \
                 : "+f"((c)[0]), "+f"((c)[1]), "+f"((c)[2]), "+f"((c)[3]) \
                 : "r"((a)[0]), "r"((a)[1]), "r"((a)[2]), "r"((a)[3]), \
                   "r"(b0), "r"(b1))

// ---------------- kernel 0: leads + conv1 transpose + conv2 B-fragments ----
__global__ void prep_kernel(const float* __restrict__ ra, const float* __restrict__ la,
                            const float* __restrict__ ll, const float* __restrict__ chest,
                            const float* __restrict__ w1, const float* __restrict__ w2) {
    int tid = threadIdx.x;
    // conv2 B fragments, uint4-interleaved layout
    for (int i = tid; i < 9216; i += 256) {
        int c4 = i & 3;                  // 0,1 = hi r0/r1; 2,3 = lo r0/r1
        int f = i >> 2;
        int lane = f & 31;
        int n8 = (f >> 5) & 3;
        int ks = f >> 7;                 // 0..17
        int s = c4 >> 1;                 // 0 = hi, 1 = lo
        int r = c4 & 1;
        int oc = n8 * 8 + (lane >> 2);
        int k0 = ks * 16 + (lane & 3) * 2 + r * 8;
        uint32_t pk = 0;
        #pragma unroll
        for (int e = 0; e < 2; ++e) {
            int k = k0 + e;
            int j = k / 32, ic = k % 32;
            float w = w2[oc * 288 + ic * 9 + j];
            __nv_bfloat16 h = __float2bfloat16(w);
            unsigned short bits;
            if (s == 0) bits = __bfloat16_as_ushort(h);
            else {
                float hf = __bfloat162float(h);
                bits = __bfloat16_as_ushort(__float2bfloat16(w - hf));
            }
            pk |= (uint32_t)bits << (16 * e);
        }
        g_bfrag[i] = pk;
    }
    for (int idx = tid; idx < 576; idx += 256) {
        int oc = idx / 18;
        int r = idx - oc * 18;
        g_w1T[r * 32 + oc] = w1[idx];
    }
    if (tid >= KK) return;
    int k = tid;
    float vx, vy, vz;
    float rax = ra[0], ray = ra[1], raz = ra[2];
    float lax = la[0], lay = la[1], laz = la[2];
    float llx = ll[0], lly = ll[1], llz = ll[2];
    switch (k) {
        case 0: vx = lax - rax; vy = lay - ray; vz = laz - raz; break;
        case 1: vx = llx - rax; vy = lly - ray; vz = llz - raz; break;
        case 2: vx = llx - lax; vy = lly - lay; vz = llz - laz; break;
        case 3: vx = rax - 0.5f * (lax + llx); vy = ray - 0.5f * (lay + lly); vz = raz - 0.5f * (laz + llz); break;
        case 4: vx = lax - 0.5f * (rax + llx); vy = lay - 0.5f * (ray + lly); vz = laz - 0.5f * (raz + llz); break;
        case 5: vx = llx - 0.5f * (rax + lax); vy = lly - 0.5f * (ray + lay); vz = llz - 0.5f * (raz + laz); break;
        default:
            vx = chest[(k - 6) * 3 + 0]; vy = chest[(k - 6) * 3 + 1]; vz = chest[(k - 6) * 3 + 2];
            break;
    }
    float n = sqrtf(vx * vx + vy * vy + vz * vz);
    float d = fmaxf(n, 1e-6f);
    float Lx = vx / d, Ly = vy / d, Lz = vz / d;
    float e1x = 0.0f, e1y = Lz, e1z = -Ly;
    float n1 = sqrtf(e1y * e1y + e1z * e1z);
    if (n1 < 1e-4f) { e1x = -Lz; e1y = 0.0f; e1z = Lx; n1 = sqrtf(e1x * e1x + e1z * e1z); }
    float d1 = fmaxf(n1, 1e-6f);
    e1x /= d1; e1y /= d1; e1z /= d1;
    float e2x = e1y * Lz - e1z * Ly;
    float e2y = e1z * Lx - e1x * Lz;
    float e2z = e1x * Ly - e1y * Lx;
    float n2 = sqrtf(e2x * e2x + e2y * e2y + e2z * e2z);
    float d2 = fmaxf(n2, 1e-6f);
    e2x /= d2; e2y /= d2; e2z /= d2;
    float* o = g_lead + k * 18;
    o[0] = Lx; o[1] = Ly; o[2] = Lz;
    o[3] = e1x; o[4] = e1y; o[5] = e1z;
    o[6] = e2x; o[7] = e2y; o[8] = e2z;
    o[9]  = 0.282095f;
    o[10] = -0.488603f * Ly;
    o[11] = 0.488603f * Lz;
    o[12] = -0.488603f * Lx;
    o[13] = 1.092548f * Lx * Ly;
    o[14] = -1.092548f * Ly * Lz;
    o[15] = 0.315392f * (3.0f * Lz * Lz - 1.0f);
    o[16] = -1.092548f * Lx * Lz;
    o[17] = 0.546274f * (Lx * Lx - Ly * Ly);
}

// ---------------- kernel 1: splat rasterization ----------------
#define NC 32

__global__ __launch_bounds__(384) void splat_kernel(
    const float* __restrict__ mu, const float* __restrict__ sigma0,
    const float* __restrict__ sigma_vel, const float* __restrict__ amplitude,
    const float* __restrict__ sh_base, const float* __restrict__ sh_vel,
    const float* __restrict__ p0, const float* __restrict__ p_vel,
    const float* __restrict__ tau_raw, const float* __restrict__ gam_raw) {
    __shared__ float  sLead[KK][18];
    __shared__ float2 sAA[NC][KK];
    __shared__ float  sKu[NC][KK][9];
    __shared__ float  sKv[NC][KK][9];

    int t = blockIdx.x, b = blockIdx.y;
    int tid = threadIdx.x;
    if (tid < KK * 18) ((float*)sLead)[tid] = g_lead[tid];

    float tau = softplusf(tau_raw[0]) + 0.06f;
    float inv2tau2 = 0.5f / (tau * tau);
    float gamma = softplusf(gam_raw[0]) + 1e-6f;
    float tval = (float)t * (1.0f / (float)(TT - 1));
    const float DLT = 2.0f / 7.0f;
    float aD = inv2tau2 * DLT;
    float Cc = __expf(-2.0f * aD * DLT);   // exp recurrence constant

    int warp = tid >> 5, lane = tid & 31;
    int px0 = lane * 2;
    int hh = px0 >> 3, w0 = px0 & 7;
    float acc00 = 0.f, acc01 = 0.f, acc10 = 0.f, acc11 = 0.f;

    int nl = tid / KK, kk = tid - nl * KK;
    __syncthreads();

    for (int c = 0; c < NN / NC; ++c) {
        {
            int n = c * NC + nl;
            int bn = b * NN + n;
            float dt = tval - mu[bn];
            float sig = softplus_fast(sigma0[bn] + sigma_vel[bn] * dt) + 1e-3f;
            float z = dt * __fdividef(1.0f, sig);
            float gauss = amplitude[bn] * __expf(-0.5f * z * z);
            float prx = p0[bn * 3 + 0] + p_vel[bn * 3 + 0] * dt;
            float pry = p0[bn * 3 + 1] + p_vel[bn * 3 + 1] * dt;
            float prz = p0[bn * 3 + 2] + p_vel[bn * 3 + 2] * dt;
            float nrm = fmaxf(sqrtf(prx * prx + pry * pry + prz * prz), 1e-8f);
            float th = tanh_fast(nrm);
            float sc = th * __fdividef(1.0f, nrm);
            float ppx = prx * sc, ppy = pry * sc, ppz = prz * sc;
            const float* Ld = sLead[kk];
            float u = tanh_pade(ppx * Ld[3] + ppy * Ld[4] + ppz * Ld[5]);
            float v = tanh_pade(ppx * Ld[6] + ppy * Ld[7] + ppz * Ld[8]);
            float pn = fmaxf(th, 1e-8f);
            float cosl = (ppx * Ld[0] + ppy * Ld[1] + ppz * Ld[2]) * __fdividef(1.0f, pn);
            float hem = fmaxf(cosl, 0.0f);
            float ccv = fminf(fmaxf(cosl, -1.0f + 1e-6f), 1.0f - 1e-6f);
            float theta = acos_fast01(ccv);
            float weight = hem * __expf(-gamma * theta * theta);
            float A = gauss * weight;
            float shp = 0.0f;
            #pragma unroll
            for (int m = 0; m < 9; ++m)
                shp += (sh_base[bn * 9 + m] + sh_vel[bn * 9 + m] * dt) * Ld[9 + m];
            sAA[nl][kk] = make_float2(A, A * shp);
            // Gaussian grid via exp recurrence: 2 exp per axis instead of 8
            {
                float d0 = u + 1.0f;
                float Kx = __expf(-inv2tau2 * d0 * d0);
                float Rx = __expf(aD * (2.0f * d0 - DLT));
                #pragma unroll
                for (int g = 0; g < GG; ++g) { sKu[nl][kk][g] = Kx; Kx *= Rx; Rx *= Cc; }
                float d0v = v + 1.0f;
                float Kv2 = __expf(-inv2tau2 * d0v * d0v);
                float Rv = __expf(aD * (2.0f * d0v - DLT));
                #pragma unroll
                for (int g = 0; g < GG; ++g) { sKv[nl][kk][g] = Kv2; Kv2 *= Rv; Rv *= Cc; }
            }
        }
        __syncthreads();
        #pragma unroll 8
        for (int n2 = 0; n2 < NC; ++n2) {
            float2 aa = sAA[n2][warp];
            float kvh = sKv[n2][warp][hh];
            float ku0 = sKu[n2][warp][w0];
            float ku1 = sKu[n2][warp][w0 + 1];
            float tA = aa.x * kvh, tS = aa.y * kvh;
            acc00 = fmaf(tA, ku0, acc00);
            acc01 = fmaf(tA, ku1, acc01);
            acc10 = fmaf(tS, ku0, acc10);
            acc11 = fmaf(tS, ku1, acc11);
        }
        __syncthreads();
    }
    size_t base = ((size_t)((b * KK + warp) * TT + t)) * 128;
    g_splat[base + px0]          = acc00;
    g_splat[base + px0 + 1]      = acc01;
    g_splat[base + 64 + px0]     = acc10;
    g_splat[base + 64 + px0 + 1] = acc11;
}

// ---------------- kernel 2: PERSISTENT CNN, pass-major MMA + IN ping-pong ----
// 256 threads = 8 warps, 4 tiles per iteration, grid 296 (2 blocks/SM).
// smem float-index layout:
#define SM_RED   0       // 16
#define SM_B1    16      // 32
#define SM_B2    48      // 32
#define SM_FC    80      // 32
#define SM_FCB   112     // 1 (+3 pad)
#define SM_W1T   116     // 576
#define SM_IN    692     // [2 buf][4 tiles][2 ch][100] fp32 = 1600
#define SM_H1H   2292    // [4 tiles][4 icg][100 px][8 ch] bf16 = 6400 f32
#define SM_H1L   8692    // 6400 f32
#define SM_BF    15092   // 9216 u32 (B fragments, uint4-interleaved)
#define SMEM_FLOATS 24308
#define CNN_SMEM_BYTES (SMEM_FLOATS * 4)
#define QUADS (BB * KK * TT / 4)   // 6144
#define CNN_GRID 296

__global__ __launch_bounds__(256, 2) void cnn_kernel(
    const float* __restrict__ b1g, const float* __restrict__ b2g,
    const float* __restrict__ fcw, const float* __restrict__ fcb,
    float* __restrict__ out) {
    extern __shared__ float sm[];
    int tid = threadIdx.x;
    int warp = tid >> 5, lane = tid & 31;
    int tj = tid >> 6;               // tile 0..3 for conv1 pixel role
    int p = tid & 63;
    int x = p & 7, y = p >> 3;

    // ---- one-time staging: weights + zeroed padded planes (both IN bufs) ----
    for (int i = tid; i < 14400; i += 256) sm[SM_IN + i] = 0.0f;  // IN(2) + H1H + H1L
    {
        float4* dst1 = (float4*)(sm + SM_W1T);
        const float4* src1 = (const float4*)g_w1T;
        for (int i = tid; i < 144; i += 256) dst1[i] = src1[i];
        float4* dbf = (float4*)(sm + SM_BF);
        const float4* sbf = (const float4*)g_bfrag;
        for (int i = tid; i < 2304; i += 256) dbf[i] = sbf[i];
    }
    if (tid < 32) {
        sm[SM_B1 + tid] = b1g[tid];
        sm[SM_B2 + tid] = b2g[tid];
        sm[SM_FC + tid] = fcw[tid];
    }
    if (tid == 0) sm[SM_FCB] = fcb[0];

    // IN staging geometry for this thread's two elements (i = tid, tid+256)
    int st_tt0 = tid >> 7, st_e0 = tid & 127;
    int st_ch0 = st_e0 >> 6, st_pp0 = st_e0 & 63;
    int st_dst0 = (st_tt0 * 2 + st_ch0) * 100 + ((st_pp0 >> 3) + 1) * 10 + (st_pp0 & 7) + 1;
    int i1 = tid + 256;
    int st_tt1 = i1 >> 7, st_e1 = i1 & 127;
    int st_ch1 = st_e1 >> 6, st_pp1 = st_e1 & 63;
    int st_dst1 = (st_tt1 * 2 + st_ch1) * 100 + ((st_pp1 >> 3) + 1) * 10 + (st_pp1 & 7) + 1;

    // conv2 warp geometry (fixed per thread)
    int wtj = warp >> 1, whalf = warp & 1;     // tile 0..3, half 0/1
    int mat = lane >> 3;
    int rl = ((mat & 1) << 3) | (lane & 7);
    int kseg = mat >> 1;
    uint32_t h1h_addr = smem_u32(sm + SM_H1H);
    uint32_t h1l_addr = smem_u32(sm + SM_H1L);
    int py0 = (whalf * 32 + rl) >> 3,       px0_ = (whalf * 32 + rl) & 7;
    int py1 = (whalf * 32 + 16 + rl) >> 3,  px1_ = (whalf * 32 + 16 + rl) & 7;
    const uint4* bfr4 = (const uint4*)(sm + SM_BF);
    __syncthreads();

    // ---- prologue: stage first quad into IN buf 0 ----
    int quad = blockIdx.x;
    {
        float r0 = g_splat[(size_t)quad * 512 + tid];
        float r1 = g_splat[(size_t)quad * 512 + tid + 256];
        sm[SM_IN + st_dst0] = r0;
        sm[SM_IN + st_dst1] = r1;
    }
    __syncthreads();
    int buf = 0;

    while (quad < QUADS) {
        int tile0 = quad * 4;
        int nq = quad + CNN_GRID;
        int inb = SM_IN + buf * 800;

        // ---- conv1 (2->32) via FFMA2; GELU; hi/lo bf16 split into H1 planes ----
        {
            u64 acc[16];
            #pragma unroll
            for (int q = 0; q < 16; ++q) acc[q] = ((const u64*)(sm + SM_B1))[q];
            #pragma unroll
            for (int c = 0; c < 2; ++c)
                #pragma unroll
                for (int r = 0; r < 3; ++r)
                    #pragma unroll
                    for (int q3 = 0; q3 < 3; ++q3) {
                        int j = c * 9 + r * 3 + q3;
                        u64 pa = pack2(sm[inb + (tj * 2 + c) * 100 + (y + r) * 10 + (x + q3)]);
                        const ulonglong2* wv = (const ulonglong2*)(sm + SM_W1T + j * 32);
                        #pragma unroll
                        for (int q = 0; q < 8; ++q) {
                            ulonglong2 w = wv[q];
                            ffma2(acc[2 * q], pa, w.x);
                            ffma2(acc[2 * q + 1], pa, w.y);
                        }
                    }
            int ppx = (y + 1) * 10 + (x + 1);
            uint4* h1hw = (uint4*)(sm + SM_H1H);
            uint4* h1lw = (uint4*)(sm + SM_H1L);
            #pragma unroll
            for (int icg = 0; icg < 4; ++icg) {
                uint32_t ph[4], pl[4];
                #pragma unroll
                for (int qq = 0; qq < 4; ++qq) {
                    float lo, hi;
                    unpack2(lo, hi, acc[icg * 4 + qq]);
                    float g0 = gelu_fast(lo);
                    float g1 = gelu_fast(hi);
                    uint32_t pr; CVTPACK(pr, g0, g1);
                    float b0 = __uint_as_float(pr << 16);
                    float b1v = __uint_as_float(pr & 0xFFFF0000u);
                    uint32_t pr2; CVTPACK(pr2, g0 - b0, g1 - b1v);
                    ph[qq] = pr; pl[qq] = pr2;
                }
                int hidx = (tj * 4 + icg) * 100 + ppx;
                h1hw[hidx] = make_uint4(ph[0], ph[1], ph[2], ph[3]);
                h1lw[hidx] = make_uint4(pl[0], pl[1], pl[2], pl[3]);
            }
        }

        // ---- prefetch next quad's splat data (latency hidden by conv2) ----
        float pf0 = 0.0f, pf1 = 0.0f;
        if (nq < QUADS) {
            pf0 = g_splat[(size_t)nq * 512 + tid];
            pf1 = g_splat[(size_t)nq * 512 + tid + 256];
        }
        __syncthreads();   // H1 planes ready

        // ---- conv2 GEMM via mma.sync, pass-major ordering ----
        float cacc[2][4][4];
        #pragma unroll
        for (int mt = 0; mt < 2; ++mt)
            #pragma unroll
            for (int n8 = 0; n8 < 4; ++n8)
                #pragma unroll
                for (int e = 0; e < 4; ++e) cacc[mt][n8][e] = 0.0f;

        #pragma unroll 1
        for (int j = 0; j < 9; ++j) {
            int dy2 = j / 3, dx2 = j - dy2 * 3;
            int pix0 = (py0 + dy2) * 10 + (px0_ + dx2);
            int pix1 = (py1 + dy2) * 10 + (px1_ + dx2);
            uint32_t ah[2][2][4], al[2][2][4];
            #pragma unroll
            for (int ksg = 0; ksg < 2; ++ksg) {
                int plane = (wtj * 4 + ksg * 2 + kseg) * 100;
                uint32_t a0h = h1h_addr + (plane + pix0) * 16;
                uint32_t a1h = h1h_addr + (plane + pix1) * 16;
                uint32_t a0l = h1l_addr + (plane + pix0) * 16;
                uint32_t a1l = h1l_addr + (plane + pix1) * 16;
                LDMATRIX_X4(ah[0][ksg][0], ah[0][ksg][1], ah[0][ksg][2], ah[0][ksg][3], a0h);
                LDMATRIX_X4(ah[1][ksg][0], ah[1][ksg][1], ah[1][ksg][2], ah[1][ksg][3], a1h);
                LDMATRIX_X4(al[0][ksg][0], al[0][ksg][1], al[0][ksg][2], al[0][ksg][3], a0l);
                LDMATRIX_X4(al[1][ksg][0], al[1][ksg][1], al[1][ksg][2], al[1][ksg][3], a1l);
            }
            // load all 8 B fragments for this j (hi+lo in one LDS.128 each)
            uint4 Bv[2][4];
            #pragma unroll
            for (int ksg = 0; ksg < 2; ++ksg)
                #pragma unroll
                for (int n8 = 0; n8 < 4; ++n8)
                    Bv[ksg][n8] = bfr4[((2 * j + ksg) * 4 + n8) * 32 + lane];
            // pass 1: ah x bh
            #pragma unroll
            for (int ksg = 0; ksg < 2; ++ksg)
                #pragma unroll
                for (int n8 = 0; n8 < 4; ++n8) {
                    MMA16816(cacc[0][n8], ah[0][ksg], Bv[ksg][n8].x, Bv[ksg][n8].y);
                    MMA16816(cacc[1][n8], ah[1][ksg], Bv[ksg][n8].x, Bv[ksg][n8].y);
                }
            // pass 2: ah x bl
            #pragma unroll
            for (int ksg = 0; ksg < 2; ++ksg)
                #pragma unroll
                for (int n8 = 0; n8 < 4; ++n8) {
                    MMA16816(cacc[0][n8], ah[0][ksg], Bv[ksg][n8].z, Bv[ksg][n8].w);
                    MMA16816(cacc[1][n8], ah[1][ksg], Bv[ksg][n8].z, Bv[ksg][n8].w);
                }
            // pass 3: al x bh
            #pragma unroll
            for (int ksg = 0; ksg < 2; ++ksg)
                #pragma unroll
                for (int n8 = 0; n8 < 4; ++n8) {
                    MMA16816(cacc[0][n8], al[0][ksg], Bv[ksg][n8].x, Bv[ksg][n8].y);
                    MMA16816(cacc[1][n8], al[1][ksg], Bv[ksg][n8].x, Bv[ksg][n8].y);
                }
        }

        // ---- epilogue: bias + GELU + fc dot, warp reduce ----
        float s = 0.0f;
        #pragma unroll
        for (int n8 = 0; n8 < 4; ++n8) {
            int oc0 = n8 * 8 + (lane & 3) * 2;
            float bb0 = sm[SM_B2 + oc0], bb1 = sm[SM_B2 + oc0 + 1];
            float ff0 = sm[SM_FC + oc0], ff1 = sm[SM_FC + oc0 + 1];
            #pragma unroll
            for (int mt = 0; mt < 2; ++mt) {
                s = fmaf(gelu_fast(cacc[mt][n8][0] + bb0), ff0, s);
                s = fmaf(gelu_fast(cacc[mt][n8][1] + bb1), ff1, s);
                s = fmaf(gelu_fast(cacc[mt][n8][2] + bb0), ff0, s);
                s = fmaf(gelu_fast(cacc[mt][n8][3] + bb1), ff1, s);
            }
        }
        #pragma unroll
        for (int off = 16; off > 0; off >>= 1)
            s += __shfl_xor_sync(0xffffffffu, s, off);
        if (lane == 0) sm[SM_RED + warp] = s;
        __syncthreads();   // RED ready; H1 reads done

        // stage next quad into the other IN buffer
        int onb = SM_IN + (buf ^ 1) * 800;
        sm[onb + st_dst0] = pf0;
        sm[onb + st_dst1] = pf1;

        if (tid < 4) {
            float v = sm[SM_RED + tid * 2] + sm[SM_RED + tid * 2 + 1];
            v = v * (1.0f / 64.0f) + sm[SM_FCB];
            int tile = tile0 + tid;
            int b = tile / (KK * TT);
            int rem = tile - b * (KK * TT);
            int k = rem / TT;
            int t = rem - k * TT;
            out[(b * TT + t) * KK + k] = v;
        }
        __syncthreads();   // IN[buf^1] ready; RED consumed
        buf ^= 1;
        quad = nq;
    }
}

// ---------------- launch ----------------
extern "C" void kernel_launch(void* const* d_in, const int* in_sizes, int n_in,
                              void* d_out, int out_size) {
    const float* mu        = (const float*)d_in[0];
    const float* sigma0    = (const float*)d_in[1];
    const float* sigma_vel = (const float*)d_in[2];
    const float* amplitude = (const float*)d_in[3];
    const float* sh_base   = (const float*)d_in[4];
    const float* sh_vel    = (const float*)d_in[5];
    const float* p0        = (const float*)d_in[6];
    const float* p_vel     = (const float*)d_in[7];
    const float* tau_raw   = (const float*)d_in[8];
    const float* gam_raw   = (const float*)d_in[9];
    const float* limb_ra   = (const float*)d_in[10];
    const float* limb_la   = (const float*)d_in[11];
    const float* limb_ll   = (const float*)d_in[12];
    const float* chest     = (const float*)d_in[13];
    const float* conv1_w   = (const float*)d_in[14];
    const float* conv1_b   = (const float*)d_in[15];
    const float* conv2_w   = (const float*)d_in[16];
    const float* conv2_b   = (const float*)d_in[17];
    const float* fc_w      = (const float*)d_in[18];
    const float* fc_b      = (const float*)d_in[19];
    float* out = (float*)d_out;

    prep_kernel<<<1, 256>>>(limb_ra, limb_la, limb_ll, chest, conv1_w, conv2_w);
    splat_kernel<<<dim3(TT, BB), 384>>>(mu, sigma0, sigma_vel, amplitude,
                                        sh_base, sh_vel, p0, p_vel, tau_raw, gam_raw);
    cudaFuncSetAttribute(cnn_kernel, cudaFuncAttributeMaxDynamicSharedMemorySize,
                         CNN_SMEM_BYTES);
    cnn_kernel<<<CNN_GRID, 256, CNN_SMEM_BYTES>>>(conv1_b, conv2_b, fc_w, fc_b, out);
}

// round 10
// speedup vs baseline: 2.5096x; 1.1837x over previous
#include <cuda_runtime.h>
#include <cuda_bf16.h>
#include <cuda_fp16.h>
#include <math.h>
#include <stdint.h>

// Problem dims (fixed by the dataset)
#define BB 4
#define NN 96
#define TT 512
#define KK 12
#define GG 8

typedef unsigned long long u64;

// ---------------- device scratch (no cudaMalloc allowed) ----------------
__device__ float g_lead[KK * 18];
__device__ float g_splat[(size_t)BB * KK * TT * 128];     // (B,K,T,2,8,8)
__device__ float g_w1T[576];                              // conv1 weights [c*9+j][oc]
// conv2 B fragments (fp16, weights pre-scaled x256), uint4-interleaved:
// frag f = (ks*4+n8)*32+lane holds uint32s [4f..4f+3] = {bh_r0, bh_r1, bl_r0, bl_r1}
__device__ __align__(16) uint32_t g_bfrag[9216];

// ---------------- small helpers ----------------
__device__ __forceinline__ u64 pack2(float x) {
    u64 r; asm("mov.b64 %0, {%1, %1};" : "=l"(r) : "f"(x)); return r;
}
__device__ __forceinline__ void ffma2(u64& d, u64 a, u64 b) {
    asm("fma.rn.f32x2 %0, %1, %2, %0;" : "+l"(d) : "l"(a), "l"(b));
}
__device__ __forceinline__ void unpack2(float& lo, float& hi, u64 v) {
    asm("mov.b64 {%0, %1}, %2;" : "=f"(lo), "=f"(hi) : "l"(v));
}
__device__ __forceinline__ float softplusf(float x) {
    return (x > 20.0f) ? x : log1pf(expf(x));
}
__device__ __forceinline__ float softplus_fast(float x) {
    return (x > 20.0f) ? x : __logf(1.0f + __expf(x));
}
__device__ __forceinline__ float tanh_fast(float x) {
    float xc = fminf(fmaxf(x, -15.0f), 15.0f);
    float t = __expf(2.0f * xc);
    return (t - 1.0f) * __fdividef(1.0f, t + 1.0f);
}
// Pade [5/4] tanh, valid |x|<=1 (args are dots of unit vectors with |p|<1)
__device__ __forceinline__ float tanh_pade(float x) {
    float x2 = x * x;
    float p = fmaf(fmaf(x2, 1.0f, 105.0f), x2, 945.0f);
    float q = fmaf(fmaf(15.0f, x2, 420.0f), x2, 945.0f);
    return __fdividef(x * p, q);
}
__device__ __forceinline__ float acos_fast01(float c) {
    float p = sqrtf(fmaxf(1.0f - c, 0.0f));
    float poly = fmaf(c, fmaf(c, fmaf(c, -0.0187293f, 0.0742610f), -0.2121144f), 1.5707288f);
    return p * poly;
}
__device__ __forceinline__ float gelu_fast(float x) {
    float ax = fabsf(x);
    float z = ax * 0.70710678118f;
    float t = __fdividef(1.0f, fmaf(0.3275911f, z, 1.0f));
    float poly = t * fmaf(t, fmaf(t, fmaf(t, fmaf(t, 1.061405429f, -1.453152027f),
                                          1.421413741f), -0.284496736f), 0.254829592f);
    float e = __expf(-z * z);
    float erfv = fmaf(-poly, e, 1.0f);
    erfv = copysignf(erfv, x);
    return 0.5f * x * (1.0f + erfv);
}
__device__ __forceinline__ uint32_t smem_u32(const void* p) {
    uint32_t a;
    asm("{ .reg .u64 t; cvta.to.shared.u64 t, %1; cvt.u32.u64 %0, t; }" : "=r"(a) : "l"(p));
    return a;
}
// pack two f32 -> f16x2 (lo = a, hi = b)
#define CVTPACK_F16(r, a, b) \
    asm("cvt.rn.f16x2.f32 %0, %2, %1;" : "=r"(r) : "f"(a), "f"(b))
// ldmatrix x4 (A fragments)
#define LDMATRIX_X4(r0, r1, r2, r3, addr) \
    asm volatile("ldmatrix.sync.aligned.m8n8.x4.shared.b16 {%0,%1,%2,%3}, [%4];" \
                 : "=r"(r0), "=r"(r1), "=r"(r2), "=r"(r3) : "r"(addr))
// fp16 mma m16n8k16, C(f32) += A*B  (B passed as two b32 regs)
#define MMA16816(c, a, b0, b1) \
    asm volatile("mma.sync.aligned.m16n8k16.row.col.f32.f16.f16.f32 " \
                 "{%0,%1,%2,%3},{%4,%5,%6,%7},{%8,%9},{%0,%1,%2,%3};" \
                 : "+f"((c)[0]), "+f"((c)[1]), "+f"((c)[2]), "+f"((c)[3]) \
                 : "r"((a)[0]), "r"((a)[1]), "r"((a)[2]), "r"((a)[3]), \
                   "r"(b0), "r"(b1))

#define W2_SCALE   256.0f
#define W2_UNSCALE (1.0f / 256.0f)

// ---------------- kernel 0: leads + conv1 transpose + conv2 B-fragments ----
__global__ void prep_kernel(const float* __restrict__ ra, const float* __restrict__ la,
                            const float* __restrict__ ll, const float* __restrict__ chest,
                            const float* __restrict__ w1, const float* __restrict__ w2) {
    int tid = threadIdx.x;
    // conv2 B fragments (fp16 hi/lo, weights x256), uint4-interleaved layout
    for (int i = tid; i < 9216; i += 256) {
        int c4 = i & 3;                  // 0,1 = hi r0/r1; 2,3 = lo r0/r1
        int f = i >> 2;
        int lane = f & 31;
        int n8 = (f >> 5) & 3;
        int ks = f >> 7;                 // 0..17
        int s = c4 >> 1;                 // 0 = hi, 1 = lo
        int r = c4 & 1;
        int oc = n8 * 8 + (lane >> 2);
        int k0 = ks * 16 + (lane & 3) * 2 + r * 8;
        uint32_t pk = 0;
        #pragma unroll
        for (int e = 0; e < 2; ++e) {
            int k = k0 + e;
            int j = k / 32, ic = k % 32;
            float w = w2[oc * 288 + ic * 9 + j] * W2_SCALE;
            __half h = __float2half_rn(w);
            unsigned short bits;
            if (s == 0) bits = __half_as_ushort(h);
            else {
                float hf = __half2float(h);
                bits = __half_as_ushort(__float2half_rn(w - hf));
            }
            pk |= (uint32_t)bits << (16 * e);
        }
        g_bfrag[i] = pk;
    }
    for (int idx = tid; idx < 576; idx += 256) {
        int oc = idx / 18;
        int r = idx - oc * 18;
        g_w1T[r * 32 + oc] = w1[idx];
    }
    if (tid >= KK) return;
    int k = tid;
    float vx, vy, vz;
    float rax = ra[0], ray = ra[1], raz = ra[2];
    float lax = la[0], lay = la[1], laz = la[2];
    float llx = ll[0], lly = ll[1], llz = ll[2];
    switch (k) {
        case 0: vx = lax - rax; vy = lay - ray; vz = laz - raz; break;
        case 1: vx = llx - rax; vy = lly - ray; vz = llz - raz; break;
        case 2: vx = llx - lax; vy = lly - lay; vz = llz - laz; break;
        case 3: vx = rax - 0.5f * (lax + llx); vy = ray - 0.5f * (lay + lly); vz = raz - 0.5f * (laz + llz); break;
        case 4: vx = lax - 0.5f * (rax + llx); vy = lay - 0.5f * (ray + lly); vz = laz - 0.5f * (raz + llz); break;
        case 5: vx = llx - 0.5f * (rax + lax); vy = lly - 0.5f * (ray + lay); vz = llz - 0.5f * (raz + laz); break;
        default:
            vx = chest[(k - 6) * 3 + 0]; vy = chest[(k - 6) * 3 + 1]; vz = chest[(k - 6) * 3 + 2];
            break;
    }
    float n = sqrtf(vx * vx + vy * vy + vz * vz);
    float d = fmaxf(n, 1e-6f);
    float Lx = vx / d, Ly = vy / d, Lz = vz / d;
    float e1x = 0.0f, e1y = Lz, e1z = -Ly;
    float n1 = sqrtf(e1y * e1y + e1z * e1z);
    if (n1 < 1e-4f) { e1x = -Lz; e1y = 0.0f; e1z = Lx; n1 = sqrtf(e1x * e1x + e1z * e1z); }
    float d1 = fmaxf(n1, 1e-6f);
    e1x /= d1; e1y /= d1; e1z /= d1;
    float e2x = e1y * Lz - e1z * Ly;
    float e2y = e1z * Lx - e1x * Lz;
    float e2z = e1x * Ly - e1y * Lx;
    float n2 = sqrtf(e2x * e2x + e2y * e2y + e2z * e2z);
    float d2 = fmaxf(n2, 1e-6f);
    e2x /= d2; e2y /= d2; e2z /= d2;
    float* o = g_lead + k * 18;
    o[0] = Lx; o[1] = Ly; o[2] = Lz;
    o[3] = e1x; o[4] = e1y; o[5] = e1z;
    o[6] = e2x; o[7] = e2y; o[8] = e2z;
    o[9]  = 0.282095f;
    o[10] = -0.488603f * Ly;
    o[11] = 0.488603f * Lz;
    o[12] = -0.488603f * Lx;
    o[13] = 1.092548f * Lx * Ly;
    o[14] = -1.092548f * Ly * Lz;
    o[15] = 0.315392f * (3.0f * Lz * Lz - 1.0f);
    o[16] = -1.092548f * Lx * Lz;
    o[17] = 0.546274f * (Lx * Lx - Ly * Ly);
}

// ---------------- kernel 1: splat rasterization ----------------
#define NC 32

__global__ __launch_bounds__(384) void splat_kernel(
    const float* __restrict__ mu, const float* __restrict__ sigma0,
    const float* __restrict__ sigma_vel, const float* __restrict__ amplitude,
    const float* __restrict__ sh_base, const float* __restrict__ sh_vel,
    const float* __restrict__ p0, const float* __restrict__ p_vel,
    const float* __restrict__ tau_raw, const float* __restrict__ gam_raw) {
    __shared__ float  sLead[KK][18];
    __shared__ float2 sAA[NC][KK];
    __shared__ float  sKu[NC][KK][9];
    __shared__ float  sKv[NC][KK][9];

    int t = blockIdx.x, b = blockIdx.y;
    int tid = threadIdx.x;
    if (tid < KK * 18) ((float*)sLead)[tid] = g_lead[tid];

    float tau = softplusf(tau_raw[0]) + 0.06f;
    float inv2tau2 = 0.5f / (tau * tau);
    float gamma = softplusf(gam_raw[0]) + 1e-6f;
    float tval = (float)t * (1.0f / (float)(TT - 1));
    const float DLT = 2.0f / 7.0f;
    float aD = inv2tau2 * DLT;
    float Cc = __expf(-2.0f * aD * DLT);   // exp recurrence constant

    int warp = tid >> 5, lane = tid & 31;
    int px0 = lane * 2;
    int hh = px0 >> 3, w0 = px0 & 7;
    float acc00 = 0.f, acc01 = 0.f, acc10 = 0.f, acc11 = 0.f;

    int nl = tid / KK, kk = tid - nl * KK;
    __syncthreads();

    for (int c = 0; c < NN / NC; ++c) {
        {
            int n = c * NC + nl;
            int bn = b * NN + n;
            float dt = tval - mu[bn];
            float sig = softplus_fast(sigma0[bn] + sigma_vel[bn] * dt) + 1e-3f;
            float z = dt * __fdividef(1.0f, sig);
            float gauss = amplitude[bn] * __expf(-0.5f * z * z);
            float prx = p0[bn * 3 + 0] + p_vel[bn * 3 + 0] * dt;
            float pry = p0[bn * 3 + 1] + p_vel[bn * 3 + 1] * dt;
            float prz = p0[bn * 3 + 2] + p_vel[bn * 3 + 2] * dt;
            float nrm = fmaxf(sqrtf(prx * prx + pry * pry + prz * prz), 1e-8f);
            float th = tanh_fast(nrm);
            float sc = th * __fdividef(1.0f, nrm);
            float ppx = prx * sc, ppy = pry * sc, ppz = prz * sc;
            const float* Ld = sLead[kk];
            float u = tanh_pade(ppx * Ld[3] + ppy * Ld[4] + ppz * Ld[5]);
            float v = tanh_pade(ppx * Ld[6] + ppy * Ld[7] + ppz * Ld[8]);
            float pn = fmaxf(th, 1e-8f);
            float cosl = (ppx * Ld[0] + ppy * Ld[1] + ppz * Ld[2]) * __fdividef(1.0f, pn);
            float hem = fmaxf(cosl, 0.0f);
            float ccv = fminf(fmaxf(cosl, -1.0f + 1e-6f), 1.0f - 1e-6f);
            float theta = acos_fast01(ccv);
            float weight = hem * __expf(-gamma * theta * theta);
            float A = gauss * weight;
            float shp = 0.0f;
            #pragma unroll
            for (int m = 0; m < 9; ++m)
                shp += (sh_base[bn * 9 + m] + sh_vel[bn * 9 + m] * dt) * Ld[9 + m];
            sAA[nl][kk] = make_float2(A, A * shp);
            // Gaussian grid via exp recurrence: 2 exp per axis instead of 8
            {
                float d0 = u + 1.0f;
                float Kx = __expf(-inv2tau2 * d0 * d0);
                float Rx = __expf(aD * (2.0f * d0 - DLT));
                #pragma unroll
                for (int g = 0; g < GG; ++g) { sKu[nl][kk][g] = Kx; Kx *= Rx; Rx *= Cc; }
                float d0v = v + 1.0f;
                float Kv2 = __expf(-inv2tau2 * d0v * d0v);
                float Rv = __expf(aD * (2.0f * d0v - DLT));
                #pragma unroll
                for (int g = 0; g < GG; ++g) { sKv[nl][kk][g] = Kv2; Kv2 *= Rv; Rv *= Cc; }
            }
        }
        __syncthreads();
        #pragma unroll 8
        for (int n2 = 0; n2 < NC; ++n2) {
            float2 aa = sAA[n2][warp];
            float kvh = sKv[n2][warp][hh];
            float ku0 = sKu[n2][warp][w0];
            float ku1 = sKu[n2][warp][w0 + 1];
            float tA = aa.x * kvh, tS = aa.y * kvh;
            acc00 = fmaf(tA, ku0, acc00);
            acc01 = fmaf(tA, ku1, acc01);
            acc10 = fmaf(tS, ku0, acc10);
            acc11 = fmaf(tS, ku1, acc11);
        }
        __syncthreads();
    }
    size_t base = ((size_t)((b * KK + warp) * TT + t)) * 128;
    g_splat[base + px0]          = acc00;
    g_splat[base + px0 + 1]      = acc01;
    g_splat[base + 64 + px0]     = acc10;
    g_splat[base + 64 + px0 + 1] = acc11;
}

// ---------------- kernel 2: PERSISTENT CNN, fp16 2-pass MMA + IN ping-pong ----
// 256 threads = 8 warps, 4 tiles per iteration, grid 296 (2 blocks/SM).
// smem float-index layout:
#define SM_RED   0       // 16
#define SM_B1    16      // 32
#define SM_B2    48      // 32
#define SM_FC    80      // 32
#define SM_FCB   112     // 1 (+3 pad)
#define SM_W1T   116     // 576
#define SM_IN    692     // [2 buf][4 tiles][2 ch][100] fp32 = 1600
#define SM_H1    2292    // [4 tiles][4 icg][100 px][8 ch] fp16 = 6400 f32
#define SM_BF    8692    // 9216 u32 (B fragments, uint4-interleaved)
#define SMEM_FLOATS 17908
#define CNN_SMEM_BYTES (SMEM_FLOATS * 4)
#define QUADS (BB * KK * TT / 4)   // 6144
#define CNN_GRID 296

__global__ __launch_bounds__(256, 2) void cnn_kernel(
    const float* __restrict__ b1g, const float* __restrict__ b2g,
    const float* __restrict__ fcw, const float* __restrict__ fcb,
    float* __restrict__ out) {
    extern __shared__ float sm[];
    int tid = threadIdx.x;
    int warp = tid >> 5, lane = tid & 31;
    int tj = tid >> 6;               // tile 0..3 for conv1 pixel role
    int p = tid & 63;
    int x = p & 7, y = p >> 3;

    // ---- one-time staging: weights + zeroed padded planes (both IN bufs) ----
    for (int i = tid; i < 8000; i += 256) sm[SM_IN + i] = 0.0f;  // IN(2) + H1
    {
        float4* dst1 = (float4*)(sm + SM_W1T);
        const float4* src1 = (const float4*)g_w1T;
        for (int i = tid; i < 144; i += 256) dst1[i] = src1[i];
        float4* dbf = (float4*)(sm + SM_BF);
        const float4* sbf = (const float4*)g_bfrag;
        for (int i = tid; i < 2304; i += 256) dbf[i] = sbf[i];
    }
    if (tid < 32) {
        sm[SM_B1 + tid] = b1g[tid];
        sm[SM_B2 + tid] = b2g[tid];
        sm[SM_FC + tid] = fcw[tid];
    }
    if (tid == 0) sm[SM_FCB] = fcb[0];

    // IN staging geometry for this thread's two elements (i = tid, tid+256)
    int st_tt0 = tid >> 7, st_e0 = tid & 127;
    int st_ch0 = st_e0 >> 6, st_pp0 = st_e0 & 63;
    int st_dst0 = (st_tt0 * 2 + st_ch0) * 100 + ((st_pp0 >> 3) + 1) * 10 + (st_pp0 & 7) + 1;
    int i1 = tid + 256;
    int st_tt1 = i1 >> 7, st_e1 = i1 & 127;
    int st_ch1 = st_e1 >> 6, st_pp1 = st_e1 & 63;
    int st_dst1 = (st_tt1 * 2 + st_ch1) * 100 + ((st_pp1 >> 3) + 1) * 10 + (st_pp1 & 7) + 1;

    // conv2 warp geometry (fixed per thread)
    int wtj = warp >> 1, whalf = warp & 1;     // tile 0..3, half 0/1
    int mat = lane >> 3;
    int rl = ((mat & 1) << 3) | (lane & 7);
    int kseg = mat >> 1;
    uint32_t h1_addr = smem_u32(sm + SM_H1);
    int py0 = (whalf * 32 + rl) >> 3,       px0_ = (whalf * 32 + rl) & 7;
    int py1 = (whalf * 32 + 16 + rl) >> 3,  px1_ = (whalf * 32 + 16 + rl) & 7;
    const uint4* bfr4 = (const uint4*)(sm + SM_BF);
    __syncthreads();

    // ---- prologue: stage first quad into IN buf 0 ----
    int quad = blockIdx.x;
    {
        float r0 = g_splat[(size_t)quad * 512 + tid];
        float r1 = g_splat[(size_t)quad * 512 + tid + 256];
        sm[SM_IN + st_dst0] = r0;
        sm[SM_IN + st_dst1] = r1;
    }
    __syncthreads();
    int buf = 0;

    while (quad < QUADS) {
        int tile0 = quad * 4;
        int nq = quad + CNN_GRID;
        int inb = SM_IN + buf * 800;

        // ---- conv1 (2->32) via FFMA2; GELU; fp16 pack into H1 plane ----
        {
            u64 acc[16];
            #pragma unroll
            for (int q = 0; q < 16; ++q) acc[q] = ((const u64*)(sm + SM_B1))[q];
            #pragma unroll
            for (int c = 0; c < 2; ++c)
                #pragma unroll
                for (int r = 0; r < 3; ++r)
                    #pragma unroll
                    for (int q3 = 0; q3 < 3; ++q3) {
                        int j = c * 9 + r * 3 + q3;
                        u64 pa = pack2(sm[inb + (tj * 2 + c) * 100 + (y + r) * 10 + (x + q3)]);
                        const ulonglong2* wv = (const ulonglong2*)(sm + SM_W1T + j * 32);
                        #pragma unroll
                        for (int q = 0; q < 8; ++q) {
                            ulonglong2 w = wv[q];
                            ffma2(acc[2 * q], pa, w.x);
                            ffma2(acc[2 * q + 1], pa, w.y);
                        }
                    }
            int ppx = (y + 1) * 10 + (x + 1);
            uint4* h1w = (uint4*)(sm + SM_H1);
            #pragma unroll
            for (int icg = 0; icg < 4; ++icg) {
                uint32_t ph[4];
                #pragma unroll
                for (int qq = 0; qq < 4; ++qq) {
                    float lo, hi;
                    unpack2(lo, hi, acc[icg * 4 + qq]);
                    float g0 = gelu_fast(lo);
                    float g1 = gelu_fast(hi);
                    CVTPACK_F16(ph[qq], g0, g1);
                }
                h1w[(tj * 4 + icg) * 100 + ppx] = make_uint4(ph[0], ph[1], ph[2], ph[3]);
            }
        }

        // ---- prefetch next quad's splat data (latency hidden by conv2) ----
        float pf0 = 0.0f, pf1 = 0.0f;
        if (nq < QUADS) {
            pf0 = g_splat[(size_t)nq * 512 + tid];
            pf1 = g_splat[(size_t)nq * 512 + tid + 256];
        }
        __syncthreads();   // H1 plane ready

        // ---- conv2 GEMM via fp16 mma.sync, 2 passes (a x bh, a x bl) ----
        float cacc[2][4][4];
        #pragma unroll
        for (int mt = 0; mt < 2; ++mt)
            #pragma unroll
            for (int n8 = 0; n8 < 4; ++n8)
                #pragma unroll
                for (int e = 0; e < 4; ++e) cacc[mt][n8][e] = 0.0f;

        #pragma unroll 1
        for (int j = 0; j < 9; ++j) {
            int dy2 = j / 3, dx2 = j - dy2 * 3;
            int pix0 = (py0 + dy2) * 10 + (px0_ + dx2);
            int pix1 = (py1 + dy2) * 10 + (px1_ + dx2);
            uint32_t ah[2][2][4];
            #pragma unroll
            for (int ksg = 0; ksg < 2; ++ksg) {
                int plane = (wtj * 4 + ksg * 2 + kseg) * 100;
                uint32_t a0 = h1_addr + (plane + pix0) * 16;
                uint32_t a1 = h1_addr + (plane + pix1) * 16;
                LDMATRIX_X4(ah[0][ksg][0], ah[0][ksg][1], ah[0][ksg][2], ah[0][ksg][3], a0);
                LDMATRIX_X4(ah[1][ksg][0], ah[1][ksg][1], ah[1][ksg][2], ah[1][ksg][3], a1);
            }
            // load all 8 B fragments for this j (hi+lo in one LDS.128 each)
            uint4 Bv[2][4];
            #pragma unroll
            for (int ksg = 0; ksg < 2; ++ksg)
                #pragma unroll
                for (int n8 = 0; n8 < 4; ++n8)
                    Bv[ksg][n8] = bfr4[((2 * j + ksg) * 4 + n8) * 32 + lane];
            // pass 1: a x bh
            #pragma unroll
            for (int ksg = 0; ksg < 2; ++ksg)
                #pragma unroll
                for (int n8 = 0; n8 < 4; ++n8) {
                    MMA16816(cacc[0][n8], ah[0][ksg], Bv[ksg][n8].x, Bv[ksg][n8].y);
                    MMA16816(cacc[1][n8], ah[1][ksg], Bv[ksg][n8].x, Bv[ksg][n8].y);
                }
            // pass 2: a x bl
            #pragma unroll
            for (int ksg = 0; ksg < 2; ++ksg)
                #pragma unroll
                for (int n8 = 0; n8 < 4; ++n8) {
                    MMA16816(cacc[0][n8], ah[0][ksg], Bv[ksg][n8].z, Bv[ksg][n8].w);
                    MMA16816(cacc[1][n8], ah[1][ksg], Bv[ksg][n8].z, Bv[ksg][n8].w);
                }
        }

        // ---- epilogue: unscale + bias + GELU + fc dot, warp reduce ----
        float s = 0.0f;
        #pragma unroll
        for (int n8 = 0; n8 < 4; ++n8) {
            int oc0 = n8 * 8 + (lane & 3) * 2;
            float bb0 = sm[SM_B2 + oc0], bb1 = sm[SM_B2 + oc0 + 1];
            float ff0 = sm[SM_FC + oc0], ff1 = sm[SM_FC + oc0 + 1];
            #pragma unroll
            for (int mt = 0; mt < 2; ++mt) {
                s = fmaf(gelu_fast(fmaf(cacc[mt][n8][0], W2_UNSCALE, bb0)), ff0, s);
                s = fmaf(gelu_fast(fmaf(cacc[mt][n8][1], W2_UNSCALE, bb1)), ff1, s);
                s = fmaf(gelu_fast(fmaf(cacc[mt][n8][2], W2_UNSCALE, bb0)), ff0, s);
                s = fmaf(gelu_fast(fmaf(cacc[mt][n8][3], W2_UNSCALE, bb1)), ff1, s);
            }
        }
        #pragma unroll
        for (int off = 16; off > 0; off >>= 1)
            s += __shfl_xor_sync(0xffffffffu, s, off);
        if (lane == 0) sm[SM_RED + warp] = s;
        __syncthreads();   // RED ready; H1 reads done

        // stage next quad into the other IN buffer
        int onb = SM_IN + (buf ^ 1) * 800;
        sm[onb + st_dst0] = pf0;
        sm[onb + st_dst1] = pf1;

        if (tid < 4) {
            float v = sm[SM_RED + tid * 2] + sm[SM_RED + tid * 2 + 1];
            v = v * (1.0f / 64.0f) + sm[SM_FCB];
            int tile = tile0 + tid;
            int b = tile / (KK * TT);
            int rem = tile - b * (KK * TT);
            int k = rem / TT;
            int t = rem - k * TT;
            out[(b * TT + t) * KK + k] = v;
        }
        __syncthreads();   // IN[buf^1] ready; RED consumed
        buf ^= 1;
        quad = nq;
    }
}

// ---------------- launch ----------------
extern "C" void kernel_launch(void* const* d_in, const int* in_sizes, int n_in,
                              void* d_out, int out_size) {
    const float* mu        = (const float*)d_in[0];
    const float* sigma0    = (const float*)d_in[1];
    const float* sigma_vel = (const float*)d_in[2];
    const float* amplitude = (const float*)d_in[3];
    const float* sh_base   = (const float*)d_in[4];
    const float* sh_vel    = (const float*)d_in[5];
    const float* p0        = (const float*)d_in[6];
    const float* p_vel     = (const float*)d_in[7];
    const float* tau_raw   = (const float*)d_in[8];
    const float* gam_raw   = (const float*)d_in[9];
    const float* limb_ra   = (const float*)d_in[10];
    const float* limb_la   = (const float*)d_in[11];
    const float* limb_ll   = (const float*)d_in[12];
    const float* chest     = (const float*)d_in[13];
    const float* conv1_w   = (const float*)d_in[14];
    const float* conv1_b   = (const float*)d_in[15];
    const float* conv2_w   = (const float*)d_in[16];
    const float* conv2_b   = (const float*)d_in[17];
    const float* fc_w      = (const float*)d_in[18];
    const float* fc_b      = (const float*)d_in[19];
    float* out = (float*)d_out;

    prep_kernel<<<1, 256>>>(limb_ra, limb_la, limb_ll, chest, conv1_w, conv2_w);
    splat_kernel<<<dim3(TT, BB), 384>>>(mu, sigma0, sigma_vel, amplitude,
                                        sh_base, sh_vel, p0, p_vel, tau_raw, gam_raw);
    cudaFuncSetAttribute(cnn_kernel, cudaFuncAttributeMaxDynamicSharedMemorySize,
                         CNN_SMEM_BYTES);
    cnn_kernel<<<CNN_GRID, 256, CNN_SMEM_BYTES>>>(conv1_b, conv2_b, fc_w, fc_b, out);
}

// round 11
// speedup vs baseline: 2.9823x; 1.1884x over previous
#include <cuda_runtime.h>
#include <cuda_bf16.h>
#include <cuda_fp16.h>
#include <math.h>
#include <stdint.h>

// Problem dims (fixed by the dataset)
#define BB 4
#define NN 96
#define TT 512
#define KK 12
#define GG 8

typedef unsigned long long u64;

// ---------------- device scratch (no cudaMalloc allowed) ----------------
__device__ float g_lead[KK * 18];
__device__ float g_splat[(size_t)BB * KK * TT * 128];     // (B,K,T,2,8,8)
__device__ float g_w1T[576];                              // conv1 weights [c*9+j][oc]
// conv2 B fragments (single fp16): frag f = (ks*4+n8)*32+lane holds
// uint32s [2f, 2f+1] = {b_r0, b_r1}
__device__ __align__(16) uint32_t g_bfrag[4608];

// ---------------- small helpers ----------------
__device__ __forceinline__ u64 pack2(float x) {
    u64 r; asm("mov.b64 %0, {%1, %1};" : "=l"(r) : "f"(x)); return r;
}
__device__ __forceinline__ void ffma2(u64& d, u64 a, u64 b) {
    asm("fma.rn.f32x2 %0, %1, %2, %0;" : "+l"(d) : "l"(a), "l"(b));
}
__device__ __forceinline__ void unpack2(float& lo, float& hi, u64 v) {
    asm("mov.b64 {%0, %1}, %2;" : "=f"(lo), "=f"(hi) : "l"(v));
}
__device__ __forceinline__ float softplusf(float x) {
    return (x > 20.0f) ? x : log1pf(expf(x));
}
__device__ __forceinline__ float softplus_fast(float x) {
    return (x > 20.0f) ? x : __logf(1.0f + __expf(x));
}
__device__ __forceinline__ float tanh_fast(float x) {
    float xc = fminf(fmaxf(x, -15.0f), 15.0f);
    float t = __expf(2.0f * xc);
    return (t - 1.0f) * __fdividef(1.0f, t + 1.0f);
}
// Pade [5/4] tanh, valid |x|<=1 (args are dots of unit vectors with |p|<1)
__device__ __forceinline__ float tanh_pade(float x) {
    float x2 = x * x;
    float p = fmaf(fmaf(x2, 1.0f, 105.0f), x2, 945.0f);
    float q = fmaf(fmaf(15.0f, x2, 420.0f), x2, 945.0f);
    return __fdividef(x * p, q);
}
__device__ __forceinline__ float acos_fast01(float c) {
    float p = sqrtf(fmaxf(1.0f - c, 0.0f));
    float poly = fmaf(c, fmaf(c, fmaf(c, -0.0187293f, 0.0742610f), -0.2121144f), 1.5707288f);
    return p * poly;
}
__device__ __forceinline__ float gelu_fast(float x) {
    float ax = fabsf(x);
    float z = ax * 0.70710678118f;
    float t = __fdividef(1.0f, fmaf(0.3275911f, z, 1.0f));
    float poly = t * fmaf(t, fmaf(t, fmaf(t, fmaf(t, 1.061405429f, -1.453152027f),
                                          1.421413741f), -0.284496736f), 0.254829592f);
    float e = __expf(-z * z);
    float erfv = fmaf(-poly, e, 1.0f);
    erfv = copysignf(erfv, x);
    return 0.5f * x * (1.0f + erfv);
}
__device__ __forceinline__ uint32_t smem_u32(const void* p) {
    uint32_t a;
    asm("{ .reg .u64 t; cvta.to.shared.u64 t, %1; cvt.u32.u64 %0, t; }" : "=r"(a) : "l"(p));
    return a;
}
// pack two f32 -> f16x2 (lo = a, hi = b)
#define CVTPACK_F16(r, a, b) \
    asm("cvt.rn.f16x2.f32 %0, %2, %1;" : "=r"(r) : "f"(a), "f"(b))
// ldmatrix x4 (A fragments)
#define LDMATRIX_X4(r0, r1, r2, r3, addr) \
    asm volatile("ldmatrix.sync.aligned.m8n8.x4.shared.b16 {%0,%1,%2,%3}, [%4];" \
                 : "=r"(r0), "=r"(r1), "=r"(r2), "=r"(r3) : "r"(addr))
// fp16 mma m16n8k16, C(f32) += A*B  (B passed as two b32 regs)
#define MMA16816(c, a, b0, b1) \
    asm volatile("mma.sync.aligned.m16n8k16.row.col.f32.f16.f16.f32 " \
                 "{%0,%1,%2,%3},{%4,%5,%6,%7},{%8,%9},{%0,%1,%2,%3};" \
                 : "+f"((c)[0]), "+f"((c)[1]), "+f"((c)[2]), "+f"((c)[3]) \
                 : "r"((a)[0]), "r"((a)[1]), "r"((a)[2]), "r"((a)[3]), \
                   "r"(b0), "r"(b1))

// ---------------- kernel 0: leads + conv1 transpose + conv2 B-fragments ----
__global__ void prep_kernel(const float* __restrict__ ra, const float* __restrict__ la,
                            const float* __restrict__ ll, const float* __restrict__ chest,
                            const float* __restrict__ w1, const float* __restrict__ w2) {
    int tid = threadIdx.x;
    // conv2 B fragments (single fp16), uint2 layout
    for (int i = tid; i < 4608; i += 256) {
        int r = i & 1;
        int f = i >> 1;
        int lane = f & 31;
        int n8 = (f >> 5) & 3;
        int ks = f >> 7;                 // 0..17
        int oc = n8 * 8 + (lane >> 2);
        int k0 = ks * 16 + (lane & 3) * 2 + r * 8;
        uint32_t pk = 0;
        #pragma unroll
        for (int e = 0; e < 2; ++e) {
            int k = k0 + e;
            int j = k / 32, ic = k % 32;
            float w = w2[oc * 288 + ic * 9 + j];
            unsigned short bits = __half_as_ushort(__float2half_rn(w));
            pk |= (uint32_t)bits << (16 * e);
        }
        g_bfrag[i] = pk;
    }
    for (int idx = tid; idx < 576; idx += 256) {
        int oc = idx / 18;
        int r = idx - oc * 18;
        g_w1T[r * 32 + oc] = w1[idx];
    }
    if (tid >= KK) return;
    int k = tid;
    float vx, vy, vz;
    float rax = ra[0], ray = ra[1], raz = ra[2];
    float lax = la[0], lay = la[1], laz = la[2];
    float llx = ll[0], lly = ll[1], llz = ll[2];
    switch (k) {
        case 0: vx = lax - rax; vy = lay - ray; vz = laz - raz; break;
        case 1: vx = llx - rax; vy = lly - ray; vz = llz - raz; break;
        case 2: vx = llx - lax; vy = lly - lay; vz = llz - laz; break;
        case 3: vx = rax - 0.5f * (lax + llx); vy = ray - 0.5f * (lay + lly); vz = raz - 0.5f * (laz + llz); break;
        case 4: vx = lax - 0.5f * (rax + llx); vy = lay - 0.5f * (ray + lly); vz = laz - 0.5f * (raz + llz); break;
        case 5: vx = llx - 0.5f * (rax + lax); vy = lly - 0.5f * (ray + lay); vz = llz - 0.5f * (raz + laz); break;
        default:
            vx = chest[(k - 6) * 3 + 0]; vy = chest[(k - 6) * 3 + 1]; vz = chest[(k - 6) * 3 + 2];
            break;
    }
    float n = sqrtf(vx * vx + vy * vy + vz * vz);
    float d = fmaxf(n, 1e-6f);
    float Lx = vx / d, Ly = vy / d, Lz = vz / d;
    float e1x = 0.0f, e1y = Lz, e1z = -Ly;
    float n1 = sqrtf(e1y * e1y + e1z * e1z);
    if (n1 < 1e-4f) { e1x = -Lz; e1y = 0.0f; e1z = Lx; n1 = sqrtf(e1x * e1x + e1z * e1z); }
    float d1 = fmaxf(n1, 1e-6f);
    e1x /= d1; e1y /= d1; e1z /= d1;
    float e2x = e1y * Lz - e1z * Ly;
    float e2y = e1z * Lx - e1x * Lz;
    float e2z = e1x * Ly - e1y * Lx;
    float n2 = sqrtf(e2x * e2x + e2y * e2y + e2z * e2z);
    float d2 = fmaxf(n2, 1e-6f);
    e2x /= d2; e2y /= d2; e2z /= d2;
    float* o = g_lead + k * 18;
    o[0] = Lx; o[1] = Ly; o[2] = Lz;
    o[3] = e1x; o[4] = e1y; o[5] = e1z;
    o[6] = e2x; o[7] = e2y; o[8] = e2z;
    o[9]  = 0.282095f;
    o[10] = -0.488603f * Ly;
    o[11] = 0.488603f * Lz;
    o[12] = -0.488603f * Lx;
    o[13] = 1.092548f * Lx * Ly;
    o[14] = -1.092548f * Ly * Lz;
    o[15] = 0.315392f * (3.0f * Lz * Lz - 1.0f);
    o[16] = -1.092548f * Lx * Lz;
    o[17] = 0.546274f * (Lx * Lx - Ly * Ly);
}

// ---------------- kernel 1: splat rasterization ----------------
#define NC 32

__global__ __launch_bounds__(384) void splat_kernel(
    const float* __restrict__ mu, const float* __restrict__ sigma0,
    const float* __restrict__ sigma_vel, const float* __restrict__ amplitude,
    const float* __restrict__ sh_base, const float* __restrict__ sh_vel,
    const float* __restrict__ p0, const float* __restrict__ p_vel,
    const float* __restrict__ tau_raw, const float* __restrict__ gam_raw) {
    __shared__ float  sLead[KK][18];
    __shared__ float2 sAA[NC][KK];
    __shared__ float  sKu[NC][KK][9];
    __shared__ float  sKv[NC][KK][9];

    int t = blockIdx.x, b = blockIdx.y;
    int tid = threadIdx.x;
    if (tid < KK * 18) ((float*)sLead)[tid] = g_lead[tid];

    float tau = softplusf(tau_raw[0]) + 0.06f;
    float inv2tau2 = 0.5f / (tau * tau);
    float gamma = softplusf(gam_raw[0]) + 1e-6f;
    float tval = (float)t * (1.0f / (float)(TT - 1));
    const float DLT = 2.0f / 7.0f;
    float aD = inv2tau2 * DLT;
    float Cc = __expf(-2.0f * aD * DLT);   // exp recurrence constant

    int warp = tid >> 5, lane = tid & 31;
    int px0 = lane * 2;
    int hh = px0 >> 3, w0 = px0 & 7;
    float acc00 = 0.f, acc01 = 0.f, acc10 = 0.f, acc11 = 0.f;

    int nl = tid / KK, kk = tid - nl * KK;
    __syncthreads();

    for (int c = 0; c < NN / NC; ++c) {
        {
            int n = c * NC + nl;
            int bn = b * NN + n;
            float dt = tval - mu[bn];
            float sig = softplus_fast(sigma0[bn] + sigma_vel[bn] * dt) + 1e-3f;
            float z = dt * __fdividef(1.0f, sig);
            float gauss = amplitude[bn] * __expf(-0.5f * z * z);
            float prx = p0[bn * 3 + 0] + p_vel[bn * 3 + 0] * dt;
            float pry = p0[bn * 3 + 1] + p_vel[bn * 3 + 1] * dt;
            float prz = p0[bn * 3 + 2] + p_vel[bn * 3 + 2] * dt;
            float nrm = fmaxf(sqrtf(prx * prx + pry * pry + prz * prz), 1e-8f);
            float th = tanh_fast(nrm);
            float sc = th * __fdividef(1.0f, nrm);
            float ppx = prx * sc, ppy = pry * sc, ppz = prz * sc;
            const float* Ld = sLead[kk];
            float u = tanh_pade(ppx * Ld[3] + ppy * Ld[4] + ppz * Ld[5]);
            float v = tanh_pade(ppx * Ld[6] + ppy * Ld[7] + ppz * Ld[8]);
            float pn = fmaxf(th, 1e-8f);
            float cosl = (ppx * Ld[0] + ppy * Ld[1] + ppz * Ld[2]) * __fdividef(1.0f, pn);
            float hem = fmaxf(cosl, 0.0f);
            float ccv = fminf(fmaxf(cosl, -1.0f + 1e-6f), 1.0f - 1e-6f);
            float theta = acos_fast01(ccv);
            float weight = hem * __expf(-gamma * theta * theta);
            float A = gauss * weight;
            float shp = 0.0f;
            #pragma unroll
            for (int m = 0; m < 9; ++m)
                shp += (sh_base[bn * 9 + m] + sh_vel[bn * 9 + m] * dt) * Ld[9 + m];
            sAA[nl][kk] = make_float2(A, A * shp);
            // Gaussian grid via exp recurrence: 2 exp per axis instead of 8
            {
                float d0 = u + 1.0f;
                float Kx = __expf(-inv2tau2 * d0 * d0);
                float Rx = __expf(aD * (2.0f * d0 - DLT));
                #pragma unroll
                for (int g = 0; g < GG; ++g) { sKu[nl][kk][g] = Kx; Kx *= Rx; Rx *= Cc; }
                float d0v = v + 1.0f;
                float Kv2 = __expf(-inv2tau2 * d0v * d0v);
                float Rv = __expf(aD * (2.0f * d0v - DLT));
                #pragma unroll
                for (int g = 0; g < GG; ++g) { sKv[nl][kk][g] = Kv2; Kv2 *= Rv; Rv *= Cc; }
            }
        }
        __syncthreads();
        #pragma unroll 8
        for (int n2 = 0; n2 < NC; ++n2) {
            float2 aa = sAA[n2][warp];
            float kvh = sKv[n2][warp][hh];
            float ku0 = sKu[n2][warp][w0];
            float ku1 = sKu[n2][warp][w0 + 1];
            float tA = aa.x * kvh, tS = aa.y * kvh;
            acc00 = fmaf(tA, ku0, acc00);
            acc01 = fmaf(tA, ku1, acc01);
            acc10 = fmaf(tS, ku0, acc10);
            acc11 = fmaf(tS, ku1, acc11);
        }
        __syncthreads();
    }
    size_t base = ((size_t)((b * KK + warp) * TT + t)) * 128;
    g_splat[base + px0]          = acc00;
    g_splat[base + px0 + 1]      = acc01;
    g_splat[base + 64 + px0]     = acc10;
    g_splat[base + 64 + px0 + 1] = acc11;
}

// ---------------- kernel 2: PERSISTENT CNN, single-pass fp16 MMA ----
// 256 threads = 8 warps, 4 tiles per iteration, grid 296 (2 blocks/SM).
// smem float-index layout:
#define SM_RED   0       // 16
#define SM_B1    16      // 32
#define SM_B2    48      // 32
#define SM_FC    80      // 32
#define SM_FCB   112     // 1 (+3 pad)
#define SM_W1T   116     // 576
#define SM_IN    692     // [2 buf][4 tiles][2 ch][100] fp32 = 1600
#define SM_H1    2292    // [4 tiles][4 icg][100 px][8 ch] fp16 = 6400 f32
#define SM_BF    8692    // 4608 u32 (B fragments, uint2 per frag)
#define SMEM_FLOATS 13300
#define CNN_SMEM_BYTES (SMEM_FLOATS * 4)
#define QUADS (BB * KK * TT / 4)   // 6144
#define CNN_GRID 296

__global__ __launch_bounds__(256, 2) void cnn_kernel(
    const float* __restrict__ b1g, const float* __restrict__ b2g,
    const float* __restrict__ fcw, const float* __restrict__ fcb,
    float* __restrict__ out) {
    extern __shared__ float sm[];
    int tid = threadIdx.x;
    int warp = tid >> 5, lane = tid & 31;
    int tj = tid >> 6;               // tile 0..3 for conv1 pixel role
    int p = tid & 63;
    int x = p & 7, y = p >> 3;

    // ---- one-time staging: weights + zeroed padded planes (both IN bufs) ----
    for (int i = tid; i < 8000; i += 256) sm[SM_IN + i] = 0.0f;  // IN(2) + H1
    {
        float4* dst1 = (float4*)(sm + SM_W1T);
        const float4* src1 = (const float4*)g_w1T;
        for (int i = tid; i < 144; i += 256) dst1[i] = src1[i];
        float4* dbf = (float4*)(sm + SM_BF);
        const float4* sbf = (const float4*)g_bfrag;
        for (int i = tid; i < 1152; i += 256) dbf[i] = sbf[i];
    }
    if (tid < 32) {
        sm[SM_B1 + tid] = b1g[tid];
        sm[SM_B2 + tid] = b2g[tid];
        sm[SM_FC + tid] = fcw[tid];
    }
    if (tid == 0) sm[SM_FCB] = fcb[0];

    // IN staging geometry for this thread's two elements (i = tid, tid+256)
    int st_tt0 = tid >> 7, st_e0 = tid & 127;
    int st_ch0 = st_e0 >> 6, st_pp0 = st_e0 & 63;
    int st_dst0 = (st_tt0 * 2 + st_ch0) * 100 + ((st_pp0 >> 3) + 1) * 10 + (st_pp0 & 7) + 1;
    int i1 = tid + 256;
    int st_tt1 = i1 >> 7, st_e1 = i1 & 127;
    int st_ch1 = st_e1 >> 6, st_pp1 = st_e1 & 63;
    int st_dst1 = (st_tt1 * 2 + st_ch1) * 100 + ((st_pp1 >> 3) + 1) * 10 + (st_pp1 & 7) + 1;

    // conv2 warp geometry (fixed per thread)
    int wtj = warp >> 1, whalf = warp & 1;     // tile 0..3, half 0/1
    int mat = lane >> 3;
    int rl = ((mat & 1) << 3) | (lane & 7);
    int kseg = mat >> 1;
    uint32_t h1_addr = smem_u32(sm + SM_H1);
    int py0 = (whalf * 32 + rl) >> 3,       px0_ = (whalf * 32 + rl) & 7;
    int py1 = (whalf * 32 + 16 + rl) >> 3,  px1_ = (whalf * 32 + 16 + rl) & 7;
    const uint2* bfr2 = (const uint2*)(sm + SM_BF);
    __syncthreads();

    // ---- prologue: stage first quad into IN buf 0 ----
    int quad = blockIdx.x;
    {
        float r0 = g_splat[(size_t)quad * 512 + tid];
        float r1 = g_splat[(size_t)quad * 512 + tid + 256];
        sm[SM_IN + st_dst0] = r0;
        sm[SM_IN + st_dst1] = r1;
    }
    __syncthreads();
    int buf = 0;

    while (quad < QUADS) {
        int tile0 = quad * 4;
        int nq = quad + CNN_GRID;
        int inb = SM_IN + buf * 800;

        // ---- conv1 (2->32) via FFMA2; GELU; fp16 pack into H1 plane ----
        {
            u64 acc[16];
            #pragma unroll
            for (int q = 0; q < 16; ++q) acc[q] = ((const u64*)(sm + SM_B1))[q];
            #pragma unroll
            for (int c = 0; c < 2; ++c)
                #pragma unroll
                for (int r = 0; r < 3; ++r)
                    #pragma unroll
                    for (int q3 = 0; q3 < 3; ++q3) {
                        int j = c * 9 + r * 3 + q3;
                        u64 pa = pack2(sm[inb + (tj * 2 + c) * 100 + (y + r) * 10 + (x + q3)]);
                        const ulonglong2* wv = (const ulonglong2*)(sm + SM_W1T + j * 32);
                        #pragma unroll
                        for (int q = 0; q < 8; ++q) {
                            ulonglong2 w = wv[q];
                            ffma2(acc[2 * q], pa, w.x);
                            ffma2(acc[2 * q + 1], pa, w.y);
                        }
                    }
            int ppx = (y + 1) * 10 + (x + 1);
            uint4* h1w = (uint4*)(sm + SM_H1);
            #pragma unroll
            for (int icg = 0; icg < 4; ++icg) {
                uint32_t ph[4];
                #pragma unroll
                for (int qq = 0; qq < 4; ++qq) {
                    float lo, hi;
                    unpack2(lo, hi, acc[icg * 4 + qq]);
                    float g0 = gelu_fast(lo);
                    float g1 = gelu_fast(hi);
                    CVTPACK_F16(ph[qq], g0, g1);
                }
                h1w[(tj * 4 + icg) * 100 + ppx] = make_uint4(ph[0], ph[1], ph[2], ph[3]);
            }
        }

        // ---- prefetch next quad's splat data (latency hidden by conv2) ----
        float pf0 = 0.0f, pf1 = 0.0f;
        if (nq < QUADS) {
            pf0 = g_splat[(size_t)nq * 512 + tid];
            pf1 = g_splat[(size_t)nq * 512 + tid + 256];
        }
        __syncthreads();   // H1 plane ready

        // ---- conv2 GEMM via fp16 mma.sync, single pass ----
        float cacc[2][4][4];
        #pragma unroll
        for (int mt = 0; mt < 2; ++mt)
            #pragma unroll
            for (int n8 = 0; n8 < 4; ++n8)
                #pragma unroll
                for (int e = 0; e < 4; ++e) cacc[mt][n8][e] = 0.0f;

        #pragma unroll 1
        for (int j = 0; j < 9; ++j) {
            int dy2 = j / 3, dx2 = j - dy2 * 3;
            int pix0 = (py0 + dy2) * 10 + (px0_ + dx2);
            int pix1 = (py1 + dy2) * 10 + (px1_ + dx2);
            uint32_t ah[2][2][4];
            #pragma unroll
            for (int ksg = 0; ksg < 2; ++ksg) {
                int plane = (wtj * 4 + ksg * 2 + kseg) * 100;
                uint32_t a0 = h1_addr + (plane + pix0) * 16;
                uint32_t a1 = h1_addr + (plane + pix1) * 16;
                LDMATRIX_X4(ah[0][ksg][0], ah[0][ksg][1], ah[0][ksg][2], ah[0][ksg][3], a0);
                LDMATRIX_X4(ah[1][ksg][0], ah[1][ksg][1], ah[1][ksg][2], ah[1][ksg][3], a1);
            }
            // load all 8 B fragments for this j
            uint2 Bv[2][4];
            #pragma unroll
            for (int ksg = 0; ksg < 2; ++ksg)
                #pragma unroll
                for (int n8 = 0; n8 < 4; ++n8)
                    Bv[ksg][n8] = bfr2[((2 * j + ksg) * 4 + n8) * 32 + lane];
            #pragma unroll
            for (int ksg = 0; ksg < 2; ++ksg)
                #pragma unroll
                for (int n8 = 0; n8 < 4; ++n8) {
                    MMA16816(cacc[0][n8], ah[0][ksg], Bv[ksg][n8].x, Bv[ksg][n8].y);
                    MMA16816(cacc[1][n8], ah[1][ksg], Bv[ksg][n8].x, Bv[ksg][n8].y);
                }
        }

        // ---- epilogue: bias + GELU + fc dot, warp reduce ----
        float s = 0.0f;
        #pragma unroll
        for (int n8 = 0; n8 < 4; ++n8) {
            int oc0 = n8 * 8 + (lane & 3) * 2;
            float bb0 = sm[SM_B2 + oc0], bb1 = sm[SM_B2 + oc0 + 1];
            float ff0 = sm[SM_FC + oc0], ff1 = sm[SM_FC + oc0 + 1];
            #pragma unroll
            for (int mt = 0; mt < 2; ++mt) {
                s = fmaf(gelu_fast(cacc[mt][n8][0] + bb0), ff0, s);
                s = fmaf(gelu_fast(cacc[mt][n8][1] + bb1), ff1, s);
                s = fmaf(gelu_fast(cacc[mt][n8][2] + bb0), ff0, s);
                s = fmaf(gelu_fast(cacc[mt][n8][3] + bb1), ff1, s);
            }
        }
        #pragma unroll
        for (int off = 16; off > 0; off >>= 1)
            s += __shfl_xor_sync(0xffffffffu, s, off);
        if (lane == 0) sm[SM_RED + warp] = s;
        __syncthreads();   // RED ready; H1 reads done

        // stage next quad into the other IN buffer
        int onb = SM_IN + (buf ^ 1) * 800;
        sm[onb + st_dst0] = pf0;
        sm[onb + st_dst1] = pf1;

        if (tid < 4) {
            float v = sm[SM_RED + tid * 2] + sm[SM_RED + tid * 2 + 1];
            v = v * (1.0f / 64.0f) + sm[SM_FCB];
            int tile = tile0 + tid;
            int b = tile / (KK * TT);
            int rem = tile - b * (KK * TT);
            int k = rem / TT;
            int t = rem - k * TT;
            out[(b * TT + t) * KK + k] = v;
        }
        __syncthreads();   // IN[buf^1] ready; RED consumed
        buf ^= 1;
        quad = nq;
    }
}

// ---------------- launch ----------------
extern "C" void kernel_launch(void* const* d_in, const int* in_sizes, int n_in,
                              void* d_out, int out_size) {
    const float* mu        = (const float*)d_in[0];
    const float* sigma0    = (const float*)d_in[1];
    const float* sigma_vel = (const float*)d_in[2];
    const float* amplitude = (const float*)d_in[3];
    const float* sh_base   = (const float*)d_in[4];
    const float* sh_vel    = (const float*)d_in[5];
    const float* p0        = (const float*)d_in[6];
    const float* p_vel     = (const float*)d_in[7];
    const float* tau_raw   = (const float*)d_in[8];
    const float* gam_raw   = (const float*)d_in[9];
    const float* limb_ra   = (const float*)d_in[10];
    const float* limb_la   = (const float*)d_in[11];
    const float* limb_ll   = (const float*)d_in[12];
    const float* chest     = (const float*)d_in[13];
    const float* conv1_w   = (const float*)d_in[14];
    const float* conv1_b   = (const float*)d_in[15];
    const float* conv2_w   = (const float*)d_in[16];
    const float* conv2_b   = (const float*)d_in[17];
    const float* fc_w      = (const float*)d_in[18];
    const float* fc_b      = (const float*)d_in[19];
    float* out = (float*)d_out;

    prep_kernel<<<1, 256>>>(limb_ra, limb_la, limb_ll, chest, conv1_w, conv2_w);
    splat_kernel<<<dim3(TT, BB), 384>>>(mu, sigma0, sigma_vel, amplitude,
                                        sh_base, sh_vel, p0, p_vel, tau_raw, gam_raw);
    cudaFuncSetAttribute(cnn_kernel, cudaFuncAttributeMaxDynamicSharedMemorySize,
                         CNN_SMEM_BYTES);
    cnn_kernel<<<CNN_GRID, 256, CNN_SMEM_BYTES>>>(conv1_b, conv2_b, fc_w, fc_b, out);
}

// round 12
// speedup vs baseline: 3.2928x; 1.1041x over previous
#include <cuda_runtime.h>
#include <cuda_bf16.h>
#include <cuda_fp16.h>
#include <math.h>
#include <stdint.h>

// Problem dims (fixed by the dataset)
#define BB 4
#define NN 96
#define TT 512
#define KK 12
#define GG 8

typedef unsigned long long u64;

// ---------------- device scratch (no cudaMalloc allowed) ----------------
__device__ float g_lead[KK * 18];
__device__ float g_splat[(size_t)BB * KK * TT * 128];     // (B,K,T,2,8,8)
__device__ float g_w1T[576];                              // conv1 weights [c*9+j][oc]
// conv2 B fragments (single fp16): frag f = (ks*4+n8)*32+lane holds
// uint32s [2f, 2f+1] = {b_r0, b_r1}
__device__ __align__(16) uint32_t g_bfrag[4608];

// ---------------- small helpers ----------------
__device__ __forceinline__ u64 pack2(float x) {
    u64 r; asm("mov.b64 %0, {%1, %1};" : "=l"(r) : "f"(x)); return r;
}
__device__ __forceinline__ void ffma2(u64& d, u64 a, u64 b) {
    asm("fma.rn.f32x2 %0, %1, %2, %0;" : "+l"(d) : "l"(a), "l"(b));
}
__device__ __forceinline__ void unpack2(float& lo, float& hi, u64 v) {
    asm("mov.b64 {%0, %1}, %2;" : "=f"(lo), "=f"(hi) : "l"(v));
}
__device__ __forceinline__ float softplusf(float x) {
    return (x > 20.0f) ? x : log1pf(expf(x));
}
__device__ __forceinline__ float softplus_fast(float x) {
    return (x > 20.0f) ? x : __logf(1.0f + __expf(x));
}
__device__ __forceinline__ float tanh_fast(float x) {
    float xc = fminf(fmaxf(x, -15.0f), 15.0f);
    float t = __expf(2.0f * xc);
    return (t - 1.0f) * __fdividef(1.0f, t + 1.0f);
}
// Pade [5/4] tanh, valid |x|<=1 (args are dots of unit vectors with |p|<1)
__device__ __forceinline__ float tanh_pade(float x) {
    float x2 = x * x;
    float p = fmaf(fmaf(x2, 1.0f, 105.0f), x2, 945.0f);
    float q = fmaf(fmaf(15.0f, x2, 420.0f), x2, 945.0f);
    return __fdividef(x * p, q);
}
__device__ __forceinline__ float acos_fast01(float c) {
    float p = sqrtf(fmaxf(1.0f - c, 0.0f));
    float poly = fmaf(c, fmaf(c, fmaf(c, -0.0187293f, 0.0742610f), -0.2121144f), 1.5707288f);
    return p * poly;
}
// GELU via 3-term A&S erf (|eps| <= 2.5e-5); gelu = 0.5x + 0.5|x|*erf(|x|/sqrt2)
__device__ __forceinline__ float gelu_fast(float x) {
    float ax = fabsf(x);
    float z = ax * 0.70710678118f;
    float t = __fdividef(1.0f, fmaf(0.47047f, z, 1.0f));
    float poly = t * fmaf(t, fmaf(t, 0.7478556f, -0.0958798f), 0.3480242f);
    float e = __expf(-z * z);
    float erfv = fmaf(-poly, e, 1.0f);
    return fmaf(0.5f * ax, erfv, 0.5f * x);
}
__device__ __forceinline__ uint32_t smem_u32(const void* p) {
    uint32_t a;
    asm("{ .reg .u64 t; cvta.to.shared.u64 t, %1; cvt.u32.u64 %0, t; }" : "=r"(a) : "l"(p));
    return a;
}
// pack two f32 -> f16x2 (lo = a, hi = b)
#define CVTPACK_F16(r, a, b) \
    asm("cvt.rn.f16x2.f32 %0, %2, %1;" : "=r"(r) : "f"(a), "f"(b))
// ldmatrix x4 (A fragments)
#define LDMATRIX_X4(r0, r1, r2, r3, addr) \
    asm volatile("ldmatrix.sync.aligned.m8n8.x4.shared.b16 {%0,%1,%2,%3}, [%4];" \
                 : "=r"(r0), "=r"(r1), "=r"(r2), "=r"(r3) : "r"(addr))
// fp16 mma m16n8k16, C(f32) += A*B  (B passed as two b32 regs)
#define MMA16816(c, a, b0, b1) \
    asm volatile("mma.sync.aligned.m16n8k16.row.col.f32.f16.f16.f32 " \
                 "{%0,%1,%2,%3},{%4,%5,%6,%7},{%8,%9},{%0,%1,%2,%3};" \
                 : "+f"((c)[0]), "+f"((c)[1]), "+f"((c)[2]), "+f"((c)[3]) \
                 : "r"((a)[0]), "r"((a)[1]), "r"((a)[2]), "r"((a)[3]), \
                   "r"(b0), "r"(b1))

// ---------------- kernel 0: leads + conv1 transpose + conv2 B-fragments ----
__global__ void prep_kernel(const float* __restrict__ ra, const float* __restrict__ la,
                            const float* __restrict__ ll, const float* __restrict__ chest,
                            const float* __restrict__ w1, const float* __restrict__ w2) {
    int tid = threadIdx.x;
    // conv2 B fragments (single fp16), uint2 layout
    for (int i = tid; i < 4608; i += 256) {
        int r = i & 1;
        int f = i >> 1;
        int lane = f & 31;
        int n8 = (f >> 5) & 3;
        int ks = f >> 7;                 // 0..17
        int oc = n8 * 8 + (lane >> 2);
        int k0 = ks * 16 + (lane & 3) * 2 + r * 8;
        uint32_t pk = 0;
        #pragma unroll
        for (int e = 0; e < 2; ++e) {
            int k = k0 + e;
            int j = k / 32, ic = k % 32;
            float w = w2[oc * 288 + ic * 9 + j];
            unsigned short bits = __half_as_ushort(__float2half_rn(w));
            pk |= (uint32_t)bits << (16 * e);
        }
        g_bfrag[i] = pk;
    }
    for (int idx = tid; idx < 576; idx += 256) {
        int oc = idx / 18;
        int r = idx - oc * 18;
        g_w1T[r * 32 + oc] = w1[idx];
    }
    if (tid >= KK) return;
    int k = tid;
    float vx, vy, vz;
    float rax = ra[0], ray = ra[1], raz = ra[2];
    float lax = la[0], lay = la[1], laz = la[2];
    float llx = ll[0], lly = ll[1], llz = ll[2];
    switch (k) {
        case 0: vx = lax - rax; vy = lay - ray; vz = laz - raz; break;
        case 1: vx = llx - rax; vy = lly - ray; vz = llz - raz; break;
        case 2: vx = llx - lax; vy = lly - lay; vz = llz - laz; break;
        case 3: vx = rax - 0.5f * (lax + llx); vy = ray - 0.5f * (lay + lly); vz = raz - 0.5f * (laz + llz); break;
        case 4: vx = lax - 0.5f * (rax + llx); vy = lay - 0.5f * (ray + lly); vz = laz - 0.5f * (raz + llz); break;
        case 5: vx = llx - 0.5f * (rax + lax); vy = lly - 0.5f * (ray + lay); vz = llz - 0.5f * (raz + laz); break;
        default:
            vx = chest[(k - 6) * 3 + 0]; vy = chest[(k - 6) * 3 + 1]; vz = chest[(k - 6) * 3 + 2];
            break;
    }
    float n = sqrtf(vx * vx + vy * vy + vz * vz);
    float d = fmaxf(n, 1e-6f);
    float Lx = vx / d, Ly = vy / d, Lz = vz / d;
    float e1x = 0.0f, e1y = Lz, e1z = -Ly;
    float n1 = sqrtf(e1y * e1y + e1z * e1z);
    if (n1 < 1e-4f) { e1x = -Lz; e1y = 0.0f; e1z = Lx; n1 = sqrtf(e1x * e1x + e1z * e1z); }
    float d1 = fmaxf(n1, 1e-6f);
    e1x /= d1; e1y /= d1; e1z /= d1;
    float e2x = e1y * Lz - e1z * Ly;
    float e2y = e1z * Lx - e1x * Lz;
    float e2z = e1x * Ly - e1y * Lx;
    float n2 = sqrtf(e2x * e2x + e2y * e2y + e2z * e2z);
    float d2 = fmaxf(n2, 1e-6f);
    e2x /= d2; e2y /= d2; e2z /= d2;
    float* o = g_lead + k * 18;
    o[0] = Lx; o[1] = Ly; o[2] = Lz;
    o[3] = e1x; o[4] = e1y; o[5] = e1z;
    o[6] = e2x; o[7] = e2y; o[8] = e2z;
    o[9]  = 0.282095f;
    o[10] = -0.488603f * Ly;
    o[11] = 0.488603f * Lz;
    o[12] = -0.488603f * Lx;
    o[13] = 1.092548f * Lx * Ly;
    o[14] = -1.092548f * Ly * Lz;
    o[15] = 0.315392f * (3.0f * Lz * Lz - 1.0f);
    o[16] = -1.092548f * Lx * Lz;
    o[17] = 0.546274f * (Lx * Lx - Ly * Ly);
}

// ---------------- kernel 1: splat rasterization (per-n work hoisted) --------
#define NC 32

__global__ __launch_bounds__(384) void splat_kernel(
    const float* __restrict__ mu, const float* __restrict__ sigma0,
    const float* __restrict__ sigma_vel, const float* __restrict__ amplitude,
    const float* __restrict__ sh_base, const float* __restrict__ sh_vel,
    const float* __restrict__ p0, const float* __restrict__ p_vel,
    const float* __restrict__ tau_raw, const float* __restrict__ gam_raw) {
    __shared__ float  sLead[KK][18];
    __shared__ float  sPN[NN][16];        // {gauss, ppx, ppy, ppz, invpn, sh_dyn[9]}
    __shared__ float2 sAA[NC][KK];
    __shared__ float  sKu[NC][KK][9];
    __shared__ float  sKv[NC][KK][9];

    int t = blockIdx.x, b = blockIdx.y;
    int tid = threadIdx.x;
    if (tid < KK * 18) ((float*)sLead)[tid] = g_lead[tid];

    float tau = softplusf(tau_raw[0]) + 0.06f;
    float inv2tau2 = 0.5f / (tau * tau);
    float gamma = softplusf(gam_raw[0]) + 1e-6f;
    float tval = (float)t * (1.0f / (float)(TT - 1));
    const float DLT = 2.0f / 7.0f;
    float aD = inv2tau2 * DLT;
    float Cc = __expf(-2.0f * aD * DLT);   // exp recurrence constant

    // ---- phase 0: per-n quantities, computed ONCE (96 threads) ----
    if (tid < NN) {
        int bn = b * NN + tid;
        float dt = tval - mu[bn];
        float sig = softplus_fast(sigma0[bn] + sigma_vel[bn] * dt) + 1e-3f;
        float z = dt * __fdividef(1.0f, sig);
        float gauss = amplitude[bn] * __expf(-0.5f * z * z);
        float prx = p0[bn * 3 + 0] + p_vel[bn * 3 + 0] * dt;
        float pry = p0[bn * 3 + 1] + p_vel[bn * 3 + 1] * dt;
        float prz = p0[bn * 3 + 2] + p_vel[bn * 3 + 2] * dt;
        float nrm = fmaxf(sqrtf(prx * prx + pry * pry + prz * prz), 1e-8f);
        float th = tanh_fast(nrm);
        float sc = th * __fdividef(1.0f, nrm);
        float* o = sPN[tid];
        o[0] = gauss;
        o[1] = prx * sc;
        o[2] = pry * sc;
        o[3] = prz * sc;
        o[4] = __fdividef(1.0f, fmaxf(th, 1e-8f));
        #pragma unroll
        for (int m = 0; m < 9; ++m)
            o[5 + m] = fmaf(sh_vel[bn * 9 + m], dt, sh_base[bn * 9 + m]);
    }

    int warp = tid >> 5, lane = tid & 31;
    int px0 = lane * 2;
    int hh = px0 >> 3, w0 = px0 & 7;
    float acc00 = 0.f, acc01 = 0.f, acc10 = 0.f, acc11 = 0.f;

    int nl = tid / KK, kk = tid - nl * KK;
    __syncthreads();

    for (int c = 0; c < NN / NC; ++c) {
        // ---- phase 1: per-(n,k) ----
        {
            int n = c * NC + nl;
            const float* pn = sPN[n];
            const float* Ld = sLead[kk];
            float gauss = pn[0], ppx = pn[1], ppy = pn[2], ppz = pn[3], invpn = pn[4];
            float u = tanh_pade(ppx * Ld[3] + ppy * Ld[4] + ppz * Ld[5]);
            float v = tanh_pade(ppx * Ld[6] + ppy * Ld[7] + ppz * Ld[8]);
            float cosl = (ppx * Ld[0] + ppy * Ld[1] + ppz * Ld[2]) * invpn;
            float hem = fmaxf(cosl, 0.0f);
            float ccv = fminf(fmaxf(cosl, -1.0f + 1e-6f), 1.0f - 1e-6f);
            float theta = acos_fast01(ccv);
            float weight = hem * __expf(-gamma * theta * theta);
            float A = gauss * weight;
            float shp = 0.0f;
            #pragma unroll
            for (int m = 0; m < 9; ++m)
                shp = fmaf(pn[5 + m], Ld[9 + m], shp);
            sAA[nl][kk] = make_float2(A, A * shp);
            // Gaussian grid via exp recurrence: 2 exp per axis
            {
                float d0 = u + 1.0f;
                float Kx = __expf(-inv2tau2 * d0 * d0);
                float Rx = __expf(aD * (2.0f * d0 - DLT));
                #pragma unroll
                for (int g = 0; g < GG; ++g) { sKu[nl][kk][g] = Kx; Kx *= Rx; Rx *= Cc; }
                float d0v = v + 1.0f;
                float Kv2 = __expf(-inv2tau2 * d0v * d0v);
                float Rv = __expf(aD * (2.0f * d0v - DLT));
                #pragma unroll
                for (int g = 0; g < GG; ++g) { sKv[nl][kk][g] = Kv2; Kv2 *= Rv; Rv *= Cc; }
            }
        }
        __syncthreads();
        #pragma unroll 8
        for (int n2 = 0; n2 < NC; ++n2) {
            float2 aa = sAA[n2][warp];
            float kvh = sKv[n2][warp][hh];
            float ku0 = sKu[n2][warp][w0];
            float ku1 = sKu[n2][warp][w0 + 1];
            float tA = aa.x * kvh, tS = aa.y * kvh;
            acc00 = fmaf(tA, ku0, acc00);
            acc01 = fmaf(tA, ku1, acc01);
            acc10 = fmaf(tS, ku0, acc10);
            acc11 = fmaf(tS, ku1, acc11);
        }
        __syncthreads();
    }
    size_t base = ((size_t)((b * KK + warp) * TT + t)) * 128;
    g_splat[base + px0]          = acc00;
    g_splat[base + px0 + 1]      = acc01;
    g_splat[base + 64 + px0]     = acc10;
    g_splat[base + 64 + px0 + 1] = acc11;
}

// ---------------- kernel 2: PERSISTENT CNN, single-pass fp16 MMA, occ 3 ----
// 256 threads = 8 warps, 4 tiles per iteration, grid 444 (3 blocks/SM).
// smem float-index layout:
#define SM_RED   0       // 16
#define SM_B1    16      // 32
#define SM_B2    48      // 32
#define SM_FC    80      // 32
#define SM_FCB   112     // 1 (+3 pad)
#define SM_W1T   116     // 576
#define SM_IN    692     // [2 buf][4 tiles][2 ch][100] fp32 = 1600
#define SM_H1    2292    // [4 tiles][4 icg][100 px][8 ch] fp16 = 6400 f32
#define SM_BF    8692    // 4608 u32 (B fragments, uint2 per frag)
#define SMEM_FLOATS 13300
#define CNN_SMEM_BYTES (SMEM_FLOATS * 4)
#define QUADS (BB * KK * TT / 4)   // 6144
#define CNN_GRID 444

__global__ __launch_bounds__(256, 3) void cnn_kernel(
    const float* __restrict__ b1g, const float* __restrict__ b2g,
    const float* __restrict__ fcw, const float* __restrict__ fcb,
    float* __restrict__ out) {
    extern __shared__ float sm[];
    int tid = threadIdx.x;
    int warp = tid >> 5, lane = tid & 31;
    int tj = tid >> 6;               // tile 0..3 for conv1 pixel role
    int p = tid & 63;
    int x = p & 7, y = p >> 3;

    // ---- one-time staging: weights + zeroed padded planes (both IN bufs) ----
    for (int i = tid; i < 8000; i += 256) sm[SM_IN + i] = 0.0f;  // IN(2) + H1
    {
        float4* dst1 = (float4*)(sm + SM_W1T);
        const float4* src1 = (const float4*)g_w1T;
        for (int i = tid; i < 144; i += 256) dst1[i] = src1[i];
        float4* dbf = (float4*)(sm + SM_BF);
        const float4* sbf = (const float4*)g_bfrag;
        for (int i = tid; i < 1152; i += 256) dbf[i] = sbf[i];
    }
    if (tid < 32) {
        sm[SM_B1 + tid] = b1g[tid];
        sm[SM_B2 + tid] = b2g[tid];
        sm[SM_FC + tid] = fcw[tid];
    }
    if (tid == 0) sm[SM_FCB] = fcb[0];

    // IN staging geometry for this thread's two elements (i = tid, tid+256)
    int st_tt0 = tid >> 7, st_e0 = tid & 127;
    int st_ch0 = st_e0 >> 6, st_pp0 = st_e0 & 63;
    int st_dst0 = (st_tt0 * 2 + st_ch0) * 100 + ((st_pp0 >> 3) + 1) * 10 + (st_pp0 & 7) + 1;
    int i1 = tid + 256;
    int st_tt1 = i1 >> 7, st_e1 = i1 & 127;
    int st_ch1 = st_e1 >> 6, st_pp1 = st_e1 & 63;
    int st_dst1 = (st_tt1 * 2 + st_ch1) * 100 + ((st_pp1 >> 3) + 1) * 10 + (st_pp1 & 7) + 1;

    // conv2 warp geometry (fixed per thread)
    int wtj = warp >> 1, whalf = warp & 1;     // tile 0..3, half 0/1
    int mat = lane >> 3;
    int rl = ((mat & 1) << 3) | (lane & 7);
    int kseg = mat >> 1;
    uint32_t h1_addr = smem_u32(sm + SM_H1);
    int py0 = (whalf * 32 + rl) >> 3,       px0_ = (whalf * 32 + rl) & 7;
    int py1 = (whalf * 32 + 16 + rl) >> 3,  px1_ = (whalf * 32 + 16 + rl) & 7;
    const uint2* bfr2 = (const uint2*)(sm + SM_BF);
    __syncthreads();

    // ---- prologue: stage first quad into IN buf 0 ----
    int quad = blockIdx.x;
    if (quad < QUADS) {
        float r0 = g_splat[(size_t)quad * 512 + tid];
        float r1 = g_splat[(size_t)quad * 512 + tid + 256];
        sm[SM_IN + st_dst0] = r0;
        sm[SM_IN + st_dst1] = r1;
    }
    __syncthreads();
    int buf = 0;

    while (quad < QUADS) {
        int tile0 = quad * 4;
        int nq = quad + CNN_GRID;
        int inb = SM_IN + buf * 800;

        // ---- conv1 (2->32) via FFMA2; GELU; fp16 pack into H1 plane ----
        {
            u64 acc[16];
            #pragma unroll
            for (int q = 0; q < 16; ++q) acc[q] = ((const u64*)(sm + SM_B1))[q];
            #pragma unroll
            for (int c = 0; c < 2; ++c)
                #pragma unroll
                for (int r = 0; r < 3; ++r)
                    #pragma unroll
                    for (int q3 = 0; q3 < 3; ++q3) {
                        int j = c * 9 + r * 3 + q3;
                        u64 pa = pack2(sm[inb + (tj * 2 + c) * 100 + (y + r) * 10 + (x + q3)]);
                        const ulonglong2* wv = (const ulonglong2*)(sm + SM_W1T + j * 32);
                        #pragma unroll
                        for (int q = 0; q < 8; ++q) {
                            ulonglong2 w = wv[q];
                            ffma2(acc[2 * q], pa, w.x);
                            ffma2(acc[2 * q + 1], pa, w.y);
                        }
                    }
            int ppx = (y + 1) * 10 + (x + 1);
            uint4* h1w = (uint4*)(sm + SM_H1);
            #pragma unroll
            for (int icg = 0; icg < 4; ++icg) {
                uint32_t ph[4];
                #pragma unroll
                for (int qq = 0; qq < 4; ++qq) {
                    float lo, hi;
                    unpack2(lo, hi, acc[icg * 4 + qq]);
                    float g0 = gelu_fast(lo);
                    float g1 = gelu_fast(hi);
                    CVTPACK_F16(ph[qq], g0, g1);
                }
                h1w[(tj * 4 + icg) * 100 + ppx] = make_uint4(ph[0], ph[1], ph[2], ph[3]);
            }
        }

        // ---- prefetch next quad's splat data (latency hidden by conv2) ----
        float pf0 = 0.0f, pf1 = 0.0f;
        if (nq < QUADS) {
            pf0 = g_splat[(size_t)nq * 512 + tid];
            pf1 = g_splat[(size_t)nq * 512 + tid + 256];
        }
        __syncthreads();   // H1 plane ready

        // ---- conv2 GEMM via fp16 mma.sync, single pass ----
        float cacc[2][4][4];
        #pragma unroll
        for (int mt = 0; mt < 2; ++mt)
            #pragma unroll
            for (int n8 = 0; n8 < 4; ++n8)
                #pragma unroll
                for (int e = 0; e < 4; ++e) cacc[mt][n8][e] = 0.0f;

        #pragma unroll 1
        for (int j = 0; j < 9; ++j) {
            int dy2 = j / 3, dx2 = j - dy2 * 3;
            int pix0 = (py0 + dy2) * 10 + (px0_ + dx2);
            int pix1 = (py1 + dy2) * 10 + (px1_ + dx2);
            #pragma unroll
            for (int ksg = 0; ksg < 2; ++ksg) {
                uint32_t ah0[4], ah1[4];
                int plane = (wtj * 4 + ksg * 2 + kseg) * 100;
                uint32_t a0 = h1_addr + (plane + pix0) * 16;
                uint32_t a1 = h1_addr + (plane + pix1) * 16;
                LDMATRIX_X4(ah0[0], ah0[1], ah0[2], ah0[3], a0);
                LDMATRIX_X4(ah1[0], ah1[1], ah1[2], ah1[3], a1);
                #pragma unroll
                for (int n8 = 0; n8 < 4; ++n8) {
                    uint2 Bv = bfr2[((2 * j + ksg) * 4 + n8) * 32 + lane];
                    MMA16816(cacc[0][n8], ah0, Bv.x, Bv.y);
                    MMA16816(cacc[1][n8], ah1, Bv.x, Bv.y);
                }
            }
        }

        // ---- epilogue: bias + GELU + fc dot, warp reduce ----
        float s = 0.0f;
        #pragma unroll
        for (int n8 = 0; n8 < 4; ++n8) {
            int oc0 = n8 * 8 + (lane & 3) * 2;
            float bb0 = sm[SM_B2 + oc0], bb1 = sm[SM_B2 + oc0 + 1];
            float ff0 = sm[SM_FC + oc0], ff1 = sm[SM_FC + oc0 + 1];
            #pragma unroll
            for (int mt = 0; mt < 2; ++mt) {
                s = fmaf(gelu_fast(cacc[mt][n8][0] + bb0), ff0, s);
                s = fmaf(gelu_fast(cacc[mt][n8][1] + bb1), ff1, s);
                s = fmaf(gelu_fast(cacc[mt][n8][2] + bb0), ff0, s);
                s = fmaf(gelu_fast(cacc[mt][n8][3] + bb1), ff1, s);
            }
        }
        #pragma unroll
        for (int off = 16; off > 0; off >>= 1)
            s += __shfl_xor_sync(0xffffffffu, s, off);
        if (lane == 0) sm[SM_RED + warp] = s;
        __syncthreads();   // RED ready; H1 reads done

        // stage next quad into the other IN buffer
        int onb = SM_IN + (buf ^ 1) * 800;
        sm[onb + st_dst0] = pf0;
        sm[onb + st_dst1] = pf1;

        if (tid < 4) {
            float v = sm[SM_RED + tid * 2] + sm[SM_RED + tid * 2 + 1];
            v = v * (1.0f / 64.0f) + sm[SM_FCB];
            int tile = tile0 + tid;
            int b = tile / (KK * TT);
            int rem = tile - b * (KK * TT);
            int k = rem / TT;
            int t = rem - k * TT;
            out[(b * TT + t) * KK + k] = v;
        }
        __syncthreads();   // IN[buf^1] ready; RED consumed
        buf ^= 1;
        quad = nq;
    }
}

// ---------------- launch ----------------
extern "C" void kernel_launch(void* const* d_in, const int* in_sizes, int n_in,
                              void* d_out, int out_size) {
    const float* mu        = (const float*)d_in[0];
    const float* sigma0    = (const float*)d_in[1];
    const float* sigma_vel = (const float*)d_in[2];
    const float* amplitude = (const float*)d_in[3];
    const float* sh_base   = (const float*)d_in[4];
    const float* sh_vel    = (const float*)d_in[5];
    const float* p0        = (const float*)d_in[6];
    const float* p_vel     = (const float*)d_in[7];
    const float* tau_raw   = (const float*)d_in[8];
    const float* gam_raw   = (const float*)d_in[9];
    const float* limb_ra   = (const float*)d_in[10];
    const float* limb_la   = (const float*)d_in[11];
    const float* limb_ll   = (const float*)d_in[12];
    const float* chest     = (const float*)d_in[13];
    const float* conv1_w   = (const float*)d_in[14];
    const float* conv1_b   = (const float*)d_in[15];
    const float* conv2_w   = (const float*)d_in[16];
    const float* conv2_b   = (const float*)d_in[17];
    const float* fc_w      = (const float*)d_in[18];
    const float* fc_b      = (const float*)d_in[19];
    float* out = (float*)d_out;

    prep_kernel<<<1, 256>>>(limb_ra, limb_la, limb_ll, chest, conv1_w, conv2_w);
    splat_kernel<<<dim3(TT, BB), 384>>>(mu, sigma0, sigma_vel, amplitude,
                                        sh_base, sh_vel, p0, p_vel, tau_raw, gam_raw);
    cudaFuncSetAttribute(cnn_kernel, cudaFuncAttributeMaxDynamicSharedMemorySize,
                         CNN_SMEM_BYTES);
    cnn_kernel<<<CNN_GRID, 256, CNN_SMEM_BYTES>>>(conv1_b, conv2_b, fc_w, fc_b, out);
}

// round 13
// speedup vs baseline: 3.7826x; 1.1487x over previous
#include <cuda_runtime.h>
#include <cuda_bf16.h>
#include <cuda_fp16.h>
#include <math.h>
#include <stdint.h>

// Problem dims (fixed by the dataset)
#define BB 4
#define NN 96
#define TT 512
#define KK 12
#define GG 8

typedef unsigned long long u64;

// ---------------- device scratch (no cudaMalloc allowed) ----------------
__device__ float g_lead[KK * 18];
__device__ float g_splat[(size_t)BB * KK * TT * 128];     // (B,K,T,2,8,8)
// conv2 B fragments (single fp16): frag f = (ks*4+n8)*32+lane holds
// uint32s [2f, 2f+1] = {b_r0, b_r1}
__device__ __align__(16) uint32_t g_bfrag[4608];
// conv1 B fragments (fp16, K=18 padded to 32): frag f = (ks*4+n8)*32+lane
__device__ __align__(16) uint32_t g_b1frag[1024];

// ---------------- small helpers ----------------
__device__ __forceinline__ float softplusf(float x) {
    return (x > 20.0f) ? x : log1pf(expf(x));
}
__device__ __forceinline__ float softplus_fast(float x) {
    return (x > 20.0f) ? x : __logf(1.0f + __expf(x));
}
__device__ __forceinline__ float tanh_fast(float x) {
    float xc = fminf(fmaxf(x, -15.0f), 15.0f);
    float t = __expf(2.0f * xc);
    return (t - 1.0f) * __fdividef(1.0f, t + 1.0f);
}
// Pade [5/4] tanh, valid |x|<=1 (args are dots of unit vectors with |p|<1)
__device__ __forceinline__ float tanh_pade(float x) {
    float x2 = x * x;
    float p = fmaf(fmaf(x2, 1.0f, 105.0f), x2, 945.0f);
    float q = fmaf(fmaf(15.0f, x2, 420.0f), x2, 945.0f);
    return __fdividef(x * p, q);
}
__device__ __forceinline__ float acos_fast01(float c) {
    float p = sqrtf(fmaxf(1.0f - c, 0.0f));
    float poly = fmaf(c, fmaf(c, fmaf(c, -0.0187293f, 0.0742610f), -0.2121144f), 1.5707288f);
    return p * poly;
}
// GELU via 3-term A&S erf (|eps| <= 2.5e-5); gelu = 0.5x + 0.5|x|*erf(|x|/sqrt2)
__device__ __forceinline__ float gelu_fast(float x) {
    float ax = fabsf(x);
    float z = ax * 0.70710678118f;
    float t = __fdividef(1.0f, fmaf(0.47047f, z, 1.0f));
    float poly = t * fmaf(t, fmaf(t, 0.7478556f, -0.0958798f), 0.3480242f);
    float e = __expf(-z * z);
    float erfv = fmaf(-poly, e, 1.0f);
    return fmaf(0.5f * ax, erfv, 0.5f * x);
}
__device__ __forceinline__ uint32_t smem_u32(const void* p) {
    uint32_t a;
    asm("{ .reg .u64 t; cvta.to.shared.u64 t, %1; cvt.u32.u64 %0, t; }" : "=r"(a) : "l"(p));
    return a;
}
// pack two f32 -> f16x2 (lo = a, hi = b)
#define CVTPACK_F16(r, a, b) \
    asm("cvt.rn.f16x2.f32 %0, %2, %1;" : "=r"(r) : "f"(a), "f"(b))
// ldmatrix x4 (A fragments)
#define LDMATRIX_X4(r0, r1, r2, r3, addr) \
    asm volatile("ldmatrix.sync.aligned.m8n8.x4.shared.b16 {%0,%1,%2,%3}, [%4];" \
                 : "=r"(r0), "=r"(r1), "=r"(r2), "=r"(r3) : "r"(addr))
// fp16 mma m16n8k16, C(f32) += A*B  (B passed as two b32 regs)
#define MMA16816(c, a, b0, b1) \
    asm volatile("mma.sync.aligned.m16n8k16.row.col.f32.f16.f16.f32 " \
                 "{%0,%1,%2,%3},{%4,%5,%6,%7},{%8,%9},{%0,%1,%2,%3};" \
                 : "+f"((c)[0]), "+f"((c)[1]), "+f"((c)[2]), "+f"((c)[3]) \
                 : "r"((a)[0]), "r"((a)[1]), "r"((a)[2]), "r"((a)[3]), \
                   "r"(b0), "r"(b1))

// ---------------- kernel 0: leads + conv2/conv1 B-fragments ----------------
__global__ void prep_kernel(const float* __restrict__ ra, const float* __restrict__ la,
                            const float* __restrict__ ll, const float* __restrict__ chest,
                            const float* __restrict__ w1, const float* __restrict__ w2) {
    int tid = threadIdx.x;
    // conv2 B fragments (single fp16), uint2 layout; GEMM k = j*32 + ic
    for (int i = tid; i < 4608; i += 256) {
        int r = i & 1;
        int f = i >> 1;
        int lane = f & 31;
        int n8 = (f >> 5) & 3;
        int ks = f >> 7;                 // 0..17
        int oc = n8 * 8 + (lane >> 2);
        int k0 = ks * 16 + (lane & 3) * 2 + r * 8;
        uint32_t pk = 0;
        #pragma unroll
        for (int e = 0; e < 2; ++e) {
            int k = k0 + e;
            int j = k / 32, ic = k % 32;
            float w = w2[oc * 288 + ic * 9 + j];
            unsigned short bits = __half_as_ushort(__float2half_rn(w));
            pk |= (uint32_t)bits << (16 * e);
        }
        g_bfrag[i] = pk;
    }
    // conv1 B fragments: GEMM k = c*9 + j (18 real, pad to 32 with zeros)
    for (int i = tid; i < 1024; i += 256) {
        int r = i & 1;
        int f = i >> 1;
        int lane = f & 31;
        int n8 = (f >> 5) & 3;
        int ks = f >> 7;                 // 0..1
        int oc = n8 * 8 + (lane >> 2);
        int k0 = ks * 16 + (lane & 3) * 2 + r * 8;
        uint32_t pk = 0;
        #pragma unroll
        for (int e = 0; e < 2; ++e) {
            int k = k0 + e;
            float w = (k < 18) ? w1[oc * 18 + k] : 0.0f;
            unsigned short bits = __half_as_ushort(__float2half_rn(w));
            pk |= (uint32_t)bits << (16 * e);
        }
        g_b1frag[i] = pk;
    }
    if (tid >= KK) return;
    int k = tid;
    float vx, vy, vz;
    float rax = ra[0], ray = ra[1], raz = ra[2];
    float lax = la[0], lay = la[1], laz = la[2];
    float llx = ll[0], lly = ll[1], llz = ll[2];
    switch (k) {
        case 0: vx = lax - rax; vy = lay - ray; vz = laz - raz; break;
        case 1: vx = llx - rax; vy = lly - ray; vz = llz - raz; break;
        case 2: vx = llx - lax; vy = lly - lay; vz = llz - laz; break;
        case 3: vx = rax - 0.5f * (lax + llx); vy = ray - 0.5f * (lay + lly); vz = raz - 0.5f * (laz + llz); break;
        case 4: vx = lax - 0.5f * (rax + llx); vy = lay - 0.5f * (ray + lly); vz = laz - 0.5f * (raz + llz); break;
        case 5: vx = llx - 0.5f * (rax + lax); vy = lly - 0.5f * (ray + lay); vz = llz - 0.5f * (raz + laz); break;
        default:
            vx = chest[(k - 6) * 3 + 0]; vy = chest[(k - 6) * 3 + 1]; vz = chest[(k - 6) * 3 + 2];
            break;
    }
    float n = sqrtf(vx * vx + vy * vy + vz * vz);
    float d = fmaxf(n, 1e-6f);
    float Lx = vx / d, Ly = vy / d, Lz = vz / d;
    float e1x = 0.0f, e1y = Lz, e1z = -Ly;
    float n1 = sqrtf(e1y * e1y + e1z * e1z);
    if (n1 < 1e-4f) { e1x = -Lz; e1y = 0.0f; e1z = Lx; n1 = sqrtf(e1x * e1x + e1z * e1z); }
    float d1 = fmaxf(n1, 1e-6f);
    e1x /= d1; e1y /= d1; e1z /= d1;
    float e2x = e1y * Lz - e1z * Ly;
    float e2y = e1z * Lx - e1x * Lz;
    float e2z = e1x * Ly - e1y * Lx;
    float n2 = sqrtf(e2x * e2x + e2y * e2y + e2z * e2z);
    float d2 = fmaxf(n2, 1e-6f);
    e2x /= d2; e2y /= d2; e2z /= d2;
    float* o = g_lead + k * 18;
    o[0] = Lx; o[1] = Ly; o[2] = Lz;
    o[3] = e1x; o[4] = e1y; o[5] = e1z;
    o[6] = e2x; o[7] = e2y; o[8] = e2z;
    o[9]  = 0.282095f;
    o[10] = -0.488603f * Ly;
    o[11] = 0.488603f * Lz;
    o[12] = -0.488603f * Lx;
    o[13] = 1.092548f * Lx * Ly;
    o[14] = -1.092548f * Ly * Lz;
    o[15] = 0.315392f * (3.0f * Lz * Lz - 1.0f);
    o[16] = -1.092548f * Lx * Lz;
    o[17] = 0.546274f * (Lx * Lx - Ly * Ly);
}

// ---------------- kernel 1: splat rasterization (per-n work hoisted) --------
#define NC 32

__global__ __launch_bounds__(384) void splat_kernel(
    const float* __restrict__ mu, const float* __restrict__ sigma0,
    const float* __restrict__ sigma_vel, const float* __restrict__ amplitude,
    const float* __restrict__ sh_base, const float* __restrict__ sh_vel,
    const float* __restrict__ p0, const float* __restrict__ p_vel,
    const float* __restrict__ tau_raw, const float* __restrict__ gam_raw) {
    __shared__ float  sLead[KK][18];
    __shared__ float  sPN[NN][16];        // {gauss, ppx, ppy, ppz, invpn, sh_dyn[9]}
    __shared__ float2 sAA[NC][KK];
    __shared__ float  sKu[NC][KK][9];
    __shared__ float  sKv[NC][KK][9];

    int t = blockIdx.x, b = blockIdx.y;
    int tid = threadIdx.x;
    if (tid < KK * 18) ((float*)sLead)[tid] = g_lead[tid];

    float tau = softplusf(tau_raw[0]) + 0.06f;
    float inv2tau2 = 0.5f / (tau * tau);
    float gamma = softplusf(gam_raw[0]) + 1e-6f;
    float tval = (float)t * (1.0f / (float)(TT - 1));
    const float DLT = 2.0f / 7.0f;
    float aD = inv2tau2 * DLT;
    float Cc = __expf(-2.0f * aD * DLT);   // exp recurrence constant

    // ---- phase 0: per-n quantities, computed ONCE (96 threads) ----
    if (tid < NN) {
        int bn = b * NN + tid;
        float dt = tval - mu[bn];
        float sig = softplus_fast(sigma0[bn] + sigma_vel[bn] * dt) + 1e-3f;
        float z = dt * __fdividef(1.0f, sig);
        float gauss = amplitude[bn] * __expf(-0.5f * z * z);
        float prx = p0[bn * 3 + 0] + p_vel[bn * 3 + 0] * dt;
        float pry = p0[bn * 3 + 1] + p_vel[bn * 3 + 1] * dt;
        float prz = p0[bn * 3 + 2] + p_vel[bn * 3 + 2] * dt;
        float nrm = fmaxf(sqrtf(prx * prx + pry * pry + prz * prz), 1e-8f);
        float th = tanh_fast(nrm);
        float sc = th * __fdividef(1.0f, nrm);
        float* o = sPN[tid];
        o[0] = gauss;
        o[1] = prx * sc;
        o[2] = pry * sc;
        o[3] = prz * sc;
        o[4] = __fdividef(1.0f, fmaxf(th, 1e-8f));
        #pragma unroll
        for (int m = 0; m < 9; ++m)
            o[5 + m] = fmaf(sh_vel[bn * 9 + m], dt, sh_base[bn * 9 + m]);
    }

    int warp = tid >> 5, lane = tid & 31;
    int px0 = lane * 2;
    int hh = px0 >> 3, w0 = px0 & 7;
    float acc00 = 0.f, acc01 = 0.f, acc10 = 0.f, acc11 = 0.f;

    int nl = tid / KK, kk = tid - nl * KK;
    __syncthreads();

    for (int c = 0; c < NN / NC; ++c) {
        // ---- phase 1: per-(n,k) ----
        {
            int n = c * NC + nl;
            const float* pn = sPN[n];
            const float* Ld = sLead[kk];
            float gauss = pn[0], ppx = pn[1], ppy = pn[2], ppz = pn[3], invpn = pn[4];
            float u = tanh_pade(ppx * Ld[3] + ppy * Ld[4] + ppz * Ld[5]);
            float v = tanh_pade(ppx * Ld[6] + ppy * Ld[7] + ppz * Ld[8]);
            float cosl = (ppx * Ld[0] + ppy * Ld[1] + ppz * Ld[2]) * invpn;
            float hem = fmaxf(cosl, 0.0f);
            float ccv = fminf(fmaxf(cosl, -1.0f + 1e-6f), 1.0f - 1e-6f);
            float theta = acos_fast01(ccv);
            float weight = hem * __expf(-gamma * theta * theta);
            float A = gauss * weight;
            float shp = 0.0f;
            #pragma unroll
            for (int m = 0; m < 9; ++m)
                shp = fmaf(pn[5 + m], Ld[9 + m], shp);
            sAA[nl][kk] = make_float2(A, A * shp);
            // Gaussian grid via exp recurrence: 2 exp per axis
            {
                float d0 = u + 1.0f;
                float Kx = __expf(-inv2tau2 * d0 * d0);
                float Rx = __expf(aD * (2.0f * d0 - DLT));
                #pragma unroll
                for (int g = 0; g < GG; ++g) { sKu[nl][kk][g] = Kx; Kx *= Rx; Rx *= Cc; }
                float d0v = v + 1.0f;
                float Kv2 = __expf(-inv2tau2 * d0v * d0v);
                float Rv = __expf(aD * (2.0f * d0v - DLT));
                #pragma unroll
                for (int g = 0; g < GG; ++g) { sKv[nl][kk][g] = Kv2; Kv2 *= Rv; Rv *= Cc; }
            }
        }
        __syncthreads();
        #pragma unroll 8
        for (int n2 = 0; n2 < NC; ++n2) {
            float2 aa = sAA[n2][warp];
            float kvh = sKv[n2][warp][hh];
            float ku0 = sKu[n2][warp][w0];
            float ku1 = sKu[n2][warp][w0 + 1];
            float tA = aa.x * kvh, tS = aa.y * kvh;
            acc00 = fmaf(tA, ku0, acc00);
            acc01 = fmaf(tA, ku1, acc01);
            acc10 = fmaf(tS, ku0, acc10);
            acc11 = fmaf(tS, ku1, acc11);
        }
        __syncthreads();
    }
    size_t base = ((size_t)((b * KK + warp) * TT + t)) * 128;
    g_splat[base + px0]          = acc00;
    g_splat[base + px0 + 1]      = acc01;
    g_splat[base + 64 + px0]     = acc10;
    g_splat[base + 64 + px0 + 1] = acc11;
}

// ---------------- kernel 2: PERSISTENT CNN — both convs on tensor cores ----
// 256 threads = 8 warps, 4 tiles per iteration, grid 444 (3 blocks/SM).
// conv1: im2col A (K=18 pad 32, chunk-major) + mma; conv2: as before.
// smem float-index layout:
#define SM_RED   0       // 16
#define SM_B1    16      // 32
#define SM_B2    48      // 32
#define SM_FC    80      // 32
#define SM_FCB   112     // 1 (+3 pad)
#define SM_IN    116     // [2 buf][4 tiles][2 ch][100] fp32 = 1600
#define SM_H1    1716    // [4 tiles][4 icg][100 px][8 ch] fp16 = 6400 f32
#define SM_BF    8116    // 4608 u32 (conv2 B fragments)
#define SM_B1F   12724   // 1024 u32 (conv1 B fragments)
#define SM_A     13748   // conv1 A buffer: [4 kchunk][256 row] x 16B = 4096 f32
#define SMEM_FLOATS 17844
#define CNN_SMEM_BYTES (SMEM_FLOATS * 4)
#define QUADS (BB * KK * TT / 4)   // 6144
#define CNN_GRID 444

__global__ __launch_bounds__(256, 3) void cnn_kernel(
    const float* __restrict__ b1g, const float* __restrict__ b2g,
    const float* __restrict__ fcw, const float* __restrict__ fcb,
    float* __restrict__ out) {
    extern __shared__ float sm[];
    int tid = threadIdx.x;
    int warp = tid >> 5, lane = tid & 31;
    int tj = tid >> 6;               // tile 0..3 for im2col pixel role
    int p = tid & 63;
    int x = p & 7, y = p >> 3;

    // ---- one-time staging: zero IN+H1 and A chunk3; stage fragments ----
    for (int i = tid; i < 8000; i += 256) sm[SM_IN + i] = 0.0f;      // IN(2) + H1
    for (int i = tid; i < 1024; i += 256) sm[SM_A + 3072 + i] = 0.0f; // A chunk3
    {
        float4* dbf = (float4*)(sm + SM_BF);
        const float4* sbf = (const float4*)g_bfrag;
        for (int i = tid; i < 1152; i += 256) dbf[i] = sbf[i];
        float4* db1 = (float4*)(sm + SM_B1F);
        const float4* sb1 = (const float4*)g_b1frag;
        for (int i = tid; i < 256; i += 256) db1[i] = sb1[i];
    }
    if (tid < 32) {
        sm[SM_B1 + tid] = b1g[tid];
        sm[SM_B2 + tid] = b2g[tid];
        sm[SM_FC + tid] = fcw[tid];
    }
    if (tid == 0) sm[SM_FCB] = fcb[0];

    // IN staging geometry for this thread's two elements (i = tid, tid+256)
    int st_tt0 = tid >> 7, st_e0 = tid & 127;
    int st_ch0 = st_e0 >> 6, st_pp0 = st_e0 & 63;
    int st_dst0 = (st_tt0 * 2 + st_ch0) * 100 + ((st_pp0 >> 3) + 1) * 10 + (st_pp0 & 7) + 1;
    int i1 = tid + 256;
    int st_tt1 = i1 >> 7, st_e1 = i1 & 127;
    int st_ch1 = st_e1 >> 6, st_pp1 = st_e1 & 63;
    int st_dst1 = (st_tt1 * 2 + st_ch1) * 100 + ((st_pp1 >> 3) + 1) * 10 + (st_pp1 & 7) + 1;

    // MMA warp geometry (shared by conv1 and conv2)
    int wtj = warp >> 1, whalf = warp & 1;     // conv2: tile 0..3, half 0/1
    int mat = lane >> 3;
    int rl = ((mat & 1) << 3) | (lane & 7);
    int kseg = mat >> 1;
    uint32_t h1_addr = smem_u32(sm + SM_H1);
    uint32_t a_addr = smem_u32(sm + SM_A);
    int py0 = (whalf * 32 + rl) >> 3,       px0_ = (whalf * 32 + rl) & 7;
    int py1 = (whalf * 32 + 16 + rl) >> 3,  px1_ = (whalf * 32 + 16 + rl) & 7;
    const uint2* bfr2 = (const uint2*)(sm + SM_BF);
    const uint2* b1f2 = (const uint2*)(sm + SM_B1F);
    uint32_t* h1u = (uint32_t*)(sm + SM_H1);
    __syncthreads();

    // ---- prologue: stage first quad into IN buf 0 ----
    int quad = blockIdx.x;
    if (quad < QUADS) {
        float r0 = g_splat[(size_t)quad * 512 + tid];
        float r1 = g_splat[(size_t)quad * 512 + tid + 256];
        sm[SM_IN + st_dst0] = r0;
        sm[SM_IN + st_dst1] = r1;
    }
    __syncthreads();
    int buf = 0;

    while (quad < QUADS) {
        int tile0 = quad * 4;
        int nq = quad + CNN_GRID;
        int inb = SM_IN + buf * 800;

        // ---- conv1 im2col: each thread packs its pixel's 18 k-values ----
        {
            float v[18];
            #pragma unroll
            for (int c = 0; c < 2; ++c)
                #pragma unroll
                for (int jy = 0; jy < 3; ++jy)
                    #pragma unroll
                    for (int jx = 0; jx < 3; ++jx)
                        v[c * 9 + jy * 3 + jx] =
                            sm[inb + (tj * 2 + c) * 100 + (y + jy) * 10 + (x + jx)];
            uint32_t kv[9];
            #pragma unroll
            for (int q = 0; q < 9; ++q) CVTPACK_F16(kv[q], v[2 * q], v[2 * q + 1]);
            ((uint4*)(sm + SM_A))[tid]        = make_uint4(kv[0], kv[1], kv[2], kv[3]);
            ((uint4*)(sm + SM_A + 1024))[tid] = make_uint4(kv[4], kv[5], kv[6], kv[7]);
            ((uint4*)(sm + SM_A + 2048))[tid] = make_uint4(kv[8], 0u, 0u, 0u);
        }
        __syncwarp();

        // ---- prefetch next quad's splat data ----
        float pf0 = 0.0f, pf1 = 0.0f;
        if (nq < QUADS) {
            pf0 = g_splat[(size_t)nq * 512 + tid];
            pf1 = g_splat[(size_t)nq * 512 + tid + 256];
        }

        // ---- conv1 MMA (warp reads its own threads' A rows) ----
        {
            float c1[2][4][4];
            #pragma unroll
            for (int mt = 0; mt < 2; ++mt)
                #pragma unroll
                for (int n8 = 0; n8 < 4; ++n8)
                    #pragma unroll
                    for (int e = 0; e < 4; ++e) c1[mt][n8][e] = 0.0f;
            #pragma unroll
            for (int mt = 0; mt < 2; ++mt)
                #pragma unroll
                for (int ks = 0; ks < 2; ++ks) {
                    uint32_t af[4];
                    uint32_t ad = a_addr + (ks * 2 + kseg) * 4096
                                + (warp * 32 + mt * 16 + rl) * 16;
                    LDMATRIX_X4(af[0], af[1], af[2], af[3], ad);
                    #pragma unroll
                    for (int n8 = 0; n8 < 4; ++n8) {
                        uint2 bv = b1f2[(ks * 4 + n8) * 32 + lane];
                        MMA16816(c1[mt][n8], af, bv.x, bv.y);
                    }
                }
            // bias + GELU + pack to H1
            #pragma unroll
            for (int mt = 0; mt < 2; ++mt) {
                int rb = warp * 32 + mt * 16 + (lane >> 2);
                #pragma unroll
                for (int half = 0; half < 2; ++half) {
                    int r = rb + half * 8;
                    int tile = r >> 6, px = r & 63;
                    int ppx = ((px >> 3) + 1) * 10 + (px & 7) + 1;
                    #pragma unroll
                    for (int n8 = 0; n8 < 4; ++n8) {
                        int c0 = n8 * 8 + (lane & 3) * 2;
                        float g0 = gelu_fast(c1[mt][n8][half * 2]     + sm[SM_B1 + c0]);
                        float g1 = gelu_fast(c1[mt][n8][half * 2 + 1] + sm[SM_B1 + c0 + 1]);
                        uint32_t pr; CVTPACK_F16(pr, g0, g1);
                        h1u[((tile * 4 + n8) * 100 + ppx) * 4 + (lane & 3)] = pr;
                    }
                }
            }
        }
        __syncthreads();   // H1 plane ready (cross-warp)

        // ---- conv2 GEMM via fp16 mma.sync, single pass ----
        float cacc[2][4][4];
        #pragma unroll
        for (int mt = 0; mt < 2; ++mt)
            #pragma unroll
            for (int n8 = 0; n8 < 4; ++n8)
                #pragma unroll
                for (int e = 0; e < 4; ++e) cacc[mt][n8][e] = 0.0f;

        #pragma unroll 1
        for (int j = 0; j < 9; ++j) {
            int dy2 = j / 3, dx2 = j - dy2 * 3;
            int pix0 = (py0 + dy2) * 10 + (px0_ + dx2);
            int pix1 = (py1 + dy2) * 10 + (px1_ + dx2);
            #pragma unroll
            for (int ksg = 0; ksg < 2; ++ksg) {
                uint32_t ah0[4], ah1[4];
                int plane = (wtj * 4 + ksg * 2 + kseg) * 100;
                uint32_t a0 = h1_addr + (plane + pix0) * 16;
                uint32_t a1 = h1_addr + (plane + pix1) * 16;
                LDMATRIX_X4(ah0[0], ah0[1], ah0[2], ah0[3], a0);
                LDMATRIX_X4(ah1[0], ah1[1], ah1[2], ah1[3], a1);
                #pragma unroll
                for (int n8 = 0; n8 < 4; ++n8) {
                    uint2 Bv = bfr2[((2 * j + ksg) * 4 + n8) * 32 + lane];
                    MMA16816(cacc[0][n8], ah0, Bv.x, Bv.y);
                    MMA16816(cacc[1][n8], ah1, Bv.x, Bv.y);
                }
            }
        }

        // ---- epilogue: bias + GELU + fc dot, warp reduce ----
        float s = 0.0f;
        #pragma unroll
        for (int n8 = 0; n8 < 4; ++n8) {
            int oc0 = n8 * 8 + (lane & 3) * 2;
            float bb0 = sm[SM_B2 + oc0], bb1 = sm[SM_B2 + oc0 + 1];
            float ff0 = sm[SM_FC + oc0], ff1 = sm[SM_FC + oc0 + 1];
            #pragma unroll
            for (int mt = 0; mt < 2; ++mt) {
                s = fmaf(gelu_fast(cacc[mt][n8][0] + bb0), ff0, s);
                s = fmaf(gelu_fast(cacc[mt][n8][1] + bb1), ff1, s);
                s = fmaf(gelu_fast(cacc[mt][n8][2] + bb0), ff0, s);
                s = fmaf(gelu_fast(cacc[mt][n8][3] + bb1), ff1, s);
            }
        }
        #pragma unroll
        for (int off = 16; off > 0; off >>= 1)
            s += __shfl_xor_sync(0xffffffffu, s, off);
        if (lane == 0) sm[SM_RED + warp] = s;

        // stage next quad into the other IN buffer (before the barrier)
        int onb = SM_IN + (buf ^ 1) * 800;
        sm[onb + st_dst0] = pf0;
        sm[onb + st_dst1] = pf1;
        __syncthreads();   // RED + IN[buf^1] ready; H1/A reads done

        if (tid < 4) {
            float v = sm[SM_RED + tid * 2] + sm[SM_RED + tid * 2 + 1];
            v = v * (1.0f / 64.0f) + sm[SM_FCB];
            int tile = tile0 + tid;
            int b = tile / (KK * TT);
            int rem = tile - b * (KK * TT);
            int k = rem / TT;
            int t = rem - k * TT;
            out[(b * TT + t) * KK + k] = v;
        }
        buf ^= 1;
        quad = nq;
    }
}

// ---------------- launch ----------------
extern "C" void kernel_launch(void* const* d_in, const int* in_sizes, int n_in,
                              void* d_out, int out_size) {
    const float* mu        = (const float*)d_in[0];
    const float* sigma0    = (const float*)d_in[1];
    const float* sigma_vel = (const float*)d_in[2];
    const float* amplitude = (const float*)d_in[3];
    const float* sh_base   = (const float*)d_in[4];
    const float* sh_vel    = (const float*)d_in[5];
    const float* p0        = (const float*)d_in[6];
    const float* p_vel     = (const float*)d_in[7];
    const float* tau_raw   = (const float*)d_in[8];
    const float* gam_raw   = (const float*)d_in[9];
    const float* limb_ra   = (const float*)d_in[10];
    const float* limb_la   = (const float*)d_in[11];
    const float* limb_ll   = (const float*)d_in[12];
    const float* chest     = (const float*)d_in[13];
    const float* conv1_w   = (const float*)d_in[14];
    const float* conv1_b   = (const float*)d_in[15];
    const float* conv2_w   = (const float*)d_in[16];
    const float* conv2_b   = (const float*)d_in[17];
    const float* fc_w      = (const float*)d_in[18];
    const float* fc_b      = (const float*)d_in[19];
    float* out = (float*)d_out;

    prep_kernel<<<1, 256>>>(limb_ra, limb_la, limb_ll, chest, conv1_w, conv2_w);
    splat_kernel<<<dim3(TT, BB), 384>>>(mu, sigma0, sigma_vel, amplitude,
                                        sh_base, sh_vel, p0, p_vel, tau_raw, gam_raw);
    cudaFuncSetAttribute(cnn_kernel, cudaFuncAttributeMaxDynamicSharedMemorySize,
                         CNN_SMEM_BYTES);
    cnn_kernel<<<CNN_GRID, 256, CNN_SMEM_BYTES>>>(conv1_b, conv2_b, fc_w, fc_b, out);
}